// round 1
// baseline (speedup 1.0000x reference)
#include <cuda_runtime.h>
#include <cstdint>

// ----------------------------------------------------------------------------
// SelfAttention: out = Attn(x @ Wqkv) @ Wout, causal, H=16, Kd=64
// B=4, L=2048, D=1024  -> tokens = 8192
// Round 0: pure fp32 (CUDA cores) for guaranteed numerics.
// ----------------------------------------------------------------------------

#define TOKENS 8192
#define LSEQ   2048
#define DMODEL 1024
#define HEADS  16
#define KD     64

// Scratch (allocation-free rule: __device__ globals)
__device__ float g_qkv[(size_t)TOKENS * 3 * DMODEL];  // 96 MB
__device__ float g_att[(size_t)TOKENS * DMODEL];      // 32 MB

// ---------------------------------------------------------------------------
// SGEMM: C[M,N] = A[M,K] * B[K,N], all row-major, M%128==0, N%128==0, K%8==0
// 128x128 block tile, BK=8, 256 threads, 8x8 per-thread microtile.
// ---------------------------------------------------------------------------
__global__ __launch_bounds__(256) void sgemm_kernel(const float* __restrict__ A,
                                                    const float* __restrict__ B,
                                                    float* __restrict__ C,
                                                    int M, int N, int K) {
    __shared__ float As[8][128];   // transposed A tile: As[k][m]
    __shared__ float Bs[8][128];   // Bs[k][n]

    const int tid = threadIdx.x;
    const int tx  = tid & 15;       // 0..15
    const int ty  = tid >> 4;       // 0..15
    const int m0  = blockIdx.y * 128;
    const int n0  = blockIdx.x * 128;

    // global load mapping
    const int arow = tid >> 1;            // 0..127
    const int acol = (tid & 1) * 4;       // 0 or 4
    const int brow = tid >> 5;            // 0..7
    const int bcol = (tid & 31) * 4;      // 0..124

    const float* Aptr = A + (size_t)(m0 + arow) * K + acol;
    const float* Bptr = B + (size_t)brow * N + n0 + bcol;

    float acc[8][8];
#pragma unroll
    for (int i = 0; i < 8; i++)
#pragma unroll
        for (int j = 0; j < 8; j++) acc[i][j] = 0.0f;

    for (int k0 = 0; k0 < K; k0 += 8) {
        float4 av = *(const float4*)(Aptr + k0);
        float4 bv = *(const float4*)(Bptr + (size_t)k0 * N);

        As[acol + 0][arow] = av.x;
        As[acol + 1][arow] = av.y;
        As[acol + 2][arow] = av.z;
        As[acol + 3][arow] = av.w;
        *(float4*)&Bs[brow][bcol] = bv;
        __syncthreads();

#pragma unroll
        for (int kk = 0; kk < 8; kk++) {
            float a[8], b[8];
            *(float4*)&a[0] = *(const float4*)&As[kk][ty * 4];
            *(float4*)&a[4] = *(const float4*)&As[kk][64 + ty * 4];
            *(float4*)&b[0] = *(const float4*)&Bs[kk][tx * 4];
            *(float4*)&b[4] = *(const float4*)&Bs[kk][64 + tx * 4];
#pragma unroll
            for (int i = 0; i < 8; i++)
#pragma unroll
                for (int j = 0; j < 8; j++) acc[i][j] += a[i] * b[j];
        }
        __syncthreads();
    }

#pragma unroll
    for (int i = 0; i < 8; i++) {
        int row = m0 + ((i < 4) ? (ty * 4 + i) : (64 + ty * 4 + (i - 4)));
        float4 c0 = make_float4(acc[i][0], acc[i][1], acc[i][2], acc[i][3]);
        float4 c1 = make_float4(acc[i][4], acc[i][5], acc[i][6], acc[i][7]);
        *(float4*)&C[(size_t)row * N + n0 + tx * 4]      = c0;
        *(float4*)&C[(size_t)row * N + n0 + 64 + tx * 4] = c1;
    }
}

// ---------------------------------------------------------------------------
// Flash attention (causal), fp32.
// Block: 64 query rows of one (b, h). Loop kv tiles of 64 (only kt <= qtile).
// 256 threads as 16x16 grid, 4x4 microtiles for S = Q K^T and O += P V.
// Online softmax per row with 16-lane shuffle reductions.
// ---------------------------------------------------------------------------
#define QS_STRIDE 65
#define KS_STRIDE 65
#define VS_STRIDE 68
#define ATT_SMEM_FLOATS (64 * QS_STRIDE + 64 * KS_STRIDE + 64 * VS_STRIDE)
#define ATT_SMEM_BYTES  (ATT_SMEM_FLOATS * 4)

__global__ __launch_bounds__(256) void attn_kernel(const float* __restrict__ qkv,
                                                   float* __restrict__ att) {
    extern __shared__ float sm[];
    float* Qs = sm;                      // [64][65]
    float* Ks = Qs + 64 * QS_STRIDE;     // [64][65]  (also reused for P)
    float* Vs = Ks + 64 * KS_STRIDE;     // [64][68]

    const int tid = threadIdx.x;
    const int tx  = tid & 15;
    const int ty  = tid >> 4;
    const int tx4 = tx * 4;
    const int ty4 = ty * 4;

    const int qtile = blockIdx.x;        // 0..31
    const int bh    = blockIdx.y;        // 0..63
    const int b     = bh >> 4;
    const int h     = bh & 15;
    const int q0    = qtile * 64;

    // qkv row layout: token-major, cols [q(1024) | k(1024) | v(1024)], head h at +h*64
    const float* qbase = qkv + (size_t)(b * LSEQ) * (3 * DMODEL) + h * KD;

    // Load Q tile (64 x 64) once
    for (int i = tid; i < 64 * 16; i += 256) {
        int row = i >> 4;
        int c4  = (i & 15) << 2;
        float4 v = *(const float4*)(qbase + (size_t)(q0 + row) * (3 * DMODEL) + c4);
        float* dst = Qs + row * QS_STRIDE + c4;
        dst[0] = v.x; dst[1] = v.y; dst[2] = v.z; dst[3] = v.w;
    }

    float m_run[4], l_run[4], o[4][4];
#pragma unroll
    for (int i = 0; i < 4; i++) {
        m_run[i] = -1e30f;
        l_run[i] = 0.0f;
#pragma unroll
        for (int j = 0; j < 4; j++) o[i][j] = 0.0f;
    }

    for (int kt = 0; kt <= qtile; kt++) {
        const int k0 = kt * 64;

        // Load K and V tiles
        for (int i = tid; i < 64 * 16; i += 256) {
            int row = i >> 4;
            int c4  = (i & 15) << 2;
            const float* tok = qbase + (size_t)(k0 + row) * (3 * DMODEL) + c4;
            float4 kv = *(const float4*)(tok + DMODEL);
            float* kd = Ks + row * KS_STRIDE + c4;
            kd[0] = kv.x; kd[1] = kv.y; kd[2] = kv.z; kd[3] = kv.w;
            float4 vv = *(const float4*)(tok + 2 * DMODEL);
            *(float4*)(Vs + row * VS_STRIDE + c4) = vv;
        }
        __syncthreads();

        // S = Q K^T (scaled, causal-masked)
        float s[4][4];
#pragma unroll
        for (int i = 0; i < 4; i++)
#pragma unroll
            for (int j = 0; j < 4; j++) s[i][j] = 0.0f;

#pragma unroll 8
        for (int d = 0; d < KD; d++) {
            float a[4], bb[4];
#pragma unroll
            for (int i = 0; i < 4; i++) a[i]  = Qs[(ty4 + i) * QS_STRIDE + d];
#pragma unroll
            for (int j = 0; j < 4; j++) bb[j] = Ks[(tx4 + j) * KS_STRIDE + d];
#pragma unroll
            for (int i = 0; i < 4; i++)
#pragma unroll
                for (int j = 0; j < 4; j++) s[i][j] += a[i] * bb[j];
        }

        float p[4][4];
#pragma unroll
        for (int i = 0; i < 4; i++) {
            const int qi = q0 + ty4 + i;
#pragma unroll
            for (int j = 0; j < 4; j++) {
                const int kj = k0 + tx4 + j;
                s[i][j] = (kj <= qi) ? s[i][j] * 0.125f : -1e30f;
            }
            // row max across this thread's 4 cols + 16-lane group
            float mloc = fmaxf(fmaxf(s[i][0], s[i][1]), fmaxf(s[i][2], s[i][3]));
            mloc = fmaxf(mloc, __shfl_xor_sync(0xffffffffu, mloc, 8));
            mloc = fmaxf(mloc, __shfl_xor_sync(0xffffffffu, mloc, 4));
            mloc = fmaxf(mloc, __shfl_xor_sync(0xffffffffu, mloc, 2));
            mloc = fmaxf(mloc, __shfl_xor_sync(0xffffffffu, mloc, 1));

            float mnew  = fmaxf(m_run[i], mloc);
            float alpha = __expf(m_run[i] - mnew);
            float lsum  = 0.0f;
#pragma unroll
            for (int j = 0; j < 4; j++) {
                p[i][j] = __expf(s[i][j] - mnew);
                lsum += p[i][j];
            }
            lsum += __shfl_xor_sync(0xffffffffu, lsum, 8);
            lsum += __shfl_xor_sync(0xffffffffu, lsum, 4);
            lsum += __shfl_xor_sync(0xffffffffu, lsum, 2);
            lsum += __shfl_xor_sync(0xffffffffu, lsum, 1);

            l_run[i] = l_run[i] * alpha + lsum;
            m_run[i] = mnew;
#pragma unroll
            for (int j = 0; j < 4; j++) o[i][j] *= alpha;
        }

        __syncthreads();  // all threads done reading Ks before overwrite with P
#pragma unroll
        for (int i = 0; i < 4; i++)
#pragma unroll
            for (int j = 0; j < 4; j++)
                Ks[(ty4 + i) * KS_STRIDE + (tx4 + j)] = p[i][j];
        __syncthreads();

        // O += P V   (P in Ks smem, V in Vs smem)
#pragma unroll 8
        for (int k = 0; k < 64; k++) {
            float4 bv = *(const float4*)(Vs + k * VS_STRIDE + tx4);
#pragma unroll
            for (int i = 0; i < 4; i++) {
                float a = Ks[(ty4 + i) * KS_STRIDE + k];
                o[i][0] += a * bv.x;
                o[i][1] += a * bv.y;
                o[i][2] += a * bv.z;
                o[i][3] += a * bv.w;
            }
        }
        __syncthreads();  // before next iteration's K/V loads
    }

    // Normalize and write attended: att[token][h*64 + d]
    float* obase = att + (size_t)(b * LSEQ + q0) * DMODEL + h * KD;
#pragma unroll
    for (int i = 0; i < 4; i++) {
        float inv = 1.0f / l_run[i];
        float4 r = make_float4(o[i][0] * inv, o[i][1] * inv, o[i][2] * inv, o[i][3] * inv);
        *(float4*)(obase + (size_t)(ty4 + i) * DMODEL + tx4) = r;
    }
}

// ---------------------------------------------------------------------------
extern "C" void kernel_launch(void* const* d_in, const int* in_sizes, int n_in,
                              void* d_out, int out_size) {
    const float* x    = (const float*)d_in[0];   // [4,2048,1024]
    const float* Wqkv = (const float*)d_in[1];   // [1024,3072]
    const float* Wout = (const float*)d_in[2];   // [1024,1024]
    float* out = (float*)d_out;                  // [4,2048,1024]

    float* qkv = nullptr;
    float* att = nullptr;
    cudaGetSymbolAddress((void**)&qkv, g_qkv);
    cudaGetSymbolAddress((void**)&att, g_att);

    cudaFuncSetAttribute((const void*)attn_kernel,
                         cudaFuncAttributeMaxDynamicSharedMemorySize, ATT_SMEM_BYTES);

    dim3 blk(256);

    // 1) qkv = x @ Wqkv   : [8192,1024] x [1024,3072]
    sgemm_kernel<<<dim3(3 * DMODEL / 128, TOKENS / 128), blk>>>(x, Wqkv, qkv,
                                                                TOKENS, 3 * DMODEL, DMODEL);

    // 2) causal flash attention -> att [8192,1024]
    attn_kernel<<<dim3(LSEQ / 64, 4 * HEADS), blk, ATT_SMEM_BYTES>>>(qkv, att);

    // 3) out = att @ Wout : [8192,1024] x [1024,1024]
    sgemm_kernel<<<dim3(DMODEL / 128, TOKENS / 128), blk>>>(att, Wout, out,
                                                            TOKENS, DMODEL, DMODEL);
}

// round 3
// speedup vs baseline: 1.5693x; 1.5693x over previous
#include <cuda_runtime.h>
#include <cuda_bf16.h>
#include <cstdint>

// ----------------------------------------------------------------------------
// SelfAttention: out = Attn(x @ Wqkv) @ Wout, causal, H=16, Kd=64
// B=4, L=2048, D=1024 -> tokens = 8192
// R3: GEMMs on mma.sync bf16 (split hi/lo, fp32 accum) — baseline PTX only,
//     no 'a'-suffix features (harness targets compute_103). Attention fp32.
// ----------------------------------------------------------------------------

#define TOKENS 8192
#define LSEQ   2048
#define DMODEL 1024
#define HEADS  16
#define KD     64

// ---------------- scratch (__device__ globals; no allocation allowed) -------
__device__ float         g_qkv[(size_t)TOKENS * 3 * DMODEL];   // fp32
__device__ __nv_bfloat16 g_xh[(size_t)TOKENS * DMODEL];
__device__ __nv_bfloat16 g_xl[(size_t)TOKENS * DMODEL];
__device__ __nv_bfloat16 g_wqkvT_h[(size_t)3 * DMODEL * DMODEL];
__device__ __nv_bfloat16 g_wqkvT_l[(size_t)3 * DMODEL * DMODEL];
__device__ __nv_bfloat16 g_woutT_h[(size_t)DMODEL * DMODEL];
__device__ __nv_bfloat16 g_woutT_l[(size_t)DMODEL * DMODEL];
__device__ __nv_bfloat16 g_att_h[(size_t)TOKENS * DMODEL];
__device__ __nv_bfloat16 g_att_l[(size_t)TOKENS * DMODEL];

// ---------------- helpers ----------------------------------------------------
__device__ __forceinline__ uint32_t smem_u32(const void* p) {
    uint32_t a;
    asm("{ .reg .u64 t; cvta.to.shared.u64 t, %1; cvt.u32.u64 %0, t; }" : "=r"(a) : "l"(p));
    return a;
}
__device__ __forceinline__ void cp16(uint32_t s, const void* g) {
    asm volatile("cp.async.cg.shared.global [%0], [%1], 16;" :: "r"(s), "l"(g));
}
#define CP_COMMIT() asm volatile("cp.async.commit_group;" ::: "memory")

__device__ __forceinline__ void ldsm4(uint32_t* r, uint32_t addr) {
    asm volatile("ldmatrix.sync.aligned.m8n8.x4.shared.b16 {%0,%1,%2,%3}, [%4];"
                 : "=r"(r[0]), "=r"(r[1]), "=r"(r[2]), "=r"(r[3]) : "r"(addr));
}
__device__ __forceinline__ void mma16816(float* c, const uint32_t* a, const uint32_t* b) {
    asm volatile("mma.sync.aligned.m16n8k16.row.col.f32.bf16.bf16.f32 "
                 "{%0,%1,%2,%3}, {%4,%5,%6,%7}, {%8,%9}, {%0,%1,%2,%3};"
                 : "+f"(c[0]), "+f"(c[1]), "+f"(c[2]), "+f"(c[3])
                 : "r"(a[0]), "r"(a[1]), "r"(a[2]), "r"(a[3]), "r"(b[0]), "r"(b[1]));
}

// ---------------------------------------------------------------------------
// Prep 1: elementwise fp32 -> (hi, lo) bf16 split
// ---------------------------------------------------------------------------
__global__ void convert_split_kernel(const float* __restrict__ in,
                                     __nv_bfloat16* __restrict__ hi,
                                     __nv_bfloat16* __restrict__ lo, int n4) {
    int i = blockIdx.x * blockDim.x + threadIdx.x;
    if (i >= n4) return;
    float4 v = ((const float4*)in)[i];
    __nv_bfloat16 h0 = __float2bfloat16(v.x), h1 = __float2bfloat16(v.y);
    __nv_bfloat16 h2 = __float2bfloat16(v.z), h3 = __float2bfloat16(v.w);
    __nv_bfloat16 l0 = __float2bfloat16(v.x - __bfloat162float(h0));
    __nv_bfloat16 l1 = __float2bfloat16(v.y - __bfloat162float(h1));
    __nv_bfloat16 l2 = __float2bfloat16(v.z - __bfloat162float(h2));
    __nv_bfloat16 l3 = __float2bfloat16(v.w - __bfloat162float(h3));
    ((ushort4*)hi)[i] = make_ushort4(__bfloat16_as_ushort(h0), __bfloat16_as_ushort(h1),
                                     __bfloat16_as_ushort(h2), __bfloat16_as_ushort(h3));
    ((ushort4*)lo)[i] = make_ushort4(__bfloat16_as_ushort(l0), __bfloat16_as_ushort(l1),
                                     __bfloat16_as_ushort(l2), __bfloat16_as_ushort(l3));
}

// ---------------------------------------------------------------------------
// Prep 2: W [K,N] fp32 -> W^T hi/lo bf16 [N,K]
// ---------------------------------------------------------------------------
__global__ void transpose_split_kernel(const float* __restrict__ W,
                                       __nv_bfloat16* __restrict__ Th,
                                       __nv_bfloat16* __restrict__ Tl,
                                       int K, int N) {
    __shared__ float t[32][33];
    int n0 = blockIdx.x * 32, k0 = blockIdx.y * 32;
    int tx = threadIdx.x, ty = threadIdx.y;  // 32 x 8
#pragma unroll
    for (int j = 0; j < 4; j++) {
        int k = ty + j * 8;
        t[k][tx] = W[(size_t)(k0 + k) * N + n0 + tx];
    }
    __syncthreads();
#pragma unroll
    for (int j = 0; j < 4; j++) {
        int nl = ty + j * 8;
        float v = t[tx][nl];
        __nv_bfloat16 h = __float2bfloat16(v);
        __nv_bfloat16 l = __float2bfloat16(v - __bfloat162float(h));
        size_t oi = (size_t)(n0 + nl) * K + k0 + tx;
        Th[oi] = h;
        Tl[oi] = l;
    }
}

// ---------------------------------------------------------------------------
// HMMA GEMM: C[M,N] = A[M,K] * Bt[N,K]^T, A/Bt split bf16 (hi/lo), C fp32.
// Block 128x128, BK=32, 256 threads (8 warps, warp tile 64x32).
// smem rows: 32 bf16 (64B data) stored at 80B stride -> conflict-free ldmatrix.
// ---------------------------------------------------------------------------
#define BM 128
#define BN 128
#define BK 32
#define RSTRIDE 80
#define TILE_B  (128 * RSTRIDE)       // 10240
#define OFF_AH  0
#define OFF_AL  (1 * TILE_B)
#define OFF_BH  (2 * TILE_B)
#define OFF_BL  (3 * TILE_B)
#define STAGE_B (4 * TILE_B)          // 40960
#define GEMM_SMEM (2 * STAGE_B)       // 81920

__global__ __launch_bounds__(256, 1) void gemm_mma_kernel(
    const __nv_bfloat16* __restrict__ Ah, const __nv_bfloat16* __restrict__ Al,
    const __nv_bfloat16* __restrict__ Bh, const __nv_bfloat16* __restrict__ Bl,
    float* __restrict__ C, int M, int N, int K) {
    extern __shared__ __align__(128) char smem[];
    const uint32_t sb = smem_u32(smem);
    const int tid  = threadIdx.x;
    const int lane = tid & 31;
    const int wid  = tid >> 5;
    const int m0 = blockIdx.y * BM;
    const int n0 = blockIdx.x * BN;
    const int wm = (wid & 1) * 64;      // warp m offset
    const int wn = (wid >> 1) * 32;     // warp n offset
    const int NS = K / BK;

    // ldmatrix per-lane address offsets
    const uint32_t a_off = (uint32_t)((lane & 15) * RSTRIDE + (lane >> 4) * 16);
    const uint32_t b_off = (uint32_t)((((lane >> 4) & 1) * 8 + (lane & 7)) * RSTRIDE +
                                      ((lane >> 3) & 1) * 16);

    float acc[4][4][4];
#pragma unroll
    for (int i = 0; i < 4; i++)
#pragma unroll
        for (int j = 0; j < 4; j++)
#pragma unroll
            for (int q = 0; q < 4; q++) acc[i][j][q] = 0.0f;

    auto load_stage = [&](int s) {
        const uint32_t base = sb + (uint32_t)(s & 1) * STAGE_B;
        const int k0 = s * BK;
        for (int i = tid; i < 512; i += 256) {
            int row = i >> 2;
            int ch  = (i & 3) * 16;                 // byte chunk within 64B row
            uint32_t so = (uint32_t)(row * RSTRIDE + ch);
            size_t ga = (size_t)(m0 + row) * K + k0 + (ch >> 1);
            size_t gb = (size_t)(n0 + row) * K + k0 + (ch >> 1);
            cp16(base + OFF_AH + so, Ah + ga);
            cp16(base + OFF_AL + so, Al + ga);
            cp16(base + OFF_BH + so, Bh + gb);
            cp16(base + OFF_BL + so, Bl + gb);
        }
        CP_COMMIT();
    };

    load_stage(0);
    load_stage(1);

    for (int s = 0; s < NS; s++) {
        asm volatile("cp.async.wait_group 1;" ::: "memory");
        __syncthreads();

        const uint32_t base = sb + (uint32_t)(s & 1) * STAGE_B;
#pragma unroll
        for (int kk = 0; kk < 2; kk++) {
            const uint32_t koff = kk * 32;          // 16 bf16 = 32 bytes
            uint32_t ah[4][4], al[4][4], bh[2][4], bl[2][4];
#pragma unroll
            for (int mt = 0; mt < 4; mt++) {
                uint32_t r = base + (uint32_t)((wm + mt * 16) * RSTRIDE) + koff;
                ldsm4(ah[mt], r + OFF_AH + a_off);
                ldsm4(al[mt], r + OFF_AL + a_off);
            }
#pragma unroll
            for (int ng = 0; ng < 2; ng++) {
                uint32_t r = base + (uint32_t)((wn + ng * 16) * RSTRIDE) + koff;
                ldsm4(bh[ng], r + OFF_BH + b_off);
                ldsm4(bl[ng], r + OFF_BL + b_off);
            }
#pragma unroll
            for (int mt = 0; mt < 4; mt++)
#pragma unroll
                for (int nt = 0; nt < 4; nt++) {
                    const uint32_t* fh = &bh[nt >> 1][(nt & 1) * 2];
                    const uint32_t* fl = &bl[nt >> 1][(nt & 1) * 2];
                    mma16816(acc[mt][nt], ah[mt], fh);
                    mma16816(acc[mt][nt], ah[mt], fl);
                    mma16816(acc[mt][nt], al[mt], fh);
                }
        }
        __syncthreads();
        if (s + 2 < NS) load_stage(s + 2);
        else            CP_COMMIT();
    }

    // epilogue: direct register -> global
#pragma unroll
    for (int mt = 0; mt < 4; mt++) {
#pragma unroll
        for (int nt = 0; nt < 4; nt++) {
            int row = m0 + wm + mt * 16 + (lane >> 2);
            int col = n0 + wn + nt * 8 + (lane & 3) * 2;
            float2 v0 = make_float2(acc[mt][nt][0], acc[mt][nt][1]);
            float2 v1 = make_float2(acc[mt][nt][2], acc[mt][nt][3]);
            *(float2*)&C[(size_t)row * N + col]       = v0;
            *(float2*)&C[(size_t)(row + 8) * N + col] = v1;
        }
    }
}

// ---------------------------------------------------------------------------
// Flash attention (causal), fp32; epilogue emits bf16 hi/lo for GEMM2.
// ---------------------------------------------------------------------------
#define QS_STRIDE 65
#define KS_STRIDE 65
#define VS_STRIDE 68
#define ATT_SMEM_FLOATS (64 * QS_STRIDE + 64 * KS_STRIDE + 64 * VS_STRIDE)
#define ATT_SMEM_BYTES  (ATT_SMEM_FLOATS * 4)

__global__ __launch_bounds__(256) void attn_kernel(const float* __restrict__ qkv,
                                                   __nv_bfloat16* __restrict__ atth,
                                                   __nv_bfloat16* __restrict__ attl) {
    extern __shared__ float sm[];
    float* Qs = sm;
    float* Ks = Qs + 64 * QS_STRIDE;
    float* Vs = Ks + 64 * KS_STRIDE;

    const int tid = threadIdx.x;
    const int tx  = tid & 15;
    const int ty  = tid >> 4;
    const int tx4 = tx * 4;
    const int ty4 = ty * 4;

    const int qtile = blockIdx.x;
    const int bh    = blockIdx.y;
    const int b     = bh >> 4;
    const int h     = bh & 15;
    const int q0    = qtile * 64;

    const float* qbase = qkv + (size_t)(b * LSEQ) * (3 * DMODEL) + h * KD;

    for (int i = tid; i < 64 * 16; i += 256) {
        int row = i >> 4;
        int c4  = (i & 15) << 2;
        float4 v = *(const float4*)(qbase + (size_t)(q0 + row) * (3 * DMODEL) + c4);
        float* dst = Qs + row * QS_STRIDE + c4;
        dst[0] = v.x; dst[1] = v.y; dst[2] = v.z; dst[3] = v.w;
    }

    float m_run[4], l_run[4], o[4][4];
#pragma unroll
    for (int i = 0; i < 4; i++) {
        m_run[i] = -1e30f;
        l_run[i] = 0.0f;
#pragma unroll
        for (int j = 0; j < 4; j++) o[i][j] = 0.0f;
    }

    for (int kt = 0; kt <= qtile; kt++) {
        const int k0 = kt * 64;
        for (int i = tid; i < 64 * 16; i += 256) {
            int row = i >> 4;
            int c4  = (i & 15) << 2;
            const float* tok = qbase + (size_t)(k0 + row) * (3 * DMODEL) + c4;
            float4 kv = *(const float4*)(tok + DMODEL);
            float* kd = Ks + row * KS_STRIDE + c4;
            kd[0] = kv.x; kd[1] = kv.y; kd[2] = kv.z; kd[3] = kv.w;
            float4 vv = *(const float4*)(tok + 2 * DMODEL);
            *(float4*)(Vs + row * VS_STRIDE + c4) = vv;
        }
        __syncthreads();

        float s[4][4];
#pragma unroll
        for (int i = 0; i < 4; i++)
#pragma unroll
            for (int j = 0; j < 4; j++) s[i][j] = 0.0f;

#pragma unroll 8
        for (int d = 0; d < KD; d++) {
            float a[4], bb[4];
#pragma unroll
            for (int i = 0; i < 4; i++) a[i]  = Qs[(ty4 + i) * QS_STRIDE + d];
#pragma unroll
            for (int j = 0; j < 4; j++) bb[j] = Ks[(tx4 + j) * KS_STRIDE + d];
#pragma unroll
            for (int i = 0; i < 4; i++)
#pragma unroll
                for (int j = 0; j < 4; j++) s[i][j] += a[i] * bb[j];
        }

        float p[4][4];
#pragma unroll
        for (int i = 0; i < 4; i++) {
            const int qi = q0 + ty4 + i;
#pragma unroll
            for (int j = 0; j < 4; j++) {
                const int kj = k0 + tx4 + j;
                s[i][j] = (kj <= qi) ? s[i][j] * 0.125f : -1e30f;
            }
            float mloc = fmaxf(fmaxf(s[i][0], s[i][1]), fmaxf(s[i][2], s[i][3]));
            mloc = fmaxf(mloc, __shfl_xor_sync(0xffffffffu, mloc, 8));
            mloc = fmaxf(mloc, __shfl_xor_sync(0xffffffffu, mloc, 4));
            mloc = fmaxf(mloc, __shfl_xor_sync(0xffffffffu, mloc, 2));
            mloc = fmaxf(mloc, __shfl_xor_sync(0xffffffffu, mloc, 1));

            float mnew  = fmaxf(m_run[i], mloc);
            float alpha = __expf(m_run[i] - mnew);
            float lsum  = 0.0f;
#pragma unroll
            for (int j = 0; j < 4; j++) {
                p[i][j] = __expf(s[i][j] - mnew);
                lsum += p[i][j];
            }
            lsum += __shfl_xor_sync(0xffffffffu, lsum, 8);
            lsum += __shfl_xor_sync(0xffffffffu, lsum, 4);
            lsum += __shfl_xor_sync(0xffffffffu, lsum, 2);
            lsum += __shfl_xor_sync(0xffffffffu, lsum, 1);

            l_run[i] = l_run[i] * alpha + lsum;
            m_run[i] = mnew;
#pragma unroll
            for (int j = 0; j < 4; j++) o[i][j] *= alpha;
        }

        __syncthreads();
#pragma unroll
        for (int i = 0; i < 4; i++)
#pragma unroll
            for (int j = 0; j < 4; j++)
                Ks[(ty4 + i) * KS_STRIDE + (tx4 + j)] = p[i][j];
        __syncthreads();

#pragma unroll 8
        for (int k = 0; k < 64; k++) {
            float4 bv = *(const float4*)(Vs + k * VS_STRIDE + tx4);
#pragma unroll
            for (int i = 0; i < 4; i++) {
                float a = Ks[(ty4 + i) * KS_STRIDE + k];
                o[i][0] += a * bv.x;
                o[i][1] += a * bv.y;
                o[i][2] += a * bv.z;
                o[i][3] += a * bv.w;
            }
        }
        __syncthreads();
    }

    size_t obase = (size_t)(b * LSEQ + q0) * DMODEL + h * KD;
#pragma unroll
    for (int i = 0; i < 4; i++) {
        float inv = 1.0f / l_run[i];
        unsigned short H[4], L[4];
#pragma unroll
        for (int j = 0; j < 4; j++) {
            float v = o[i][j] * inv;
            __nv_bfloat16 hb = __float2bfloat16(v);
            __nv_bfloat16 lb = __float2bfloat16(v - __bfloat162float(hb));
            H[j] = __bfloat16_as_ushort(hb);
            L[j] = __bfloat16_as_ushort(lb);
        }
        size_t oi = obase + (size_t)(ty4 + i) * DMODEL + tx4;
        *(ushort4*)(atth + oi) = make_ushort4(H[0], H[1], H[2], H[3]);
        *(ushort4*)(attl + oi) = make_ushort4(L[0], L[1], L[2], L[3]);
    }
}

// ---------------------------------------------------------------------------
extern "C" void kernel_launch(void* const* d_in, const int* in_sizes, int n_in,
                              void* d_out, int out_size) {
    const float* x    = (const float*)d_in[0];   // [4,2048,1024]
    const float* Wqkv = (const float*)d_in[1];   // [1024,3072]
    const float* Wout = (const float*)d_in[2];   // [1024,1024]
    float* out = (float*)d_out;

    float* qkv;
    __nv_bfloat16 *xh, *xl, *wqh, *wql, *woh, *wol, *ath, *atl;
    cudaGetSymbolAddress((void**)&qkv, g_qkv);
    cudaGetSymbolAddress((void**)&xh, g_xh);
    cudaGetSymbolAddress((void**)&xl, g_xl);
    cudaGetSymbolAddress((void**)&wqh, g_wqkvT_h);
    cudaGetSymbolAddress((void**)&wql, g_wqkvT_l);
    cudaGetSymbolAddress((void**)&woh, g_woutT_h);
    cudaGetSymbolAddress((void**)&wol, g_woutT_l);
    cudaGetSymbolAddress((void**)&ath, g_att_h);
    cudaGetSymbolAddress((void**)&atl, g_att_l);

    cudaFuncSetAttribute((const void*)gemm_mma_kernel,
                         cudaFuncAttributeMaxDynamicSharedMemorySize, GEMM_SMEM);
    cudaFuncSetAttribute((const void*)attn_kernel,
                         cudaFuncAttributeMaxDynamicSharedMemorySize, ATT_SMEM_BYTES);

    // prep
    {
        int n4 = TOKENS * DMODEL / 4;
        convert_split_kernel<<<(n4 + 255) / 256, 256>>>(x, xh, xl, n4);
        transpose_split_kernel<<<dim3(3 * DMODEL / 32, DMODEL / 32), dim3(32, 8)>>>(
            Wqkv, wqh, wql, DMODEL, 3 * DMODEL);
        transpose_split_kernel<<<dim3(DMODEL / 32, DMODEL / 32), dim3(32, 8)>>>(
            Wout, woh, wol, DMODEL, DMODEL);
    }

    // 1) qkv = x @ Wqkv
    gemm_mma_kernel<<<dim3(3 * DMODEL / BN, TOKENS / BM), 256, GEMM_SMEM>>>(
        xh, xl, wqh, wql, qkv, TOKENS, 3 * DMODEL, DMODEL);

    // 2) causal flash attention -> att hi/lo bf16
    attn_kernel<<<dim3(LSEQ / 64, 4 * HEADS), 256, ATT_SMEM_BYTES>>>(qkv, ath, atl);

    // 3) out = att @ Wout
    gemm_mma_kernel<<<dim3(DMODEL / BN, TOKENS / BM), 256, GEMM_SMEM>>>(
        ath, atl, woh, wol, out, TOKENS, DMODEL, DMODEL);
}

// round 4
// speedup vs baseline: 2.5645x; 1.6342x over previous
#include <cuda_runtime.h>
#include <cuda_bf16.h>
#include <cstdint>

// ----------------------------------------------------------------------------
// SelfAttention: out = Attn(x @ Wqkv) @ Wout, causal, H=16, Kd=64
// B=4, L=2048, D=1024 -> tokens = 8192
// R4: everything on mma.sync bf16 (split hi/lo, fp32 accum), including a
//     register-resident flash attention. Baseline PTX only (compute_103).
// ----------------------------------------------------------------------------

#define TOKENS 8192
#define LSEQ   2048
#define DMODEL 1024
#define HEADS  16
#define KD     64
#define BH_CNT (4 * HEADS)   // 64

// ---------------- scratch ----------------------------------------------------
__device__ __nv_bfloat16 g_xh[(size_t)TOKENS * DMODEL];
__device__ __nv_bfloat16 g_xl[(size_t)TOKENS * DMODEL];
__device__ __nv_bfloat16 g_wqkvT_h[(size_t)3 * DMODEL * DMODEL];
__device__ __nv_bfloat16 g_wqkvT_l[(size_t)3 * DMODEL * DMODEL];
__device__ __nv_bfloat16 g_woutT_h[(size_t)DMODEL * DMODEL];
__device__ __nv_bfloat16 g_woutT_l[(size_t)DMODEL * DMODEL];
// head-major [B*H][L][64] split bf16 q/k/v
__device__ __nv_bfloat16 g_qh[(size_t)BH_CNT * LSEQ * KD];
__device__ __nv_bfloat16 g_ql[(size_t)BH_CNT * LSEQ * KD];
__device__ __nv_bfloat16 g_kh[(size_t)BH_CNT * LSEQ * KD];
__device__ __nv_bfloat16 g_kl[(size_t)BH_CNT * LSEQ * KD];
__device__ __nv_bfloat16 g_vh[(size_t)BH_CNT * LSEQ * KD];
__device__ __nv_bfloat16 g_vl[(size_t)BH_CNT * LSEQ * KD];
__device__ __nv_bfloat16 g_att_h[(size_t)TOKENS * DMODEL];
__device__ __nv_bfloat16 g_att_l[(size_t)TOKENS * DMODEL];

// ---------------- helpers ----------------------------------------------------
__device__ __forceinline__ uint32_t smem_u32(const void* p) {
    uint32_t a;
    asm("{ .reg .u64 t; cvta.to.shared.u64 t, %1; cvt.u32.u64 %0, t; }" : "=r"(a) : "l"(p));
    return a;
}
__device__ __forceinline__ void cp16(uint32_t s, const void* g) {
    asm volatile("cp.async.cg.shared.global [%0], [%1], 16;" :: "r"(s), "l"(g));
}
#define CP_COMMIT() asm volatile("cp.async.commit_group;" ::: "memory")
#define CP_WAIT1()  asm volatile("cp.async.wait_group 1;" ::: "memory")

__device__ __forceinline__ void ldsm4(uint32_t* r, uint32_t addr) {
    asm volatile("ldmatrix.sync.aligned.m8n8.x4.shared.b16 {%0,%1,%2,%3}, [%4];"
                 : "=r"(r[0]), "=r"(r[1]), "=r"(r[2]), "=r"(r[3]) : "r"(addr));
}
__device__ __forceinline__ void ldsm4t(uint32_t* r, uint32_t addr) {
    asm volatile("ldmatrix.sync.aligned.m8n8.x4.trans.shared.b16 {%0,%1,%2,%3}, [%4];"
                 : "=r"(r[0]), "=r"(r[1]), "=r"(r[2]), "=r"(r[3]) : "r"(addr));
}
__device__ __forceinline__ void mma16816(float* c, const uint32_t* a, const uint32_t* b) {
    asm volatile("mma.sync.aligned.m16n8k16.row.col.f32.bf16.bf16.f32 "
                 "{%0,%1,%2,%3}, {%4,%5,%6,%7}, {%8,%9}, {%0,%1,%2,%3};"
                 : "+f"(c[0]), "+f"(c[1]), "+f"(c[2]), "+f"(c[3])
                 : "r"(a[0]), "r"(a[1]), "r"(a[2]), "r"(a[3]), "r"(b[0]), "r"(b[1]));
}
__device__ __forceinline__ void split2(float v, unsigned short& h, unsigned short& l) {
    __nv_bfloat16 hb = __float2bfloat16(v);
    __nv_bfloat16 lb = __float2bfloat16(v - __bfloat162float(hb));
    h = __bfloat16_as_ushort(hb);
    l = __bfloat16_as_ushort(lb);
}
__device__ __forceinline__ uint32_t pack2(unsigned short a, unsigned short b) {
    return (uint32_t)a | ((uint32_t)b << 16);
}

// ---------------------------------------------------------------------------
// Prep kernels
// ---------------------------------------------------------------------------
__global__ void convert_split_kernel(const float* __restrict__ in,
                                     __nv_bfloat16* __restrict__ hi,
                                     __nv_bfloat16* __restrict__ lo, int n4) {
    int i = blockIdx.x * blockDim.x + threadIdx.x;
    if (i >= n4) return;
    float4 v = ((const float4*)in)[i];
    unsigned short h0, l0, h1, l1, h2, l2, h3, l3;
    split2(v.x, h0, l0); split2(v.y, h1, l1);
    split2(v.z, h2, l2); split2(v.w, h3, l3);
    ((ushort4*)hi)[i] = make_ushort4(h0, h1, h2, h3);
    ((ushort4*)lo)[i] = make_ushort4(l0, l1, l2, l3);
}

__global__ void transpose_split_kernel(const float* __restrict__ W,
                                       __nv_bfloat16* __restrict__ Th,
                                       __nv_bfloat16* __restrict__ Tl,
                                       int K, int N) {
    __shared__ float t[32][33];
    int n0 = blockIdx.x * 32, k0 = blockIdx.y * 32;
    int tx = threadIdx.x, ty = threadIdx.y;
#pragma unroll
    for (int j = 0; j < 4; j++) {
        int k = ty + j * 8;
        t[k][tx] = W[(size_t)(k0 + k) * N + n0 + tx];
    }
    __syncthreads();
#pragma unroll
    for (int j = 0; j < 4; j++) {
        int nl = ty + j * 8;
        float v = t[tx][nl];
        unsigned short h, l;
        split2(v, h, l);
        size_t oi = (size_t)(n0 + nl) * K + k0 + tx;
        Th[oi] = __ushort_as_bfloat16(h);
        Tl[oi] = __ushort_as_bfloat16(l);
    }
}

// ---------------------------------------------------------------------------
// HMMA GEMM (from R3). MODE 0: C fp32. MODE 1: split-bf16 head-major qkv out.
// ---------------------------------------------------------------------------
#define BM 128
#define BN 128
#define BK 32
#define RSTRIDE 80
#define TILE_B  (128 * RSTRIDE)
#define OFF_AH  0
#define OFF_AL  (1 * TILE_B)
#define OFF_BH  (2 * TILE_B)
#define OFF_BL  (3 * TILE_B)
#define STAGE_B (4 * TILE_B)
#define GEMM_SMEM (2 * STAGE_B)

template <int MODE>
__global__ __launch_bounds__(256, 1) void gemm_mma_kernel(
    const __nv_bfloat16* __restrict__ Ah, const __nv_bfloat16* __restrict__ Al,
    const __nv_bfloat16* __restrict__ Bh, const __nv_bfloat16* __restrict__ Bl,
    float* __restrict__ C,
    __nv_bfloat16* __restrict__ qh, __nv_bfloat16* __restrict__ ql,
    __nv_bfloat16* __restrict__ kh, __nv_bfloat16* __restrict__ kl,
    __nv_bfloat16* __restrict__ vh, __nv_bfloat16* __restrict__ vl,
    int M, int N, int K) {
    extern __shared__ __align__(128) char smem[];
    const uint32_t sb = smem_u32(smem);
    const int tid  = threadIdx.x;
    const int lane = tid & 31;
    const int wid  = tid >> 5;
    const int m0 = blockIdx.y * BM;
    const int n0 = blockIdx.x * BN;
    const int wm = (wid & 1) * 64;
    const int wn = (wid >> 1) * 32;
    const int NS = K / BK;

    const uint32_t a_off = (uint32_t)((lane & 15) * RSTRIDE + (lane >> 4) * 16);
    const uint32_t b_off = (uint32_t)((((lane >> 4) & 1) * 8 + (lane & 7)) * RSTRIDE +
                                      ((lane >> 3) & 1) * 16);

    float acc[4][4][4];
#pragma unroll
    for (int i = 0; i < 4; i++)
#pragma unroll
        for (int j = 0; j < 4; j++)
#pragma unroll
            for (int q = 0; q < 4; q++) acc[i][j][q] = 0.0f;

    auto load_stage = [&](int s) {
        const uint32_t base = sb + (uint32_t)(s & 1) * STAGE_B;
        const int k0 = s * BK;
        for (int i = tid; i < 512; i += 256) {
            int row = i >> 2;
            int ch  = (i & 3) * 16;
            uint32_t so = (uint32_t)(row * RSTRIDE + ch);
            size_t ga = (size_t)(m0 + row) * K + k0 + (ch >> 1);
            size_t gb = (size_t)(n0 + row) * K + k0 + (ch >> 1);
            cp16(base + OFF_AH + so, Ah + ga);
            cp16(base + OFF_AL + so, Al + ga);
            cp16(base + OFF_BH + so, Bh + gb);
            cp16(base + OFF_BL + so, Bl + gb);
        }
        CP_COMMIT();
    };

    load_stage(0);
    load_stage(1);

    for (int s = 0; s < NS; s++) {
        CP_WAIT1();
        __syncthreads();

        const uint32_t base = sb + (uint32_t)(s & 1) * STAGE_B;
#pragma unroll
        for (int kk = 0; kk < 2; kk++) {
            const uint32_t koff = kk * 32;
            uint32_t ah[4][4], al[4][4], bh[2][4], bl[2][4];
#pragma unroll
            for (int mt = 0; mt < 4; mt++) {
                uint32_t r = base + (uint32_t)((wm + mt * 16) * RSTRIDE) + koff;
                ldsm4(ah[mt], r + OFF_AH + a_off);
                ldsm4(al[mt], r + OFF_AL + a_off);
            }
#pragma unroll
            for (int ng = 0; ng < 2; ng++) {
                uint32_t r = base + (uint32_t)((wn + ng * 16) * RSTRIDE) + koff;
                ldsm4(bh[ng], r + OFF_BH + b_off);
                ldsm4(bl[ng], r + OFF_BL + b_off);
            }
#pragma unroll
            for (int mt = 0; mt < 4; mt++)
#pragma unroll
                for (int nt = 0; nt < 4; nt++) {
                    const uint32_t* fh = &bh[nt >> 1][(nt & 1) * 2];
                    const uint32_t* fl = &bl[nt >> 1][(nt & 1) * 2];
                    mma16816(acc[mt][nt], ah[mt], fh);
                    mma16816(acc[mt][nt], ah[mt], fl);
                    mma16816(acc[mt][nt], al[mt], fh);
                }
        }
        __syncthreads();
        if (s + 2 < NS) load_stage(s + 2);
        else            CP_COMMIT();
    }

    if (MODE == 0) {
#pragma unroll
        for (int mt = 0; mt < 4; mt++)
#pragma unroll
            for (int nt = 0; nt < 4; nt++) {
                int row = m0 + wm + mt * 16 + (lane >> 2);
                int col = n0 + wn + nt * 8 + (lane & 3) * 2;
                *(float2*)&C[(size_t)row * N + col] =
                    make_float2(acc[mt][nt][0], acc[mt][nt][1]);
                *(float2*)&C[(size_t)(row + 8) * N + col] =
                    make_float2(acc[mt][nt][2], acc[mt][nt][3]);
            }
    } else {
        // qkv epilogue: col -> section (q/k/v), head, dim; row -> (b, l)
        const int sec = (n0 + wn) >> 10;
        const int hh  = ((n0 + wn) >> 6) & 15;
        __nv_bfloat16* BH_ = (sec == 0) ? qh : (sec == 1) ? kh : vh;
        __nv_bfloat16* BL_ = (sec == 0) ? ql : (sec == 1) ? kl : vl;
#pragma unroll
        for (int mt = 0; mt < 4; mt++)
#pragma unroll
            for (int nt = 0; nt < 4; nt++) {
                int row = m0 + wm + mt * 16 + (lane >> 2);
                int d   = ((wn + nt * 8) & 63) + (lane & 3) * 2;
                int b   = row >> 11;
                int ll  = row & 2047;
                size_t idx = ((size_t)(b * HEADS + hh) * LSEQ + ll) * KD + d;
                unsigned short h0, l0, h1, l1;
                split2(acc[mt][nt][0], h0, l0);
                split2(acc[mt][nt][1], h1, l1);
                *(uint32_t*)(BH_ + idx) = pack2(h0, h1);
                *(uint32_t*)(BL_ + idx) = pack2(l0, l1);
                split2(acc[mt][nt][2], h0, l0);
                split2(acc[mt][nt][3], h1, l1);
                *(uint32_t*)(BH_ + idx + (size_t)8 * KD) = pack2(h0, h1);
                *(uint32_t*)(BL_ + idx + (size_t)8 * KD) = pack2(l0, l1);
            }
    }
}

// ---------------------------------------------------------------------------
// Flash attention on mma.sync, split bf16, causal.
// Block: 128 queries of one bh; 8 warps x 16 rows; kv tiles of 64.
// ---------------------------------------------------------------------------
#define ASTRIDE 144                    // 64 bf16 = 128B data + 16B pad
#define AQH_OFF 0
#define AQL_OFF (128 * ASTRIDE)        // 18432
#define ASTG0   (2 * 128 * ASTRIDE)    // 36864
#define ASTG_SZ (4 * 64 * ASTRIDE)     // 36864 per stage (KH,KL,VH,VL)
#define AKH 0
#define AKL (64 * ASTRIDE)
#define AVH (2 * 64 * ASTRIDE)
#define AVL (3 * 64 * ASTRIDE)
#define ATT_SMEM (ASTG0 + 2 * ASTG_SZ) // 110592

__global__ __launch_bounds__(256, 1) void attn_mma_kernel(
    const __nv_bfloat16* __restrict__ qh, const __nv_bfloat16* __restrict__ ql,
    const __nv_bfloat16* __restrict__ kh, const __nv_bfloat16* __restrict__ kl,
    const __nv_bfloat16* __restrict__ vh, const __nv_bfloat16* __restrict__ vl,
    __nv_bfloat16* __restrict__ atth, __nv_bfloat16* __restrict__ attl) {
    extern __shared__ __align__(128) char smem[];
    const uint32_t sb = smem_u32(smem);
    const int tid  = threadIdx.x;
    const int lane = tid & 31;
    const int wid  = tid >> 5;
    const int qt   = blockIdx.x;
    const int bh   = blockIdx.y;
    const int q0   = qt * 128;
    const int nkv  = 2 * qt + 2;

    const size_t hb = (size_t)bh * LSEQ * KD;
    const char* Qh = (const char*)(qh + hb + (size_t)q0 * KD);
    const char* Ql = (const char*)(ql + hb + (size_t)q0 * KD);
    const char* Kh = (const char*)(kh + hb);
    const char* Kl = (const char*)(kl + hb);
    const char* Vh = (const char*)(vh + hb);
    const char* Vl = (const char*)(vl + hb);

    auto load_q = [&]() {
        for (int i = tid; i < 1024; i += 256) {
            int row = i >> 3, ch = (i & 7) * 16;
            uint32_t so = (uint32_t)(row * ASTRIDE + ch);
            size_t go = (size_t)row * 128 + ch;
            cp16(sb + AQH_OFF + so, Qh + go);
            cp16(sb + AQL_OFF + so, Ql + go);
        }
    };
    auto load_stage = [&](int kt) {
        const uint32_t base = sb + ASTG0 + (uint32_t)(kt & 1) * ASTG_SZ;
        for (int i = tid; i < 512; i += 256) {
            int row = i >> 3, ch = (i & 7) * 16;
            uint32_t so = (uint32_t)(row * ASTRIDE + ch);
            size_t go = (size_t)(kt * 64 + row) * 128 + ch;
            cp16(base + AKH + so, Kh + go);
            cp16(base + AKL + so, Kl + go);
            cp16(base + AVH + so, Vh + go);
            cp16(base + AVL + so, Vl + go);
        }
    };

    load_q();
    load_stage(0);
    CP_COMMIT();                // group: Q + stage0
    load_stage(1);
    CP_COMMIT();                // group: stage1

    // lane offset patterns
    const uint32_t a_off = (uint32_t)((lane & 15) * ASTRIDE + (lane >> 4) * 16);
    const uint32_t b_off = (uint32_t)((((lane >> 4) & 1) * 8 + (lane & 7)) * ASTRIDE +
                                      ((lane >> 3) & 1) * 16);
    const uint32_t v_off = (uint32_t)((lane & 15) * ASTRIDE + (lane >> 4) * 16);

    uint32_t qfh[4][4], qfl[4][4];
    float oacc[8][4];
#pragma unroll
    for (int i = 0; i < 8; i++)
#pragma unroll
        for (int j = 0; j < 4; j++) oacc[i][j] = 0.0f;
    float mr0 = -1e30f, mr1 = -1e30f, lr0 = 0.0f, lr1 = 0.0f;

    const int r0 = q0 + wid * 16 + (lane >> 2);
    const int r1 = r0 + 8;

    for (int kt = 0; kt < nkv; kt++) {
        CP_WAIT1();
        __syncthreads();

        if (kt == 0) {
#pragma unroll
            for (int kc = 0; kc < 4; kc++) {
                uint32_t r = sb + (uint32_t)(wid * 16 * ASTRIDE) + kc * 32 + a_off;
                ldsm4(qfh[kc], r + AQH_OFF);
                ldsm4(qfl[kc], r + AQL_OFF);
            }
        }

        const uint32_t stg = sb + ASTG0 + (uint32_t)(kt & 1) * ASTG_SZ;

        // ---- S = Q K^T (split, fp32 acc) ----
        float sacc[8][4];
#pragma unroll
        for (int i = 0; i < 8; i++)
#pragma unroll
            for (int j = 0; j < 4; j++) sacc[i][j] = 0.0f;

#pragma unroll
        for (int kc = 0; kc < 4; kc++) {
            uint32_t khf[4][4], klf[4][4];
#pragma unroll
            for (int ng = 0; ng < 4; ng++) {
                uint32_t r = stg + (uint32_t)(ng * 16 * ASTRIDE) + kc * 32 + b_off;
                ldsm4(khf[ng], r + AKH);
                ldsm4(klf[ng], r + AKL);
            }
#pragma unroll
            for (int nt = 0; nt < 8; nt++) {
                const uint32_t* fh = &khf[nt >> 1][(nt & 1) * 2];
                const uint32_t* fl = &klf[nt >> 1][(nt & 1) * 2];
                mma16816(sacc[nt], qfh[kc], fh);
                mma16816(sacc[nt], qfh[kc], fl);
                mma16816(sacc[nt], qfl[kc], fh);
            }
        }

        // ---- mask + scale ----
        const bool need_mask = (kt * 64 + 63) > (q0 + wid * 16);
        if (need_mask) {
#pragma unroll
            for (int nt = 0; nt < 8; nt++) {
                int colb = kt * 64 + nt * 8 + (lane & 3) * 2;
                sacc[nt][0] = (colb     <= r0) ? sacc[nt][0] * 0.125f : -1e30f;
                sacc[nt][1] = (colb + 1 <= r0) ? sacc[nt][1] * 0.125f : -1e30f;
                sacc[nt][2] = (colb     <= r1) ? sacc[nt][2] * 0.125f : -1e30f;
                sacc[nt][3] = (colb + 1 <= r1) ? sacc[nt][3] * 0.125f : -1e30f;
            }
        } else {
#pragma unroll
            for (int nt = 0; nt < 8; nt++)
#pragma unroll
                for (int e = 0; e < 4; e++) sacc[nt][e] *= 0.125f;
        }

        // ---- online softmax ----
        float m0 = -1e30f, m1 = -1e30f;
#pragma unroll
        for (int nt = 0; nt < 8; nt++) {
            m0 = fmaxf(m0, fmaxf(sacc[nt][0], sacc[nt][1]));
            m1 = fmaxf(m1, fmaxf(sacc[nt][2], sacc[nt][3]));
        }
        m0 = fmaxf(m0, __shfl_xor_sync(0xffffffffu, m0, 1));
        m0 = fmaxf(m0, __shfl_xor_sync(0xffffffffu, m0, 2));
        m1 = fmaxf(m1, __shfl_xor_sync(0xffffffffu, m1, 1));
        m1 = fmaxf(m1, __shfl_xor_sync(0xffffffffu, m1, 2));

        float mn0 = fmaxf(mr0, m0), mn1 = fmaxf(mr1, m1);
        float al0 = __expf(mr0 - mn0), al1 = __expf(mr1 - mn1);
        mr0 = mn0; mr1 = mn1;

        uint32_t pA[8], pB[8], plA[8], plB[8];
        float s0 = 0.0f, s1 = 0.0f;
#pragma unroll
        for (int nt = 0; nt < 8; nt++) {
            float p0 = __expf(sacc[nt][0] - mn0);
            float p1 = __expf(sacc[nt][1] - mn0);
            float p2 = __expf(sacc[nt][2] - mn1);
            float p3 = __expf(sacc[nt][3] - mn1);
            s0 += p0 + p1;
            s1 += p2 + p3;
            unsigned short h0, l0, h1, l1;
            split2(p0, h0, l0); split2(p1, h1, l1);
            pA[nt] = pack2(h0, h1); plA[nt] = pack2(l0, l1);
            split2(p2, h0, l0); split2(p3, h1, l1);
            pB[nt] = pack2(h0, h1); plB[nt] = pack2(l0, l1);
        }
        s0 += __shfl_xor_sync(0xffffffffu, s0, 1);
        s0 += __shfl_xor_sync(0xffffffffu, s0, 2);
        s1 += __shfl_xor_sync(0xffffffffu, s1, 1);
        s1 += __shfl_xor_sync(0xffffffffu, s1, 2);
        lr0 = lr0 * al0 + s0;
        lr1 = lr1 * al1 + s1;

#pragma unroll
        for (int dt = 0; dt < 8; dt++) {
            oacc[dt][0] *= al0; oacc[dt][1] *= al0;
            oacc[dt][2] *= al1; oacc[dt][3] *= al1;
        }

        // ---- O += P V (split) ----
#pragma unroll
        for (int kc = 0; kc < 4; kc++) {
            uint32_t ah[4] = {pA[2 * kc], pB[2 * kc], pA[2 * kc + 1], pB[2 * kc + 1]};
            uint32_t al[4] = {plA[2 * kc], plB[2 * kc], plA[2 * kc + 1], plB[2 * kc + 1]};
#pragma unroll
            for (int dg = 0; dg < 4; dg++) {
                uint32_t v4h[4], v4l[4];
                uint32_t r = stg + (uint32_t)(kc * 16 * ASTRIDE) + dg * 32 + v_off;
                ldsm4t(v4h, r + AVH);
                ldsm4t(v4l, r + AVL);
                mma16816(oacc[dg * 2], ah, &v4h[0]);
                mma16816(oacc[dg * 2], ah, &v4l[0]);
                mma16816(oacc[dg * 2], al, &v4h[0]);
                mma16816(oacc[dg * 2 + 1], ah, &v4h[2]);
                mma16816(oacc[dg * 2 + 1], ah, &v4l[2]);
                mma16816(oacc[dg * 2 + 1], al, &v4h[2]);
            }
        }

        __syncthreads();
        if (kt + 2 < nkv) load_stage(kt + 2);
        CP_COMMIT();
    }

    // ---- epilogue: normalize, split bf16, write att[token][h*64+d] ----
    const float inv0 = 1.0f / lr0, inv1 = 1.0f / lr1;
    const int b = bh >> 4, hh = bh & 15;
    size_t base0 = ((size_t)(b * LSEQ + r0)) * DMODEL + hh * KD + (lane & 3) * 2;
    size_t base1 = base0 + (size_t)8 * DMODEL;
#pragma unroll
    for (int dt = 0; dt < 8; dt++) {
        unsigned short h0, l0, h1, l1;
        split2(oacc[dt][0] * inv0, h0, l0);
        split2(oacc[dt][1] * inv0, h1, l1);
        *(uint32_t*)(atth + base0 + dt * 8) = pack2(h0, h1);
        *(uint32_t*)(attl + base0 + dt * 8) = pack2(l0, l1);
        split2(oacc[dt][2] * inv1, h0, l0);
        split2(oacc[dt][3] * inv1, h1, l1);
        *(uint32_t*)(atth + base1 + dt * 8) = pack2(h0, h1);
        *(uint32_t*)(attl + base1 + dt * 8) = pack2(l0, l1);
    }
}

// ---------------------------------------------------------------------------
extern "C" void kernel_launch(void* const* d_in, const int* in_sizes, int n_in,
                              void* d_out, int out_size) {
    const float* x    = (const float*)d_in[0];
    const float* Wqkv = (const float*)d_in[1];
    const float* Wout = (const float*)d_in[2];
    float* out = (float*)d_out;

    __nv_bfloat16 *xh, *xl, *wqh, *wql, *woh, *wol;
    __nv_bfloat16 *qh, *ql, *kh, *kl, *vh, *vl, *ath, *atl;
    cudaGetSymbolAddress((void**)&xh, g_xh);
    cudaGetSymbolAddress((void**)&xl, g_xl);
    cudaGetSymbolAddress((void**)&wqh, g_wqkvT_h);
    cudaGetSymbolAddress((void**)&wql, g_wqkvT_l);
    cudaGetSymbolAddress((void**)&woh, g_woutT_h);
    cudaGetSymbolAddress((void**)&wol, g_woutT_l);
    cudaGetSymbolAddress((void**)&qh, g_qh);
    cudaGetSymbolAddress((void**)&ql, g_ql);
    cudaGetSymbolAddress((void**)&kh, g_kh);
    cudaGetSymbolAddress((void**)&kl, g_kl);
    cudaGetSymbolAddress((void**)&vh, g_vh);
    cudaGetSymbolAddress((void**)&vl, g_vl);
    cudaGetSymbolAddress((void**)&ath, g_att_h);
    cudaGetSymbolAddress((void**)&atl, g_att_l);

    cudaFuncSetAttribute((const void*)gemm_mma_kernel<0>,
                         cudaFuncAttributeMaxDynamicSharedMemorySize, GEMM_SMEM);
    cudaFuncSetAttribute((const void*)gemm_mma_kernel<1>,
                         cudaFuncAttributeMaxDynamicSharedMemorySize, GEMM_SMEM);
    cudaFuncSetAttribute((const void*)attn_mma_kernel,
                         cudaFuncAttributeMaxDynamicSharedMemorySize, ATT_SMEM);

    // prep
    {
        int n4 = TOKENS * DMODEL / 4;
        convert_split_kernel<<<(n4 + 255) / 256, 256>>>(x, xh, xl, n4);
        transpose_split_kernel<<<dim3(3 * DMODEL / 32, DMODEL / 32), dim3(32, 8)>>>(
            Wqkv, wqh, wql, DMODEL, 3 * DMODEL);
        transpose_split_kernel<<<dim3(DMODEL / 32, DMODEL / 32), dim3(32, 8)>>>(
            Wout, woh, wol, DMODEL, DMODEL);
    }

    // 1) qkv GEMM -> split bf16 head-major q/k/v
    gemm_mma_kernel<1><<<dim3(3 * DMODEL / BN, TOKENS / BM), 256, GEMM_SMEM>>>(
        xh, xl, wqh, wql, nullptr, qh, ql, kh, kl, vh, vl,
        TOKENS, 3 * DMODEL, DMODEL);

    // 2) tensor-core causal flash attention -> att hi/lo
    attn_mma_kernel<<<dim3(LSEQ / 128, BH_CNT), 256, ATT_SMEM>>>(
        qh, ql, kh, kl, vh, vl, ath, atl);

    // 3) out = att @ Wout
    gemm_mma_kernel<0><<<dim3(DMODEL / BN, TOKENS / BM), 256, GEMM_SMEM>>>(
        ath, atl, woh, wol, out, nullptr, nullptr, nullptr, nullptr, nullptr, nullptr,
        TOKENS, DMODEL, DMODEL);
}

// round 5
// speedup vs baseline: 2.7811x; 1.0845x over previous
#include <cuda_runtime.h>
#include <cuda_bf16.h>
#include <cstdint>

// ----------------------------------------------------------------------------
// SelfAttention: out = Attn(x @ Wqkv) @ Wout, causal, H=16, Kd=64
// B=4, L=2048, D=1024 -> tokens = 8192
// R5: R4 + (a) __launch_bounds__(256,2) on GEMM to restore 2 CTA/SM,
//     (b) term-major MMA ordering to break accumulator dependency chains.
// ----------------------------------------------------------------------------

#define TOKENS 8192
#define LSEQ   2048
#define DMODEL 1024
#define HEADS  16
#define KD     64
#define BH_CNT (4 * HEADS)   // 64

// ---------------- scratch ----------------------------------------------------
__device__ __nv_bfloat16 g_xh[(size_t)TOKENS * DMODEL];
__device__ __nv_bfloat16 g_xl[(size_t)TOKENS * DMODEL];
__device__ __nv_bfloat16 g_wqkvT_h[(size_t)3 * DMODEL * DMODEL];
__device__ __nv_bfloat16 g_wqkvT_l[(size_t)3 * DMODEL * DMODEL];
__device__ __nv_bfloat16 g_woutT_h[(size_t)DMODEL * DMODEL];
__device__ __nv_bfloat16 g_woutT_l[(size_t)DMODEL * DMODEL];
__device__ __nv_bfloat16 g_qh[(size_t)BH_CNT * LSEQ * KD];
__device__ __nv_bfloat16 g_ql[(size_t)BH_CNT * LSEQ * KD];
__device__ __nv_bfloat16 g_kh[(size_t)BH_CNT * LSEQ * KD];
__device__ __nv_bfloat16 g_kl[(size_t)BH_CNT * LSEQ * KD];
__device__ __nv_bfloat16 g_vh[(size_t)BH_CNT * LSEQ * KD];
__device__ __nv_bfloat16 g_vl[(size_t)BH_CNT * LSEQ * KD];
__device__ __nv_bfloat16 g_att_h[(size_t)TOKENS * DMODEL];
__device__ __nv_bfloat16 g_att_l[(size_t)TOKENS * DMODEL];

// ---------------- helpers ----------------------------------------------------
__device__ __forceinline__ uint32_t smem_u32(const void* p) {
    uint32_t a;
    asm("{ .reg .u64 t; cvta.to.shared.u64 t, %1; cvt.u32.u64 %0, t; }" : "=r"(a) : "l"(p));
    return a;
}
__device__ __forceinline__ void cp16(uint32_t s, const void* g) {
    asm volatile("cp.async.cg.shared.global [%0], [%1], 16;" :: "r"(s), "l"(g));
}
#define CP_COMMIT() asm volatile("cp.async.commit_group;" ::: "memory")
#define CP_WAIT1()  asm volatile("cp.async.wait_group 1;" ::: "memory")

__device__ __forceinline__ void ldsm4(uint32_t* r, uint32_t addr) {
    asm volatile("ldmatrix.sync.aligned.m8n8.x4.shared.b16 {%0,%1,%2,%3}, [%4];"
                 : "=r"(r[0]), "=r"(r[1]), "=r"(r[2]), "=r"(r[3]) : "r"(addr));
}
__device__ __forceinline__ void ldsm4t(uint32_t* r, uint32_t addr) {
    asm volatile("ldmatrix.sync.aligned.m8n8.x4.trans.shared.b16 {%0,%1,%2,%3}, [%4];"
                 : "=r"(r[0]), "=r"(r[1]), "=r"(r[2]), "=r"(r[3]) : "r"(addr));
}
__device__ __forceinline__ void mma16816(float* c, const uint32_t* a, const uint32_t* b) {
    asm volatile("mma.sync.aligned.m16n8k16.row.col.f32.bf16.bf16.f32 "
                 "{%0,%1,%2,%3}, {%4,%5,%6,%7}, {%8,%9}, {%0,%1,%2,%3};"
                 : "+f"(c[0]), "+f"(c[1]), "+f"(c[2]), "+f"(c[3])
                 : "r"(a[0]), "r"(a[1]), "r"(a[2]), "r"(a[3]), "r"(b[0]), "r"(b[1]));
}
__device__ __forceinline__ void split2(float v, unsigned short& h, unsigned short& l) {
    __nv_bfloat16 hb = __float2bfloat16(v);
    __nv_bfloat16 lb = __float2bfloat16(v - __bfloat162float(hb));
    h = __bfloat16_as_ushort(hb);
    l = __bfloat16_as_ushort(lb);
}
__device__ __forceinline__ uint32_t pack2(unsigned short a, unsigned short b) {
    return (uint32_t)a | ((uint32_t)b << 16);
}

// ---------------------------------------------------------------------------
// Prep kernels
// ---------------------------------------------------------------------------
__global__ void convert_split_kernel(const float* __restrict__ in,
                                     __nv_bfloat16* __restrict__ hi,
                                     __nv_bfloat16* __restrict__ lo, int n4) {
    int i = blockIdx.x * blockDim.x + threadIdx.x;
    if (i >= n4) return;
    float4 v = ((const float4*)in)[i];
    unsigned short h0, l0, h1, l1, h2, l2, h3, l3;
    split2(v.x, h0, l0); split2(v.y, h1, l1);
    split2(v.z, h2, l2); split2(v.w, h3, l3);
    ((ushort4*)hi)[i] = make_ushort4(h0, h1, h2, h3);
    ((ushort4*)lo)[i] = make_ushort4(l0, l1, l2, l3);
}

__global__ void transpose_split_kernel(const float* __restrict__ W,
                                       __nv_bfloat16* __restrict__ Th,
                                       __nv_bfloat16* __restrict__ Tl,
                                       int K, int N) {
    __shared__ float t[32][33];
    int n0 = blockIdx.x * 32, k0 = blockIdx.y * 32;
    int tx = threadIdx.x, ty = threadIdx.y;
#pragma unroll
    for (int j = 0; j < 4; j++) {
        int k = ty + j * 8;
        t[k][tx] = W[(size_t)(k0 + k) * N + n0 + tx];
    }
    __syncthreads();
#pragma unroll
    for (int j = 0; j < 4; j++) {
        int nl = ty + j * 8;
        float v = t[tx][nl];
        unsigned short h, l;
        split2(v, h, l);
        size_t oi = (size_t)(n0 + nl) * K + k0 + tx;
        Th[oi] = __ushort_as_bfloat16(h);
        Tl[oi] = __ushort_as_bfloat16(l);
    }
}

// ---------------------------------------------------------------------------
// HMMA GEMM. MODE 0: C fp32. MODE 1: split-bf16 head-major qkv out.
// ---------------------------------------------------------------------------
#define BM 128
#define BN 128
#define BK 32
#define RSTRIDE 80
#define TILE_B  (128 * RSTRIDE)
#define OFF_AH  0
#define OFF_AL  (1 * TILE_B)
#define OFF_BH  (2 * TILE_B)
#define OFF_BL  (3 * TILE_B)
#define STAGE_B (4 * TILE_B)
#define GEMM_SMEM (2 * STAGE_B)

template <int MODE>
__global__ __launch_bounds__(256, 2) void gemm_mma_kernel(
    const __nv_bfloat16* __restrict__ Ah, const __nv_bfloat16* __restrict__ Al,
    const __nv_bfloat16* __restrict__ Bh, const __nv_bfloat16* __restrict__ Bl,
    float* __restrict__ C,
    __nv_bfloat16* __restrict__ qh, __nv_bfloat16* __restrict__ ql,
    __nv_bfloat16* __restrict__ kh, __nv_bfloat16* __restrict__ kl,
    __nv_bfloat16* __restrict__ vh, __nv_bfloat16* __restrict__ vl,
    int M, int N, int K) {
    extern __shared__ __align__(128) char smem[];
    const uint32_t sb = smem_u32(smem);
    const int tid  = threadIdx.x;
    const int lane = tid & 31;
    const int wid  = tid >> 5;
    const int m0 = blockIdx.y * BM;
    const int n0 = blockIdx.x * BN;
    const int wm = (wid & 1) * 64;
    const int wn = (wid >> 1) * 32;
    const int NS = K / BK;

    const uint32_t a_off = (uint32_t)((lane & 15) * RSTRIDE + (lane >> 4) * 16);
    const uint32_t b_off = (uint32_t)((((lane >> 4) & 1) * 8 + (lane & 7)) * RSTRIDE +
                                      ((lane >> 3) & 1) * 16);

    float acc[4][4][4];
#pragma unroll
    for (int i = 0; i < 4; i++)
#pragma unroll
        for (int j = 0; j < 4; j++)
#pragma unroll
            for (int q = 0; q < 4; q++) acc[i][j][q] = 0.0f;

    auto load_stage = [&](int s) {
        const uint32_t base = sb + (uint32_t)(s & 1) * STAGE_B;
        const int k0 = s * BK;
        for (int i = tid; i < 512; i += 256) {
            int row = i >> 2;
            int ch  = (i & 3) * 16;
            uint32_t so = (uint32_t)(row * RSTRIDE + ch);
            size_t ga = (size_t)(m0 + row) * K + k0 + (ch >> 1);
            size_t gb = (size_t)(n0 + row) * K + k0 + (ch >> 1);
            cp16(base + OFF_AH + so, Ah + ga);
            cp16(base + OFF_AL + so, Al + ga);
            cp16(base + OFF_BH + so, Bh + gb);
            cp16(base + OFF_BL + so, Bl + gb);
        }
        CP_COMMIT();
    };

    load_stage(0);
    load_stage(1);

    for (int s = 0; s < NS; s++) {
        CP_WAIT1();
        __syncthreads();

        const uint32_t base = sb + (uint32_t)(s & 1) * STAGE_B;
#pragma unroll
        for (int kk = 0; kk < 2; kk++) {
            const uint32_t koff = kk * 32;
            uint32_t ah[4][4], al[4][4], bh[2][4], bl[2][4];
#pragma unroll
            for (int mt = 0; mt < 4; mt++) {
                uint32_t r = base + (uint32_t)((wm + mt * 16) * RSTRIDE) + koff;
                ldsm4(ah[mt], r + OFF_AH + a_off);
                ldsm4(al[mt], r + OFF_AL + a_off);
            }
#pragma unroll
            for (int ng = 0; ng < 2; ng++) {
                uint32_t r = base + (uint32_t)((wn + ng * 16) * RSTRIDE) + koff;
                ldsm4(bh[ng], r + OFF_BH + b_off);
                ldsm4(bl[ng], r + OFF_BL + b_off);
            }
            // term-major passes: consecutive MMAs independent
#pragma unroll
            for (int mt = 0; mt < 4; mt++)
#pragma unroll
                for (int nt = 0; nt < 4; nt++)
                    mma16816(acc[mt][nt], ah[mt], &bh[nt >> 1][(nt & 1) * 2]);
#pragma unroll
            for (int mt = 0; mt < 4; mt++)
#pragma unroll
                for (int nt = 0; nt < 4; nt++)
                    mma16816(acc[mt][nt], ah[mt], &bl[nt >> 1][(nt & 1) * 2]);
#pragma unroll
            for (int mt = 0; mt < 4; mt++)
#pragma unroll
                for (int nt = 0; nt < 4; nt++)
                    mma16816(acc[mt][nt], al[mt], &bh[nt >> 1][(nt & 1) * 2]);
        }
        __syncthreads();
        if (s + 2 < NS) load_stage(s + 2);
        else            CP_COMMIT();
    }

    if (MODE == 0) {
#pragma unroll
        for (int mt = 0; mt < 4; mt++)
#pragma unroll
            for (int nt = 0; nt < 4; nt++) {
                int row = m0 + wm + mt * 16 + (lane >> 2);
                int col = n0 + wn + nt * 8 + (lane & 3) * 2;
                *(float2*)&C[(size_t)row * N + col] =
                    make_float2(acc[mt][nt][0], acc[mt][nt][1]);
                *(float2*)&C[(size_t)(row + 8) * N + col] =
                    make_float2(acc[mt][nt][2], acc[mt][nt][3]);
            }
    } else {
        const int sec = (n0 + wn) >> 10;
        const int hh  = ((n0 + wn) >> 6) & 15;
        __nv_bfloat16* BH_ = (sec == 0) ? qh : (sec == 1) ? kh : vh;
        __nv_bfloat16* BL_ = (sec == 0) ? ql : (sec == 1) ? kl : vl;
#pragma unroll
        for (int mt = 0; mt < 4; mt++)
#pragma unroll
            for (int nt = 0; nt < 4; nt++) {
                int row = m0 + wm + mt * 16 + (lane >> 2);
                int d   = ((wn + nt * 8) & 63) + (lane & 3) * 2;
                int b   = row >> 11;
                int ll  = row & 2047;
                size_t idx = ((size_t)(b * HEADS + hh) * LSEQ + ll) * KD + d;
                unsigned short h0, l0, h1, l1;
                split2(acc[mt][nt][0], h0, l0);
                split2(acc[mt][nt][1], h1, l1);
                *(uint32_t*)(BH_ + idx) = pack2(h0, h1);
                *(uint32_t*)(BL_ + idx) = pack2(l0, l1);
                split2(acc[mt][nt][2], h0, l0);
                split2(acc[mt][nt][3], h1, l1);
                *(uint32_t*)(BH_ + idx + (size_t)8 * KD) = pack2(h0, h1);
                *(uint32_t*)(BL_ + idx + (size_t)8 * KD) = pack2(l0, l1);
            }
    }
}

// ---------------------------------------------------------------------------
// Flash attention on mma.sync, split bf16, causal.
// ---------------------------------------------------------------------------
#define ASTRIDE 144
#define AQH_OFF 0
#define AQL_OFF (128 * ASTRIDE)
#define ASTG0   (2 * 128 * ASTRIDE)
#define ASTG_SZ (4 * 64 * ASTRIDE)
#define AKH 0
#define AKL (64 * ASTRIDE)
#define AVH (2 * 64 * ASTRIDE)
#define AVL (3 * 64 * ASTRIDE)
#define ATT_SMEM (ASTG0 + 2 * ASTG_SZ)

__global__ __launch_bounds__(256, 1) void attn_mma_kernel(
    const __nv_bfloat16* __restrict__ qh, const __nv_bfloat16* __restrict__ ql,
    const __nv_bfloat16* __restrict__ kh, const __nv_bfloat16* __restrict__ kl,
    const __nv_bfloat16* __restrict__ vh, const __nv_bfloat16* __restrict__ vl,
    __nv_bfloat16* __restrict__ atth, __nv_bfloat16* __restrict__ attl) {
    extern __shared__ __align__(128) char smem[];
    const uint32_t sb = smem_u32(smem);
    const int tid  = threadIdx.x;
    const int lane = tid & 31;
    const int wid  = tid >> 5;
    const int qt   = blockIdx.x;
    const int bh   = blockIdx.y;
    const int q0   = qt * 128;
    const int nkv  = 2 * qt + 2;

    const size_t hb = (size_t)bh * LSEQ * KD;
    const char* Qh = (const char*)(qh + hb + (size_t)q0 * KD);
    const char* Ql = (const char*)(ql + hb + (size_t)q0 * KD);
    const char* Kh = (const char*)(kh + hb);
    const char* Kl = (const char*)(kl + hb);
    const char* Vh = (const char*)(vh + hb);
    const char* Vl = (const char*)(vl + hb);

    auto load_q = [&]() {
        for (int i = tid; i < 1024; i += 256) {
            int row = i >> 3, ch = (i & 7) * 16;
            uint32_t so = (uint32_t)(row * ASTRIDE + ch);
            size_t go = (size_t)row * 128 + ch;
            cp16(sb + AQH_OFF + so, Qh + go);
            cp16(sb + AQL_OFF + so, Ql + go);
        }
    };
    auto load_stage = [&](int kt) {
        const uint32_t base = sb + ASTG0 + (uint32_t)(kt & 1) * ASTG_SZ;
        for (int i = tid; i < 512; i += 256) {
            int row = i >> 3, ch = (i & 7) * 16;
            uint32_t so = (uint32_t)(row * ASTRIDE + ch);
            size_t go = (size_t)(kt * 64 + row) * 128 + ch;
            cp16(base + AKH + so, Kh + go);
            cp16(base + AKL + so, Kl + go);
            cp16(base + AVH + so, Vh + go);
            cp16(base + AVL + so, Vl + go);
        }
    };

    load_q();
    load_stage(0);
    CP_COMMIT();
    load_stage(1);
    CP_COMMIT();

    const uint32_t a_off = (uint32_t)((lane & 15) * ASTRIDE + (lane >> 4) * 16);
    const uint32_t b_off = (uint32_t)((((lane >> 4) & 1) * 8 + (lane & 7)) * ASTRIDE +
                                      ((lane >> 3) & 1) * 16);
    const uint32_t v_off = (uint32_t)((lane & 15) * ASTRIDE + (lane >> 4) * 16);

    uint32_t qfh[4][4], qfl[4][4];
    float oacc[8][4];
#pragma unroll
    for (int i = 0; i < 8; i++)
#pragma unroll
        for (int j = 0; j < 4; j++) oacc[i][j] = 0.0f;
    float mr0 = -1e30f, mr1 = -1e30f, lr0 = 0.0f, lr1 = 0.0f;

    const int r0 = q0 + wid * 16 + (lane >> 2);
    const int r1 = r0 + 8;

    for (int kt = 0; kt < nkv; kt++) {
        CP_WAIT1();
        __syncthreads();

        if (kt == 0) {
#pragma unroll
            for (int kc = 0; kc < 4; kc++) {
                uint32_t r = sb + (uint32_t)(wid * 16 * ASTRIDE) + kc * 32 + a_off;
                ldsm4(qfh[kc], r + AQH_OFF);
                ldsm4(qfl[kc], r + AQL_OFF);
            }
        }

        const uint32_t stg = sb + ASTG0 + (uint32_t)(kt & 1) * ASTG_SZ;

        // ---- S = Q K^T (split, term-major) ----
        float sacc[8][4];
#pragma unroll
        for (int i = 0; i < 8; i++)
#pragma unroll
            for (int j = 0; j < 4; j++) sacc[i][j] = 0.0f;

#pragma unroll
        for (int kc = 0; kc < 4; kc++) {
            uint32_t khf[4][4], klf[4][4];
#pragma unroll
            for (int ng = 0; ng < 4; ng++) {
                uint32_t r = stg + (uint32_t)(ng * 16 * ASTRIDE) + kc * 32 + b_off;
                ldsm4(khf[ng], r + AKH);
                ldsm4(klf[ng], r + AKL);
            }
#pragma unroll
            for (int nt = 0; nt < 8; nt++)
                mma16816(sacc[nt], qfh[kc], &khf[nt >> 1][(nt & 1) * 2]);
#pragma unroll
            for (int nt = 0; nt < 8; nt++)
                mma16816(sacc[nt], qfh[kc], &klf[nt >> 1][(nt & 1) * 2]);
#pragma unroll
            for (int nt = 0; nt < 8; nt++)
                mma16816(sacc[nt], qfl[kc], &khf[nt >> 1][(nt & 1) * 2]);
        }

        // ---- mask + scale ----
        const bool need_mask = (kt * 64 + 63) > (q0 + wid * 16);
        if (need_mask) {
#pragma unroll
            for (int nt = 0; nt < 8; nt++) {
                int colb = kt * 64 + nt * 8 + (lane & 3) * 2;
                sacc[nt][0] = (colb     <= r0) ? sacc[nt][0] * 0.125f : -1e30f;
                sacc[nt][1] = (colb + 1 <= r0) ? sacc[nt][1] * 0.125f : -1e30f;
                sacc[nt][2] = (colb     <= r1) ? sacc[nt][2] * 0.125f : -1e30f;
                sacc[nt][3] = (colb + 1 <= r1) ? sacc[nt][3] * 0.125f : -1e30f;
            }
        } else {
#pragma unroll
            for (int nt = 0; nt < 8; nt++)
#pragma unroll
                for (int e = 0; e < 4; e++) sacc[nt][e] *= 0.125f;
        }

        // ---- online softmax ----
        float m0 = -1e30f, m1 = -1e30f;
#pragma unroll
        for (int nt = 0; nt < 8; nt++) {
            m0 = fmaxf(m0, fmaxf(sacc[nt][0], sacc[nt][1]));
            m1 = fmaxf(m1, fmaxf(sacc[nt][2], sacc[nt][3]));
        }
        m0 = fmaxf(m0, __shfl_xor_sync(0xffffffffu, m0, 1));
        m0 = fmaxf(m0, __shfl_xor_sync(0xffffffffu, m0, 2));
        m1 = fmaxf(m1, __shfl_xor_sync(0xffffffffu, m1, 1));
        m1 = fmaxf(m1, __shfl_xor_sync(0xffffffffu, m1, 2));

        float mn0 = fmaxf(mr0, m0), mn1 = fmaxf(mr1, m1);
        float al0 = __expf(mr0 - mn0), al1 = __expf(mr1 - mn1);
        mr0 = mn0; mr1 = mn1;

        uint32_t pA[8], pB[8], plA[8], plB[8];
        float s0 = 0.0f, s1 = 0.0f;
#pragma unroll
        for (int nt = 0; nt < 8; nt++) {
            float p0 = __expf(sacc[nt][0] - mn0);
            float p1 = __expf(sacc[nt][1] - mn0);
            float p2 = __expf(sacc[nt][2] - mn1);
            float p3 = __expf(sacc[nt][3] - mn1);
            s0 += p0 + p1;
            s1 += p2 + p3;
            unsigned short h0, l0, h1, l1;
            split2(p0, h0, l0); split2(p1, h1, l1);
            pA[nt] = pack2(h0, h1); plA[nt] = pack2(l0, l1);
            split2(p2, h0, l0); split2(p3, h1, l1);
            pB[nt] = pack2(h0, h1); plB[nt] = pack2(l0, l1);
        }
        s0 += __shfl_xor_sync(0xffffffffu, s0, 1);
        s0 += __shfl_xor_sync(0xffffffffu, s0, 2);
        s1 += __shfl_xor_sync(0xffffffffu, s1, 1);
        s1 += __shfl_xor_sync(0xffffffffu, s1, 2);
        lr0 = lr0 * al0 + s0;
        lr1 = lr1 * al1 + s1;

#pragma unroll
        for (int dt = 0; dt < 8; dt++) {
            oacc[dt][0] *= al0; oacc[dt][1] *= al0;
            oacc[dt][2] *= al1; oacc[dt][3] *= al1;
        }

        // ---- O += P V (split, term-major per kc) ----
#pragma unroll
        for (int kc = 0; kc < 4; kc++) {
            uint32_t ah[4] = {pA[2 * kc], pB[2 * kc], pA[2 * kc + 1], pB[2 * kc + 1]};
            uint32_t al[4] = {plA[2 * kc], plB[2 * kc], plA[2 * kc + 1], plB[2 * kc + 1]};
            uint32_t v4h[4][4], v4l[4][4];
#pragma unroll
            for (int dg = 0; dg < 4; dg++) {
                uint32_t r = stg + (uint32_t)(kc * 16 * ASTRIDE) + dg * 32 + v_off;
                ldsm4t(v4h[dg], r + AVH);
                ldsm4t(v4l[dg], r + AVL);
            }
#pragma unroll
            for (int dg = 0; dg < 4; dg++) {
                mma16816(oacc[dg * 2],     ah, &v4h[dg][0]);
                mma16816(oacc[dg * 2 + 1], ah, &v4h[dg][2]);
            }
#pragma unroll
            for (int dg = 0; dg < 4; dg++) {
                mma16816(oacc[dg * 2],     ah, &v4l[dg][0]);
                mma16816(oacc[dg * 2 + 1], ah, &v4l[dg][2]);
            }
#pragma unroll
            for (int dg = 0; dg < 4; dg++) {
                mma16816(oacc[dg * 2],     al, &v4h[dg][0]);
                mma16816(oacc[dg * 2 + 1], al, &v4h[dg][2]);
            }
        }

        __syncthreads();
        if (kt + 2 < nkv) load_stage(kt + 2);
        CP_COMMIT();
    }

    // ---- epilogue ----
    const float inv0 = 1.0f / lr0, inv1 = 1.0f / lr1;
    const int b = bh >> 4, hh = bh & 15;
    size_t base0 = ((size_t)(b * LSEQ + r0)) * DMODEL + hh * KD + (lane & 3) * 2;
    size_t base1 = base0 + (size_t)8 * DMODEL;
#pragma unroll
    for (int dt = 0; dt < 8; dt++) {
        unsigned short h0, l0, h1, l1;
        split2(oacc[dt][0] * inv0, h0, l0);
        split2(oacc[dt][1] * inv0, h1, l1);
        *(uint32_t*)(atth + base0 + dt * 8) = pack2(h0, h1);
        *(uint32_t*)(attl + base0 + dt * 8) = pack2(l0, l1);
        split2(oacc[dt][2] * inv1, h0, l0);
        split2(oacc[dt][3] * inv1, h1, l1);
        *(uint32_t*)(atth + base1 + dt * 8) = pack2(h0, h1);
        *(uint32_t*)(attl + base1 + dt * 8) = pack2(l0, l1);
    }
}

// ---------------------------------------------------------------------------
extern "C" void kernel_launch(void* const* d_in, const int* in_sizes, int n_in,
                              void* d_out, int out_size) {
    const float* x    = (const float*)d_in[0];
    const float* Wqkv = (const float*)d_in[1];
    const float* Wout = (const float*)d_in[2];
    float* out = (float*)d_out;

    __nv_bfloat16 *xh, *xl, *wqh, *wql, *woh, *wol;
    __nv_bfloat16 *qh, *ql, *kh, *kl, *vh, *vl, *ath, *atl;
    cudaGetSymbolAddress((void**)&xh, g_xh);
    cudaGetSymbolAddress((void**)&xl, g_xl);
    cudaGetSymbolAddress((void**)&wqh, g_wqkvT_h);
    cudaGetSymbolAddress((void**)&wql, g_wqkvT_l);
    cudaGetSymbolAddress((void**)&woh, g_woutT_h);
    cudaGetSymbolAddress((void**)&wol, g_woutT_l);
    cudaGetSymbolAddress((void**)&qh, g_qh);
    cudaGetSymbolAddress((void**)&ql, g_ql);
    cudaGetSymbolAddress((void**)&kh, g_kh);
    cudaGetSymbolAddress((void**)&kl, g_kl);
    cudaGetSymbolAddress((void**)&vh, g_vh);
    cudaGetSymbolAddress((void**)&vl, g_vl);
    cudaGetSymbolAddress((void**)&ath, g_att_h);
    cudaGetSymbolAddress((void**)&atl, g_att_l);

    cudaFuncSetAttribute((const void*)gemm_mma_kernel<0>,
                         cudaFuncAttributeMaxDynamicSharedMemorySize, GEMM_SMEM);
    cudaFuncSetAttribute((const void*)gemm_mma_kernel<1>,
                         cudaFuncAttributeMaxDynamicSharedMemorySize, GEMM_SMEM);
    cudaFuncSetAttribute((const void*)attn_mma_kernel,
                         cudaFuncAttributeMaxDynamicSharedMemorySize, ATT_SMEM);

    // prep
    {
        int n4 = TOKENS * DMODEL / 4;
        convert_split_kernel<<<(n4 + 255) / 256, 256>>>(x, xh, xl, n4);
        transpose_split_kernel<<<dim3(3 * DMODEL / 32, DMODEL / 32), dim3(32, 8)>>>(
            Wqkv, wqh, wql, DMODEL, 3 * DMODEL);
        transpose_split_kernel<<<dim3(DMODEL / 32, DMODEL / 32), dim3(32, 8)>>>(
            Wout, woh, wol, DMODEL, DMODEL);
    }

    // 1) qkv GEMM -> split bf16 head-major q/k/v
    gemm_mma_kernel<1><<<dim3(3 * DMODEL / BN, TOKENS / BM), 256, GEMM_SMEM>>>(
        xh, xl, wqh, wql, nullptr, qh, ql, kh, kl, vh, vl,
        TOKENS, 3 * DMODEL, DMODEL);

    // 2) tensor-core causal flash attention -> att hi/lo
    attn_mma_kernel<<<dim3(LSEQ / 128, BH_CNT), 256, ATT_SMEM>>>(
        qh, ql, kh, kl, vh, vl, ath, atl);

    // 3) out = att @ Wout
    gemm_mma_kernel<0><<<dim3(DMODEL / BN, TOKENS / BM), 256, GEMM_SMEM>>>(
        ath, atl, woh, wol, out, nullptr, nullptr, nullptr, nullptr, nullptr, nullptr,
        TOKENS, DMODEL, DMODEL);
}

// round 6
// speedup vs baseline: 2.8592x; 1.0281x over previous
#include <cuda_runtime.h>
#include <cuda_bf16.h>
#include <cstdint>

// ----------------------------------------------------------------------------
// SelfAttention: out = Attn(x @ Wqkv) @ Wout, causal, H=16, Kd=64
// B=4, L=2048, D=1024 -> tokens = 8192
// R6: single-barrier software pipeline (wait0 -> sync -> load next -> MMA)
//     in both GEMM and attention. Split bf16 hi/lo everywhere (rel_err ~1e-5).
// ----------------------------------------------------------------------------

#define TOKENS 8192
#define LSEQ   2048
#define DMODEL 1024
#define HEADS  16
#define KD     64
#define BH_CNT (4 * HEADS)   // 64

// ---------------- scratch ----------------------------------------------------
__device__ __nv_bfloat16 g_xh[(size_t)TOKENS * DMODEL];
__device__ __nv_bfloat16 g_xl[(size_t)TOKENS * DMODEL];
__device__ __nv_bfloat16 g_wqkvT_h[(size_t)3 * DMODEL * DMODEL];
__device__ __nv_bfloat16 g_wqkvT_l[(size_t)3 * DMODEL * DMODEL];
__device__ __nv_bfloat16 g_woutT_h[(size_t)DMODEL * DMODEL];
__device__ __nv_bfloat16 g_woutT_l[(size_t)DMODEL * DMODEL];
__device__ __nv_bfloat16 g_qh[(size_t)BH_CNT * LSEQ * KD];
__device__ __nv_bfloat16 g_ql[(size_t)BH_CNT * LSEQ * KD];
__device__ __nv_bfloat16 g_kh[(size_t)BH_CNT * LSEQ * KD];
__device__ __nv_bfloat16 g_kl[(size_t)BH_CNT * LSEQ * KD];
__device__ __nv_bfloat16 g_vh[(size_t)BH_CNT * LSEQ * KD];
__device__ __nv_bfloat16 g_vl[(size_t)BH_CNT * LSEQ * KD];
__device__ __nv_bfloat16 g_att_h[(size_t)TOKENS * DMODEL];
__device__ __nv_bfloat16 g_att_l[(size_t)TOKENS * DMODEL];

// ---------------- helpers ----------------------------------------------------
__device__ __forceinline__ uint32_t smem_u32(const void* p) {
    uint32_t a;
    asm("{ .reg .u64 t; cvta.to.shared.u64 t, %1; cvt.u32.u64 %0, t; }" : "=r"(a) : "l"(p));
    return a;
}
__device__ __forceinline__ void cp16(uint32_t s, const void* g) {
    asm volatile("cp.async.cg.shared.global [%0], [%1], 16;" :: "r"(s), "l"(g));
}
#define CP_COMMIT() asm volatile("cp.async.commit_group;" ::: "memory")
#define CP_WAIT0()  asm volatile("cp.async.wait_group 0;" ::: "memory")

__device__ __forceinline__ void ldsm4(uint32_t* r, uint32_t addr) {
    asm volatile("ldmatrix.sync.aligned.m8n8.x4.shared.b16 {%0,%1,%2,%3}, [%4];"
                 : "=r"(r[0]), "=r"(r[1]), "=r"(r[2]), "=r"(r[3]) : "r"(addr));
}
__device__ __forceinline__ void ldsm4t(uint32_t* r, uint32_t addr) {
    asm volatile("ldmatrix.sync.aligned.m8n8.x4.trans.shared.b16 {%0,%1,%2,%3}, [%4];"
                 : "=r"(r[0]), "=r"(r[1]), "=r"(r[2]), "=r"(r[3]) : "r"(addr));
}
__device__ __forceinline__ void mma16816(float* c, const uint32_t* a, const uint32_t* b) {
    asm volatile("mma.sync.aligned.m16n8k16.row.col.f32.bf16.bf16.f32 "
                 "{%0,%1,%2,%3}, {%4,%5,%6,%7}, {%8,%9}, {%0,%1,%2,%3};"
                 : "+f"(c[0]), "+f"(c[1]), "+f"(c[2]), "+f"(c[3])
                 : "r"(a[0]), "r"(a[1]), "r"(a[2]), "r"(a[3]), "r"(b[0]), "r"(b[1]));
}
__device__ __forceinline__ void split2(float v, unsigned short& h, unsigned short& l) {
    __nv_bfloat16 hb = __float2bfloat16(v);
    __nv_bfloat16 lb = __float2bfloat16(v - __bfloat162float(hb));
    h = __bfloat16_as_ushort(hb);
    l = __bfloat16_as_ushort(lb);
}
__device__ __forceinline__ uint32_t pack2(unsigned short a, unsigned short b) {
    return (uint32_t)a | ((uint32_t)b << 16);
}

// ---------------------------------------------------------------------------
// Prep kernels
// ---------------------------------------------------------------------------
__global__ void convert_split_kernel(const float* __restrict__ in,
                                     __nv_bfloat16* __restrict__ hi,
                                     __nv_bfloat16* __restrict__ lo, int n4) {
    int i = blockIdx.x * blockDim.x + threadIdx.x;
    if (i >= n4) return;
    float4 v = ((const float4*)in)[i];
    unsigned short h0, l0, h1, l1, h2, l2, h3, l3;
    split2(v.x, h0, l0); split2(v.y, h1, l1);
    split2(v.z, h2, l2); split2(v.w, h3, l3);
    ((ushort4*)hi)[i] = make_ushort4(h0, h1, h2, h3);
    ((ushort4*)lo)[i] = make_ushort4(l0, l1, l2, l3);
}

__global__ void transpose_split_kernel(const float* __restrict__ W,
                                       __nv_bfloat16* __restrict__ Th,
                                       __nv_bfloat16* __restrict__ Tl,
                                       int K, int N) {
    __shared__ float t[32][33];
    int n0 = blockIdx.x * 32, k0 = blockIdx.y * 32;
    int tx = threadIdx.x, ty = threadIdx.y;
#pragma unroll
    for (int j = 0; j < 4; j++) {
        int k = ty + j * 8;
        t[k][tx] = W[(size_t)(k0 + k) * N + n0 + tx];
    }
    __syncthreads();
#pragma unroll
    for (int j = 0; j < 4; j++) {
        int nl = ty + j * 8;
        float v = t[tx][nl];
        unsigned short h, l;
        split2(v, h, l);
        size_t oi = (size_t)(n0 + nl) * K + k0 + tx;
        Th[oi] = __ushort_as_bfloat16(h);
        Tl[oi] = __ushort_as_bfloat16(l);
    }
}

// ---------------------------------------------------------------------------
// HMMA GEMM. MODE 0: C fp32. MODE 1: split-bf16 head-major qkv out.
// ---------------------------------------------------------------------------
#define BM 128
#define BN 128
#define BK 32
#define RSTRIDE 80
#define TILE_B  (128 * RSTRIDE)
#define OFF_AH  0
#define OFF_AL  (1 * TILE_B)
#define OFF_BH  (2 * TILE_B)
#define OFF_BL  (3 * TILE_B)
#define STAGE_B (4 * TILE_B)
#define GEMM_SMEM (2 * STAGE_B)

template <int MODE>
__global__ __launch_bounds__(256, 2) void gemm_mma_kernel(
    const __nv_bfloat16* __restrict__ Ah, const __nv_bfloat16* __restrict__ Al,
    const __nv_bfloat16* __restrict__ Bh, const __nv_bfloat16* __restrict__ Bl,
    float* __restrict__ C,
    __nv_bfloat16* __restrict__ qh, __nv_bfloat16* __restrict__ ql,
    __nv_bfloat16* __restrict__ kh, __nv_bfloat16* __restrict__ kl,
    __nv_bfloat16* __restrict__ vh, __nv_bfloat16* __restrict__ vl,
    int M, int N, int K) {
    extern __shared__ __align__(128) char smem[];
    const uint32_t sb = smem_u32(smem);
    const int tid  = threadIdx.x;
    const int lane = tid & 31;
    const int wid  = tid >> 5;
    const int m0 = blockIdx.y * BM;
    const int n0 = blockIdx.x * BN;
    const int wm = (wid & 1) * 64;
    const int wn = (wid >> 1) * 32;
    const int NS = K / BK;

    const uint32_t a_off = (uint32_t)((lane & 15) * RSTRIDE + (lane >> 4) * 16);
    const uint32_t b_off = (uint32_t)((((lane >> 4) & 1) * 8 + (lane & 7)) * RSTRIDE +
                                      ((lane >> 3) & 1) * 16);

    float acc[4][4][4];
#pragma unroll
    for (int i = 0; i < 4; i++)
#pragma unroll
        for (int j = 0; j < 4; j++)
#pragma unroll
            for (int q = 0; q < 4; q++) acc[i][j][q] = 0.0f;

    auto load_stage = [&](int s) {
        const uint32_t base = sb + (uint32_t)(s & 1) * STAGE_B;
        const int k0 = s * BK;
        for (int i = tid; i < 512; i += 256) {
            int row = i >> 2;
            int ch  = (i & 3) * 16;
            uint32_t so = (uint32_t)(row * RSTRIDE + ch);
            size_t ga = (size_t)(m0 + row) * K + k0 + (ch >> 1);
            size_t gb = (size_t)(n0 + row) * K + k0 + (ch >> 1);
            cp16(base + OFF_AH + so, Ah + ga);
            cp16(base + OFF_AL + so, Al + ga);
            cp16(base + OFF_BH + so, Bh + gb);
            cp16(base + OFF_BL + so, Bl + gb);
        }
        CP_COMMIT();
    };

    load_stage(0);

    for (int s = 0; s < NS; s++) {
        CP_WAIT0();              // this thread's stage-s group done
        __syncthreads();         // publish all threads' smem writes; also
                                 // guarantees prior iter's readers finished
        if (s + 1 < NS) load_stage(s + 1);   // fills the other buffer, overlaps MMAs

        const uint32_t base = sb + (uint32_t)(s & 1) * STAGE_B;
#pragma unroll
        for (int kk = 0; kk < 2; kk++) {
            const uint32_t koff = kk * 32;
            uint32_t ah[4][4], al[4][4], bh[2][4], bl[2][4];
#pragma unroll
            for (int mt = 0; mt < 4; mt++) {
                uint32_t r = base + (uint32_t)((wm + mt * 16) * RSTRIDE) + koff;
                ldsm4(ah[mt], r + OFF_AH + a_off);
                ldsm4(al[mt], r + OFF_AL + a_off);
            }
#pragma unroll
            for (int ng = 0; ng < 2; ng++) {
                uint32_t r = base + (uint32_t)((wn + ng * 16) * RSTRIDE) + koff;
                ldsm4(bh[ng], r + OFF_BH + b_off);
                ldsm4(bl[ng], r + OFF_BL + b_off);
            }
            // term-major passes: consecutive MMAs independent
#pragma unroll
            for (int mt = 0; mt < 4; mt++)
#pragma unroll
                for (int nt = 0; nt < 4; nt++)
                    mma16816(acc[mt][nt], ah[mt], &bh[nt >> 1][(nt & 1) * 2]);
#pragma unroll
            for (int mt = 0; mt < 4; mt++)
#pragma unroll
                for (int nt = 0; nt < 4; nt++)
                    mma16816(acc[mt][nt], ah[mt], &bl[nt >> 1][(nt & 1) * 2]);
#pragma unroll
            for (int mt = 0; mt < 4; mt++)
#pragma unroll
                for (int nt = 0; nt < 4; nt++)
                    mma16816(acc[mt][nt], al[mt], &bh[nt >> 1][(nt & 1) * 2]);
        }
    }

    if (MODE == 0) {
#pragma unroll
        for (int mt = 0; mt < 4; mt++)
#pragma unroll
            for (int nt = 0; nt < 4; nt++) {
                int row = m0 + wm + mt * 16 + (lane >> 2);
                int col = n0 + wn + nt * 8 + (lane & 3) * 2;
                *(float2*)&C[(size_t)row * N + col] =
                    make_float2(acc[mt][nt][0], acc[mt][nt][1]);
                *(float2*)&C[(size_t)(row + 8) * N + col] =
                    make_float2(acc[mt][nt][2], acc[mt][nt][3]);
            }
    } else {
        const int sec = (n0 + wn) >> 10;
        const int hh  = ((n0 + wn) >> 6) & 15;
        __nv_bfloat16* BH_ = (sec == 0) ? qh : (sec == 1) ? kh : vh;
        __nv_bfloat16* BL_ = (sec == 0) ? ql : (sec == 1) ? kl : vl;
#pragma unroll
        for (int mt = 0; mt < 4; mt++)
#pragma unroll
            for (int nt = 0; nt < 4; nt++) {
                int row = m0 + wm + mt * 16 + (lane >> 2);
                int d   = ((wn + nt * 8) & 63) + (lane & 3) * 2;
                int b   = row >> 11;
                int ll  = row & 2047;
                size_t idx = ((size_t)(b * HEADS + hh) * LSEQ + ll) * KD + d;
                unsigned short h0, l0, h1, l1;
                split2(acc[mt][nt][0], h0, l0);
                split2(acc[mt][nt][1], h1, l1);
                *(uint32_t*)(BH_ + idx) = pack2(h0, h1);
                *(uint32_t*)(BL_ + idx) = pack2(l0, l1);
                split2(acc[mt][nt][2], h0, l0);
                split2(acc[mt][nt][3], h1, l1);
                *(uint32_t*)(BH_ + idx + (size_t)8 * KD) = pack2(h0, h1);
                *(uint32_t*)(BL_ + idx + (size_t)8 * KD) = pack2(l0, l1);
            }
    }
}

// ---------------------------------------------------------------------------
// Flash attention on mma.sync, split bf16, causal. Single-barrier pipeline.
// ---------------------------------------------------------------------------
#define ASTRIDE 144
#define AQH_OFF 0
#define AQL_OFF (128 * ASTRIDE)
#define ASTG0   (2 * 128 * ASTRIDE)
#define ASTG_SZ (4 * 64 * ASTRIDE)
#define AKH 0
#define AKL (64 * ASTRIDE)
#define AVH (2 * 64 * ASTRIDE)
#define AVL (3 * 64 * ASTRIDE)
#define ATT_SMEM (ASTG0 + 2 * ASTG_SZ)

__global__ __launch_bounds__(256, 1) void attn_mma_kernel(
    const __nv_bfloat16* __restrict__ qh, const __nv_bfloat16* __restrict__ ql,
    const __nv_bfloat16* __restrict__ kh, const __nv_bfloat16* __restrict__ kl,
    const __nv_bfloat16* __restrict__ vh, const __nv_bfloat16* __restrict__ vl,
    __nv_bfloat16* __restrict__ atth, __nv_bfloat16* __restrict__ attl) {
    extern __shared__ __align__(128) char smem[];
    const uint32_t sb = smem_u32(smem);
    const int tid  = threadIdx.x;
    const int lane = tid & 31;
    const int wid  = tid >> 5;
    const int qt   = blockIdx.x;
    const int bh   = blockIdx.y;
    const int q0   = qt * 128;
    const int nkv  = 2 * qt + 2;

    const size_t hb = (size_t)bh * LSEQ * KD;
    const char* Qh = (const char*)(qh + hb + (size_t)q0 * KD);
    const char* Ql = (const char*)(ql + hb + (size_t)q0 * KD);
    const char* Kh = (const char*)(kh + hb);
    const char* Kl = (const char*)(kl + hb);
    const char* Vh = (const char*)(vh + hb);
    const char* Vl = (const char*)(vl + hb);

    auto load_q = [&]() {
        for (int i = tid; i < 1024; i += 256) {
            int row = i >> 3, ch = (i & 7) * 16;
            uint32_t so = (uint32_t)(row * ASTRIDE + ch);
            size_t go = (size_t)row * 128 + ch;
            cp16(sb + AQH_OFF + so, Qh + go);
            cp16(sb + AQL_OFF + so, Ql + go);
        }
    };
    auto load_stage = [&](int kt) {
        const uint32_t base = sb + ASTG0 + (uint32_t)(kt & 1) * ASTG_SZ;
        for (int i = tid; i < 512; i += 256) {
            int row = i >> 3, ch = (i & 7) * 16;
            uint32_t so = (uint32_t)(row * ASTRIDE + ch);
            size_t go = (size_t)(kt * 64 + row) * 128 + ch;
            cp16(base + AKH + so, Kh + go);
            cp16(base + AKL + so, Kl + go);
            cp16(base + AVH + so, Vh + go);
            cp16(base + AVL + so, Vl + go);
        }
        CP_COMMIT();
    };

    load_q();
    load_stage(0);   // Q + stage0 in one group

    const uint32_t a_off = (uint32_t)((lane & 15) * ASTRIDE + (lane >> 4) * 16);
    const uint32_t b_off = (uint32_t)((((lane >> 4) & 1) * 8 + (lane & 7)) * ASTRIDE +
                                      ((lane >> 3) & 1) * 16);
    const uint32_t v_off = (uint32_t)((lane & 15) * ASTRIDE + (lane >> 4) * 16);

    uint32_t qfh[4][4], qfl[4][4];
    float oacc[8][4];
#pragma unroll
    for (int i = 0; i < 8; i++)
#pragma unroll
        for (int j = 0; j < 4; j++) oacc[i][j] = 0.0f;
    float mr0 = -1e30f, mr1 = -1e30f, lr0 = 0.0f, lr1 = 0.0f;

    const int r0 = q0 + wid * 16 + (lane >> 2);
    const int r1 = r0 + 8;

    for (int kt = 0; kt < nkv; kt++) {
        CP_WAIT0();
        __syncthreads();
        if (kt + 1 < nkv) load_stage(kt + 1);   // fill other buffer, overlap compute

        if (kt == 0) {
#pragma unroll
            for (int kc = 0; kc < 4; kc++) {
                uint32_t r = sb + (uint32_t)(wid * 16 * ASTRIDE) + kc * 32 + a_off;
                ldsm4(qfh[kc], r + AQH_OFF);
                ldsm4(qfl[kc], r + AQL_OFF);
            }
        }

        const uint32_t stg = sb + ASTG0 + (uint32_t)(kt & 1) * ASTG_SZ;

        // ---- S = Q K^T (split, term-major) ----
        float sacc[8][4];
#pragma unroll
        for (int i = 0; i < 8; i++)
#pragma unroll
            for (int j = 0; j < 4; j++) sacc[i][j] = 0.0f;

#pragma unroll
        for (int kc = 0; kc < 4; kc++) {
            uint32_t khf[4][4], klf[4][4];
#pragma unroll
            for (int ng = 0; ng < 4; ng++) {
                uint32_t r = stg + (uint32_t)(ng * 16 * ASTRIDE) + kc * 32 + b_off;
                ldsm4(khf[ng], r + AKH);
                ldsm4(klf[ng], r + AKL);
            }
#pragma unroll
            for (int nt = 0; nt < 8; nt++)
                mma16816(sacc[nt], qfh[kc], &khf[nt >> 1][(nt & 1) * 2]);
#pragma unroll
            for (int nt = 0; nt < 8; nt++)
                mma16816(sacc[nt], qfh[kc], &klf[nt >> 1][(nt & 1) * 2]);
#pragma unroll
            for (int nt = 0; nt < 8; nt++)
                mma16816(sacc[nt], qfl[kc], &khf[nt >> 1][(nt & 1) * 2]);
        }

        // ---- mask + scale ----
        const bool need_mask = (kt * 64 + 63) > (q0 + wid * 16);
        if (need_mask) {
#pragma unroll
            for (int nt = 0; nt < 8; nt++) {
                int colb = kt * 64 + nt * 8 + (lane & 3) * 2;
                sacc[nt][0] = (colb     <= r0) ? sacc[nt][0] * 0.125f : -1e30f;
                sacc[nt][1] = (colb + 1 <= r0) ? sacc[nt][1] * 0.125f : -1e30f;
                sacc[nt][2] = (colb     <= r1) ? sacc[nt][2] * 0.125f : -1e30f;
                sacc[nt][3] = (colb + 1 <= r1) ? sacc[nt][3] * 0.125f : -1e30f;
            }
        } else {
#pragma unroll
            for (int nt = 0; nt < 8; nt++)
#pragma unroll
                for (int e = 0; e < 4; e++) sacc[nt][e] *= 0.125f;
        }

        // ---- online softmax ----
        float m0 = -1e30f, m1 = -1e30f;
#pragma unroll
        for (int nt = 0; nt < 8; nt++) {
            m0 = fmaxf(m0, fmaxf(sacc[nt][0], sacc[nt][1]));
            m1 = fmaxf(m1, fmaxf(sacc[nt][2], sacc[nt][3]));
        }
        m0 = fmaxf(m0, __shfl_xor_sync(0xffffffffu, m0, 1));
        m0 = fmaxf(m0, __shfl_xor_sync(0xffffffffu, m0, 2));
        m1 = fmaxf(m1, __shfl_xor_sync(0xffffffffu, m1, 1));
        m1 = fmaxf(m1, __shfl_xor_sync(0xffffffffu, m1, 2));

        float mn0 = fmaxf(mr0, m0), mn1 = fmaxf(mr1, m1);
        float al0 = __expf(mr0 - mn0), al1 = __expf(mr1 - mn1);
        mr0 = mn0; mr1 = mn1;

        uint32_t pA[8], pB[8], plA[8], plB[8];
        float s0 = 0.0f, s1 = 0.0f;
#pragma unroll
        for (int nt = 0; nt < 8; nt++) {
            float p0 = __expf(sacc[nt][0] - mn0);
            float p1 = __expf(sacc[nt][1] - mn0);
            float p2 = __expf(sacc[nt][2] - mn1);
            float p3 = __expf(sacc[nt][3] - mn1);
            s0 += p0 + p1;
            s1 += p2 + p3;
            unsigned short h0, l0, h1, l1;
            split2(p0, h0, l0); split2(p1, h1, l1);
            pA[nt] = pack2(h0, h1); plA[nt] = pack2(l0, l1);
            split2(p2, h0, l0); split2(p3, h1, l1);
            pB[nt] = pack2(h0, h1); plB[nt] = pack2(l0, l1);
        }
        s0 += __shfl_xor_sync(0xffffffffu, s0, 1);
        s0 += __shfl_xor_sync(0xffffffffu, s0, 2);
        s1 += __shfl_xor_sync(0xffffffffu, s1, 1);
        s1 += __shfl_xor_sync(0xffffffffu, s1, 2);
        lr0 = lr0 * al0 + s0;
        lr1 = lr1 * al1 + s1;

#pragma unroll
        for (int dt = 0; dt < 8; dt++) {
            oacc[dt][0] *= al0; oacc[dt][1] *= al0;
            oacc[dt][2] *= al1; oacc[dt][3] *= al1;
        }

        // ---- O += P V (split, term-major per kc) ----
#pragma unroll
        for (int kc = 0; kc < 4; kc++) {
            uint32_t ah[4] = {pA[2 * kc], pB[2 * kc], pA[2 * kc + 1], pB[2 * kc + 1]};
            uint32_t al[4] = {plA[2 * kc], plB[2 * kc], plA[2 * kc + 1], plB[2 * kc + 1]};
            uint32_t v4h[4][4], v4l[4][4];
#pragma unroll
            for (int dg = 0; dg < 4; dg++) {
                uint32_t r = stg + (uint32_t)(kc * 16 * ASTRIDE) + dg * 32 + v_off;
                ldsm4t(v4h[dg], r + AVH);
                ldsm4t(v4l[dg], r + AVL);
            }
#pragma unroll
            for (int dg = 0; dg < 4; dg++) {
                mma16816(oacc[dg * 2],     ah, &v4h[dg][0]);
                mma16816(oacc[dg * 2 + 1], ah, &v4h[dg][2]);
            }
#pragma unroll
            for (int dg = 0; dg < 4; dg++) {
                mma16816(oacc[dg * 2],     ah, &v4l[dg][0]);
                mma16816(oacc[dg * 2 + 1], ah, &v4l[dg][2]);
            }
#pragma unroll
            for (int dg = 0; dg < 4; dg++) {
                mma16816(oacc[dg * 2],     al, &v4h[dg][0]);
                mma16816(oacc[dg * 2 + 1], al, &v4h[dg][2]);
            }
        }
    }

    // ---- epilogue ----
    const float inv0 = 1.0f / lr0, inv1 = 1.0f / lr1;
    const int b = bh >> 4, hh = bh & 15;
    size_t base0 = ((size_t)(b * LSEQ + r0)) * DMODEL + hh * KD + (lane & 3) * 2;
    size_t base1 = base0 + (size_t)8 * DMODEL;
#pragma unroll
    for (int dt = 0; dt < 8; dt++) {
        unsigned short h0, l0, h1, l1;
        split2(oacc[dt][0] * inv0, h0, l0);
        split2(oacc[dt][1] * inv0, h1, l1);
        *(uint32_t*)(atth + base0 + dt * 8) = pack2(h0, h1);
        *(uint32_t*)(attl + base0 + dt * 8) = pack2(l0, l1);
        split2(oacc[dt][2] * inv1, h0, l0);
        split2(oacc[dt][3] * inv1, h1, l1);
        *(uint32_t*)(atth + base1 + dt * 8) = pack2(h0, h1);
        *(uint32_t*)(attl + base1 + dt * 8) = pack2(l0, l1);
    }
}

// ---------------------------------------------------------------------------
extern "C" void kernel_launch(void* const* d_in, const int* in_sizes, int n_in,
                              void* d_out, int out_size) {
    const float* x    = (const float*)d_in[0];
    const float* Wqkv = (const float*)d_in[1];
    const float* Wout = (const float*)d_in[2];
    float* out = (float*)d_out;

    __nv_bfloat16 *xh, *xl, *wqh, *wql, *woh, *wol;
    __nv_bfloat16 *qh, *ql, *kh, *kl, *vh, *vl, *ath, *atl;
    cudaGetSymbolAddress((void**)&xh, g_xh);
    cudaGetSymbolAddress((void**)&xl, g_xl);
    cudaGetSymbolAddress((void**)&wqh, g_wqkvT_h);
    cudaGetSymbolAddress((void**)&wql, g_wqkvT_l);
    cudaGetSymbolAddress((void**)&woh, g_woutT_h);
    cudaGetSymbolAddress((void**)&wol, g_woutT_l);
    cudaGetSymbolAddress((void**)&qh, g_qh);
    cudaGetSymbolAddress((void**)&ql, g_ql);
    cudaGetSymbolAddress((void**)&kh, g_kh);
    cudaGetSymbolAddress((void**)&kl, g_kl);
    cudaGetSymbolAddress((void**)&vh, g_vh);
    cudaGetSymbolAddress((void**)&vl, g_vl);
    cudaGetSymbolAddress((void**)&ath, g_att_h);
    cudaGetSymbolAddress((void**)&atl, g_att_l);

    cudaFuncSetAttribute((const void*)gemm_mma_kernel<0>,
                         cudaFuncAttributeMaxDynamicSharedMemorySize, GEMM_SMEM);
    cudaFuncSetAttribute((const void*)gemm_mma_kernel<1>,
                         cudaFuncAttributeMaxDynamicSharedMemorySize, GEMM_SMEM);
    cudaFuncSetAttribute((const void*)attn_mma_kernel,
                         cudaFuncAttributeMaxDynamicSharedMemorySize, ATT_SMEM);

    // prep
    {
        int n4 = TOKENS * DMODEL / 4;
        convert_split_kernel<<<(n4 + 255) / 256, 256>>>(x, xh, xl, n4);
        transpose_split_kernel<<<dim3(3 * DMODEL / 32, DMODEL / 32), dim3(32, 8)>>>(
            Wqkv, wqh, wql, DMODEL, 3 * DMODEL);
        transpose_split_kernel<<<dim3(DMODEL / 32, DMODEL / 32), dim3(32, 8)>>>(
            Wout, woh, wol, DMODEL, DMODEL);
    }

    // 1) qkv GEMM -> split bf16 head-major q/k/v
    gemm_mma_kernel<1><<<dim3(3 * DMODEL / BN, TOKENS / BM), 256, GEMM_SMEM>>>(
        xh, xl, wqh, wql, nullptr, qh, ql, kh, kl, vh, vl,
        TOKENS, 3 * DMODEL, DMODEL);

    // 2) tensor-core causal flash attention -> att hi/lo
    attn_mma_kernel<<<dim3(LSEQ / 128, BH_CNT), 256, ATT_SMEM>>>(
        qh, ql, kh, kl, vh, vl, ath, atl);

    // 3) out = att @ Wout
    gemm_mma_kernel<0><<<dim3(DMODEL / BN, TOKENS / BM), 256, GEMM_SMEM>>>(
        ath, atl, woh, wol, out, nullptr, nullptr, nullptr, nullptr, nullptr, nullptr,
        TOKENS, DMODEL, DMODEL);
}

// round 7
// speedup vs baseline: 4.0870x; 1.4294x over previous
#include <cuda_runtime.h>
#include <cuda_fp16.h>
#include <cstdint>

// ----------------------------------------------------------------------------
// SelfAttention: out = Attn(x @ Wqkv) @ Wout, causal, H=16, Kd=64
// B=4, L=2048, D=1024 -> tokens = 8192
// R7: fp16 2-term split (A * (Bh + Bl)), residual ~2^-12.
//     GEMM: 3-stage cp.async pipeline, 2 CTA/SM. Attention: 2 CTA/SM.
// ----------------------------------------------------------------------------

#define TOKENS 8192
#define LSEQ   2048
#define DMODEL 1024
#define HEADS  16
#define KD     64
#define BH_CNT (4 * HEADS)   // 64

// ---------------- scratch ----------------------------------------------------
__device__ __half g_x16[(size_t)TOKENS * DMODEL];
__device__ __half g_wqkvT_h[(size_t)3 * DMODEL * DMODEL];
__device__ __half g_wqkvT_l[(size_t)3 * DMODEL * DMODEL];
__device__ __half g_woutT_h[(size_t)DMODEL * DMODEL];
__device__ __half g_woutT_l[(size_t)DMODEL * DMODEL];
__device__ __half g_q16[(size_t)BH_CNT * LSEQ * KD];
__device__ __half g_kh[(size_t)BH_CNT * LSEQ * KD];
__device__ __half g_kl[(size_t)BH_CNT * LSEQ * KD];
__device__ __half g_vh[(size_t)BH_CNT * LSEQ * KD];
__device__ __half g_vl[(size_t)BH_CNT * LSEQ * KD];
__device__ __half g_att16[(size_t)TOKENS * DMODEL];

// ---------------- helpers ----------------------------------------------------
__device__ __forceinline__ uint32_t smem_u32(const void* p) {
    uint32_t a;
    asm("{ .reg .u64 t; cvta.to.shared.u64 t, %1; cvt.u32.u64 %0, t; }" : "=r"(a) : "l"(p));
    return a;
}
__device__ __forceinline__ void cp16(uint32_t s, const void* g) {
    asm volatile("cp.async.cg.shared.global [%0], [%1], 16;" :: "r"(s), "l"(g));
}
#define CP_COMMIT() asm volatile("cp.async.commit_group;" ::: "memory")
#define CP_WAIT0()  asm volatile("cp.async.wait_group 0;" ::: "memory")
#define CP_WAIT1()  asm volatile("cp.async.wait_group 1;" ::: "memory")

__device__ __forceinline__ void ldsm4(uint32_t* r, uint32_t addr) {
    asm volatile("ldmatrix.sync.aligned.m8n8.x4.shared.b16 {%0,%1,%2,%3}, [%4];"
                 : "=r"(r[0]), "=r"(r[1]), "=r"(r[2]), "=r"(r[3]) : "r"(addr));
}
__device__ __forceinline__ void ldsm4t(uint32_t* r, uint32_t addr) {
    asm volatile("ldmatrix.sync.aligned.m8n8.x4.trans.shared.b16 {%0,%1,%2,%3}, [%4];"
                 : "=r"(r[0]), "=r"(r[1]), "=r"(r[2]), "=r"(r[3]) : "r"(addr));
}
__device__ __forceinline__ void mma16816(float* c, const uint32_t* a, const uint32_t* b) {
    asm volatile("mma.sync.aligned.m16n8k16.row.col.f32.f16.f16.f32 "
                 "{%0,%1,%2,%3}, {%4,%5,%6,%7}, {%8,%9}, {%0,%1,%2,%3};"
                 : "+f"(c[0]), "+f"(c[1]), "+f"(c[2]), "+f"(c[3])
                 : "r"(a[0]), "r"(a[1]), "r"(a[2]), "r"(a[3]), "r"(b[0]), "r"(b[1]));
}
__device__ __forceinline__ void split2h(float v, unsigned short& h, unsigned short& l) {
    __half hb = __float2half_rn(v);
    __half lb = __float2half_rn(v - __half2float(hb));
    h = __half_as_ushort(hb);
    l = __half_as_ushort(lb);
}
__device__ __forceinline__ unsigned short h16(float v) {
    return __half_as_ushort(__float2half_rn(v));
}
__device__ __forceinline__ uint32_t pack2(unsigned short a, unsigned short b) {
    return (uint32_t)a | ((uint32_t)b << 16);
}

// ---------------------------------------------------------------------------
// Prep kernels
// ---------------------------------------------------------------------------
__global__ void convert_f16_kernel(const float* __restrict__ in,
                                   __half* __restrict__ o16, int n4) {
    int i = blockIdx.x * blockDim.x + threadIdx.x;
    if (i >= n4) return;
    float4 v = ((const float4*)in)[i];
    ((ushort4*)o16)[i] = make_ushort4(h16(v.x), h16(v.y), h16(v.z), h16(v.w));
}

__global__ void transpose_split_kernel(const float* __restrict__ W,
                                       __half* __restrict__ Th,
                                       __half* __restrict__ Tl,
                                       int K, int N) {
    __shared__ float t[32][33];
    int n0 = blockIdx.x * 32, k0 = blockIdx.y * 32;
    int tx = threadIdx.x, ty = threadIdx.y;
#pragma unroll
    for (int j = 0; j < 4; j++) {
        int k = ty + j * 8;
        t[k][tx] = W[(size_t)(k0 + k) * N + n0 + tx];
    }
    __syncthreads();
#pragma unroll
    for (int j = 0; j < 4; j++) {
        int nl = ty + j * 8;
        float v = t[tx][nl];
        unsigned short h, l;
        split2h(v, h, l);
        size_t oi = (size_t)(n0 + nl) * K + k0 + tx;
        Th[oi] = __ushort_as_half(h);
        Tl[oi] = __ushort_as_half(l);
    }
}

// ---------------------------------------------------------------------------
// HMMA GEMM, 2-term: C = A * (Bh + Bl).  A single fp16, B split.
// 128x128 tile, BK=32, 8 warps, 3-stage cp.async pipeline, 2 CTA/SM.
// MODE 0: C fp32.  MODE 1: split/pack head-major q/k/v epilogue.
// ---------------------------------------------------------------------------
#define BM 128
#define BN 128
#define BK 32
#define RSTRIDE 80
#define TILE_B  (128 * RSTRIDE)       // 10240
#define OFF_A   0
#define OFF_BH  (1 * TILE_B)
#define OFF_BL  (2 * TILE_B)
#define STAGE_B (3 * TILE_B)          // 30720
#define GEMM_SMEM (3 * STAGE_B)       // 92160

template <int MODE>
__global__ __launch_bounds__(256, 2) void gemm_mma_kernel(
    const __half* __restrict__ A,
    const __half* __restrict__ Bh, const __half* __restrict__ Bl,
    float* __restrict__ C,
    __half* __restrict__ q16,
    __half* __restrict__ kh, __half* __restrict__ kl,
    __half* __restrict__ vh, __half* __restrict__ vl,
    int M, int N, int K) {
    extern __shared__ __align__(128) char smem[];
    const uint32_t sb = smem_u32(smem);
    const int tid  = threadIdx.x;
    const int lane = tid & 31;
    const int wid  = tid >> 5;
    const int m0 = blockIdx.y * BM;
    const int n0 = blockIdx.x * BN;
    const int wm = (wid & 1) * 64;
    const int wn = (wid >> 1) * 32;
    const int NS = K / BK;

    const uint32_t a_off = (uint32_t)((lane & 15) * RSTRIDE + (lane >> 4) * 16);
    const uint32_t b_off = (uint32_t)((((lane >> 4) & 1) * 8 + (lane & 7)) * RSTRIDE +
                                      ((lane >> 3) & 1) * 16);

    float acc[4][4][4];
#pragma unroll
    for (int i = 0; i < 4; i++)
#pragma unroll
        for (int j = 0; j < 4; j++)
#pragma unroll
            for (int q = 0; q < 4; q++) acc[i][j][q] = 0.0f;

    auto load_stage = [&](int s) {
        const uint32_t base = sb + (uint32_t)(s % 3) * STAGE_B;
        const int k0 = s * BK;
        for (int i = tid; i < 512; i += 256) {
            int row = i >> 2;
            int ch  = (i & 3) * 16;                 // 16B chunk in 64B row
            uint32_t so = (uint32_t)(row * RSTRIDE + ch);
            size_t ga = (size_t)(m0 + row) * K + k0 + (ch >> 1);
            size_t gb = (size_t)(n0 + row) * K + k0 + (ch >> 1);
            cp16(base + OFF_A  + so, A  + ga);
            cp16(base + OFF_BH + so, Bh + gb);
            cp16(base + OFF_BL + so, Bl + gb);
        }
        CP_COMMIT();
    };

    load_stage(0);
    load_stage(1);

    for (int s = 0; s < NS; s++) {
        if (s + 1 < NS) { CP_WAIT1(); }   // stage s group complete
        else            { CP_WAIT0(); }
        __syncthreads();                  // prior readers of buffer (s+2)%3 done
        if (s + 2 < NS) load_stage(s + 2);

        const uint32_t base = sb + (uint32_t)(s % 3) * STAGE_B;
#pragma unroll
        for (int kk = 0; kk < 2; kk++) {
            const uint32_t koff = kk * 32;
            uint32_t af[4][4], bh_[2][4], bl_[2][4];
#pragma unroll
            for (int mt = 0; mt < 4; mt++) {
                uint32_t r = base + (uint32_t)((wm + mt * 16) * RSTRIDE) + koff;
                ldsm4(af[mt], r + OFF_A + a_off);
            }
#pragma unroll
            for (int ng = 0; ng < 2; ng++) {
                uint32_t r = base + (uint32_t)((wn + ng * 16) * RSTRIDE) + koff;
                ldsm4(bh_[ng], r + OFF_BH + b_off);
                ldsm4(bl_[ng], r + OFF_BL + b_off);
            }
#pragma unroll
            for (int mt = 0; mt < 4; mt++)
#pragma unroll
                for (int nt = 0; nt < 4; nt++)
                    mma16816(acc[mt][nt], af[mt], &bh_[nt >> 1][(nt & 1) * 2]);
#pragma unroll
            for (int mt = 0; mt < 4; mt++)
#pragma unroll
                for (int nt = 0; nt < 4; nt++)
                    mma16816(acc[mt][nt], af[mt], &bl_[nt >> 1][(nt & 1) * 2]);
        }
    }

    if (MODE == 0) {
#pragma unroll
        for (int mt = 0; mt < 4; mt++)
#pragma unroll
            for (int nt = 0; nt < 4; nt++) {
                int row = m0 + wm + mt * 16 + (lane >> 2);
                int col = n0 + wn + nt * 8 + (lane & 3) * 2;
                *(float2*)&C[(size_t)row * N + col] =
                    make_float2(acc[mt][nt][0], acc[mt][nt][1]);
                *(float2*)&C[(size_t)(row + 8) * N + col] =
                    make_float2(acc[mt][nt][2], acc[mt][nt][3]);
            }
    } else {
        const int sec = (n0 + wn) >> 10;          // 0=q 1=k 2=v
        const int hh  = ((n0 + wn) >> 6) & 15;
#pragma unroll
        for (int mt = 0; mt < 4; mt++)
#pragma unroll
            for (int nt = 0; nt < 4; nt++) {
                int row = m0 + wm + mt * 16 + (lane >> 2);
                int d   = ((wn + nt * 8) & 63) + (lane & 3) * 2;
                int b   = row >> 11;
                int ll  = row & 2047;
                size_t idx = ((size_t)(b * HEADS + hh) * LSEQ + ll) * KD + d;
                if (sec == 0) {
                    *(uint32_t*)(q16 + idx) =
                        pack2(h16(acc[mt][nt][0]), h16(acc[mt][nt][1]));
                    *(uint32_t*)(q16 + idx + (size_t)8 * KD) =
                        pack2(h16(acc[mt][nt][2]), h16(acc[mt][nt][3]));
                } else {
                    __half* H = (sec == 1) ? kh : vh;
                    __half* L = (sec == 1) ? kl : vl;
                    unsigned short h0, l0, h1, l1;
                    split2h(acc[mt][nt][0], h0, l0);
                    split2h(acc[mt][nt][1], h1, l1);
                    *(uint32_t*)(H + idx) = pack2(h0, h1);
                    *(uint32_t*)(L + idx) = pack2(l0, l1);
                    split2h(acc[mt][nt][2], h0, l0);
                    split2h(acc[mt][nt][3], h1, l1);
                    *(uint32_t*)(H + idx + (size_t)8 * KD) = pack2(h0, h1);
                    *(uint32_t*)(L + idx + (size_t)8 * KD) = pack2(l0, l1);
                }
            }
    }
}

// ---------------------------------------------------------------------------
// Flash attention, fp16 2-term: S = Q(Kh+Kl), O += P(Vh+Vl). 2 CTA/SM.
// ---------------------------------------------------------------------------
#define ASTRIDE 144
#define AQ_OFF  0
#define ASTG0   (128 * ASTRIDE)        // 18432 (Q single tile)
#define ASTG_SZ (4 * 64 * ASTRIDE)     // 36864 per stage (KH,KL,VH,VL)
#define AKH 0
#define AKL (64 * ASTRIDE)
#define AVH (2 * 64 * ASTRIDE)
#define AVL (3 * 64 * ASTRIDE)
#define ATT_SMEM (ASTG0 + 2 * ASTG_SZ) // 92160

__global__ __launch_bounds__(256, 2) void attn_mma_kernel(
    const __half* __restrict__ q16,
    const __half* __restrict__ kh, const __half* __restrict__ kl,
    const __half* __restrict__ vh, const __half* __restrict__ vl,
    __half* __restrict__ att16) {
    extern __shared__ __align__(128) char smem[];
    const uint32_t sb = smem_u32(smem);
    const int tid  = threadIdx.x;
    const int lane = tid & 31;
    const int wid  = tid >> 5;
    const int qt   = blockIdx.x;
    const int bh   = blockIdx.y;
    const int q0   = qt * 128;
    const int nkv  = 2 * qt + 2;

    const size_t hb = (size_t)bh * LSEQ * KD;
    const char* Qp = (const char*)(q16 + hb + (size_t)q0 * KD);
    const char* Kh = (const char*)(kh + hb);
    const char* Kl = (const char*)(kl + hb);
    const char* Vh = (const char*)(vh + hb);
    const char* Vl = (const char*)(vl + hb);

    auto load_q = [&]() {
        for (int i = tid; i < 1024; i += 256) {
            int row = i >> 3, ch = (i & 7) * 16;
            uint32_t so = (uint32_t)(row * ASTRIDE + ch);
            cp16(sb + AQ_OFF + so, Qp + (size_t)row * 128 + ch);
        }
    };
    auto load_stage = [&](int kt) {
        const uint32_t base = sb + ASTG0 + (uint32_t)(kt & 1) * ASTG_SZ;
        for (int i = tid; i < 512; i += 256) {
            int row = i >> 3, ch = (i & 7) * 16;
            uint32_t so = (uint32_t)(row * ASTRIDE + ch);
            size_t go = (size_t)(kt * 64 + row) * 128 + ch;
            cp16(base + AKH + so, Kh + go);
            cp16(base + AKL + so, Kl + go);
            cp16(base + AVH + so, Vh + go);
            cp16(base + AVL + so, Vl + go);
        }
        CP_COMMIT();
    };

    load_q();
    load_stage(0);   // Q + stage0 in one group

    const uint32_t a_off = (uint32_t)((lane & 15) * ASTRIDE + (lane >> 4) * 16);
    const uint32_t b_off = (uint32_t)((((lane >> 4) & 1) * 8 + (lane & 7)) * ASTRIDE +
                                      ((lane >> 3) & 1) * 16);
    const uint32_t v_off = (uint32_t)((lane & 15) * ASTRIDE + (lane >> 4) * 16);

    uint32_t qf[4][4];
    float oacc[8][4];
#pragma unroll
    for (int i = 0; i < 8; i++)
#pragma unroll
        for (int j = 0; j < 4; j++) oacc[i][j] = 0.0f;
    float mr0 = -1e30f, mr1 = -1e30f, lr0 = 0.0f, lr1 = 0.0f;

    const int r0 = q0 + wid * 16 + (lane >> 2);
    const int r1 = r0 + 8;

    for (int kt = 0; kt < nkv; kt++) {
        CP_WAIT0();
        __syncthreads();
        if (kt + 1 < nkv) load_stage(kt + 1);

        if (kt == 0) {
#pragma unroll
            for (int kc = 0; kc < 4; kc++) {
                uint32_t r = sb + (uint32_t)(wid * 16 * ASTRIDE) + kc * 32 + a_off;
                ldsm4(qf[kc], r + AQ_OFF);
            }
        }

        const uint32_t stg = sb + ASTG0 + (uint32_t)(kt & 1) * ASTG_SZ;

        // ---- S = Q (Kh + Kl) ----
        float sacc[8][4];
#pragma unroll
        for (int i = 0; i < 8; i++)
#pragma unroll
            for (int j = 0; j < 4; j++) sacc[i][j] = 0.0f;

#pragma unroll
        for (int kc = 0; kc < 4; kc++) {
            uint32_t khf[4][4], klf[4][4];
#pragma unroll
            for (int ng = 0; ng < 4; ng++) {
                uint32_t r = stg + (uint32_t)(ng * 16 * ASTRIDE) + kc * 32 + b_off;
                ldsm4(khf[ng], r + AKH);
                ldsm4(klf[ng], r + AKL);
            }
#pragma unroll
            for (int nt = 0; nt < 8; nt++)
                mma16816(sacc[nt], qf[kc], &khf[nt >> 1][(nt & 1) * 2]);
#pragma unroll
            for (int nt = 0; nt < 8; nt++)
                mma16816(sacc[nt], qf[kc], &klf[nt >> 1][(nt & 1) * 2]);
        }

        // ---- mask + scale ----
        const bool need_mask = (kt * 64 + 63) > (q0 + wid * 16);
        if (need_mask) {
#pragma unroll
            for (int nt = 0; nt < 8; nt++) {
                int colb = kt * 64 + nt * 8 + (lane & 3) * 2;
                sacc[nt][0] = (colb     <= r0) ? sacc[nt][0] * 0.125f : -1e30f;
                sacc[nt][1] = (colb + 1 <= r0) ? sacc[nt][1] * 0.125f : -1e30f;
                sacc[nt][2] = (colb     <= r1) ? sacc[nt][2] * 0.125f : -1e30f;
                sacc[nt][3] = (colb + 1 <= r1) ? sacc[nt][3] * 0.125f : -1e30f;
            }
        } else {
#pragma unroll
            for (int nt = 0; nt < 8; nt++)
#pragma unroll
                for (int e = 0; e < 4; e++) sacc[nt][e] *= 0.125f;
        }

        // ---- online softmax ----
        float m0 = -1e30f, m1 = -1e30f;
#pragma unroll
        for (int nt = 0; nt < 8; nt++) {
            m0 = fmaxf(m0, fmaxf(sacc[nt][0], sacc[nt][1]));
            m1 = fmaxf(m1, fmaxf(sacc[nt][2], sacc[nt][3]));
        }
        m0 = fmaxf(m0, __shfl_xor_sync(0xffffffffu, m0, 1));
        m0 = fmaxf(m0, __shfl_xor_sync(0xffffffffu, m0, 2));
        m1 = fmaxf(m1, __shfl_xor_sync(0xffffffffu, m1, 1));
        m1 = fmaxf(m1, __shfl_xor_sync(0xffffffffu, m1, 2));

        float mn0 = fmaxf(mr0, m0), mn1 = fmaxf(mr1, m1);
        float al0 = __expf(mr0 - mn0), al1 = __expf(mr1 - mn1);
        mr0 = mn0; mr1 = mn1;

        uint32_t pA[8], pB[8];
        float s0 = 0.0f, s1 = 0.0f;
#pragma unroll
        for (int nt = 0; nt < 8; nt++) {
            float p0 = __expf(sacc[nt][0] - mn0);
            float p1 = __expf(sacc[nt][1] - mn0);
            float p2 = __expf(sacc[nt][2] - mn1);
            float p3 = __expf(sacc[nt][3] - mn1);
            s0 += p0 + p1;
            s1 += p2 + p3;
            pA[nt] = pack2(h16(p0), h16(p1));
            pB[nt] = pack2(h16(p2), h16(p3));
        }
        s0 += __shfl_xor_sync(0xffffffffu, s0, 1);
        s0 += __shfl_xor_sync(0xffffffffu, s0, 2);
        s1 += __shfl_xor_sync(0xffffffffu, s1, 1);
        s1 += __shfl_xor_sync(0xffffffffu, s1, 2);
        lr0 = lr0 * al0 + s0;
        lr1 = lr1 * al1 + s1;

#pragma unroll
        for (int dt = 0; dt < 8; dt++) {
            oacc[dt][0] *= al0; oacc[dt][1] *= al0;
            oacc[dt][2] *= al1; oacc[dt][3] *= al1;
        }

        // ---- O += P (Vh + Vl) ----
#pragma unroll
        for (int kc = 0; kc < 4; kc++) {
            uint32_t pf[4] = {pA[2 * kc], pB[2 * kc], pA[2 * kc + 1], pB[2 * kc + 1]};
            uint32_t v4h[4][4], v4l[4][4];
#pragma unroll
            for (int dg = 0; dg < 4; dg++) {
                uint32_t r = stg + (uint32_t)(kc * 16 * ASTRIDE) + dg * 32 + v_off;
                ldsm4t(v4h[dg], r + AVH);
                ldsm4t(v4l[dg], r + AVL);
            }
#pragma unroll
            for (int dg = 0; dg < 4; dg++) {
                mma16816(oacc[dg * 2],     pf, &v4h[dg][0]);
                mma16816(oacc[dg * 2 + 1], pf, &v4h[dg][2]);
            }
#pragma unroll
            for (int dg = 0; dg < 4; dg++) {
                mma16816(oacc[dg * 2],     pf, &v4l[dg][0]);
                mma16816(oacc[dg * 2 + 1], pf, &v4l[dg][2]);
            }
        }
    }

    // ---- epilogue: normalize, fp16, write att[token][h*64+d] ----
    const float inv0 = 1.0f / lr0, inv1 = 1.0f / lr1;
    const int b = bh >> 4, hh = bh & 15;
    size_t base0 = ((size_t)(b * LSEQ + r0)) * DMODEL + hh * KD + (lane & 3) * 2;
    size_t base1 = base0 + (size_t)8 * DMODEL;
#pragma unroll
    for (int dt = 0; dt < 8; dt++) {
        *(uint32_t*)(att16 + base0 + dt * 8) =
            pack2(h16(oacc[dt][0] * inv0), h16(oacc[dt][1] * inv0));
        *(uint32_t*)(att16 + base1 + dt * 8) =
            pack2(h16(oacc[dt][2] * inv1), h16(oacc[dt][3] * inv1));
    }
}

// ---------------------------------------------------------------------------
extern "C" void kernel_launch(void* const* d_in, const int* in_sizes, int n_in,
                              void* d_out, int out_size) {
    const float* x    = (const float*)d_in[0];
    const float* Wqkv = (const float*)d_in[1];
    const float* Wout = (const float*)d_in[2];
    float* out = (float*)d_out;

    __half *x16, *wqh, *wql, *woh, *wol;
    __half *q16, *kh, *kl, *vh, *vl, *att16;
    cudaGetSymbolAddress((void**)&x16, g_x16);
    cudaGetSymbolAddress((void**)&wqh, g_wqkvT_h);
    cudaGetSymbolAddress((void**)&wql, g_wqkvT_l);
    cudaGetSymbolAddress((void**)&woh, g_woutT_h);
    cudaGetSymbolAddress((void**)&wol, g_woutT_l);
    cudaGetSymbolAddress((void**)&q16, g_q16);
    cudaGetSymbolAddress((void**)&kh, g_kh);
    cudaGetSymbolAddress((void**)&kl, g_kl);
    cudaGetSymbolAddress((void**)&vh, g_vh);
    cudaGetSymbolAddress((void**)&vl, g_vl);
    cudaGetSymbolAddress((void**)&att16, g_att16);

    cudaFuncSetAttribute((const void*)gemm_mma_kernel<0>,
                         cudaFuncAttributeMaxDynamicSharedMemorySize, GEMM_SMEM);
    cudaFuncSetAttribute((const void*)gemm_mma_kernel<1>,
                         cudaFuncAttributeMaxDynamicSharedMemorySize, GEMM_SMEM);
    cudaFuncSetAttribute((const void*)attn_mma_kernel,
                         cudaFuncAttributeMaxDynamicSharedMemorySize, ATT_SMEM);

    // prep
    {
        int n4 = TOKENS * DMODEL / 4;
        convert_f16_kernel<<<(n4 + 255) / 256, 256>>>(x, x16, n4);
        transpose_split_kernel<<<dim3(3 * DMODEL / 32, DMODEL / 32), dim3(32, 8)>>>(
            Wqkv, wqh, wql, DMODEL, 3 * DMODEL);
        transpose_split_kernel<<<dim3(DMODEL / 32, DMODEL / 32), dim3(32, 8)>>>(
            Wout, woh, wol, DMODEL, DMODEL);
    }

    // 1) qkv GEMM -> fp16 head-major q (single) / k,v (split)
    gemm_mma_kernel<1><<<dim3(3 * DMODEL / BN, TOKENS / BM), 256, GEMM_SMEM>>>(
        x16, wqh, wql, nullptr, q16, kh, kl, vh, vl,
        TOKENS, 3 * DMODEL, DMODEL);

    // 2) tensor-core causal flash attention -> att fp16
    attn_mma_kernel<<<dim3(LSEQ / 128, BH_CNT), 256, ATT_SMEM>>>(
        q16, kh, kl, vh, vl, att16);

    // 3) out = att @ Wout
    gemm_mma_kernel<0><<<dim3(DMODEL / BN, TOKENS / BM), 256, GEMM_SMEM>>>(
        att16, woh, wol, out, nullptr, nullptr, nullptr, nullptr, nullptr,
        TOKENS, DMODEL, DMODEL);
}

// round 8
// speedup vs baseline: 6.2462x; 1.5283x over previous
#include <cuda_runtime.h>
#include <cuda_fp16.h>
#include <cstdint>

// ----------------------------------------------------------------------------
// SelfAttention: out = Attn(x @ Wqkv) @ Wout, causal, H=16, Kd=64
// B=4, L=2048, D=1024 -> tokens = 8192
// R8: pure fp16 HMMA everywhere (no hi/lo splits), fp32 accum.
//     Calibrated error model predicts rel_err ~4.5e-4 < 1e-3.
// ----------------------------------------------------------------------------

#define TOKENS 8192
#define LSEQ   2048
#define DMODEL 1024
#define HEADS  16
#define KD     64
#define BH_CNT (4 * HEADS)   // 64

// ---------------- scratch ----------------------------------------------------
__device__ __half g_x16[(size_t)TOKENS * DMODEL];
__device__ __half g_wqkvT[(size_t)3 * DMODEL * DMODEL];
__device__ __half g_woutT[(size_t)DMODEL * DMODEL];
__device__ __half g_q16[(size_t)BH_CNT * LSEQ * KD];
__device__ __half g_k16[(size_t)BH_CNT * LSEQ * KD];
__device__ __half g_v16[(size_t)BH_CNT * LSEQ * KD];
__device__ __half g_att16[(size_t)TOKENS * DMODEL];

// ---------------- helpers ----------------------------------------------------
__device__ __forceinline__ uint32_t smem_u32(const void* p) {
    uint32_t a;
    asm("{ .reg .u64 t; cvta.to.shared.u64 t, %1; cvt.u32.u64 %0, t; }" : "=r"(a) : "l"(p));
    return a;
}
__device__ __forceinline__ void cp16(uint32_t s, const void* g) {
    asm volatile("cp.async.cg.shared.global [%0], [%1], 16;" :: "r"(s), "l"(g));
}
#define CP_COMMIT() asm volatile("cp.async.commit_group;" ::: "memory")
#define CP_WAIT0()  asm volatile("cp.async.wait_group 0;" ::: "memory")
#define CP_WAIT1()  asm volatile("cp.async.wait_group 1;" ::: "memory")

__device__ __forceinline__ void ldsm4(uint32_t* r, uint32_t addr) {
    asm volatile("ldmatrix.sync.aligned.m8n8.x4.shared.b16 {%0,%1,%2,%3}, [%4];"
                 : "=r"(r[0]), "=r"(r[1]), "=r"(r[2]), "=r"(r[3]) : "r"(addr));
}
__device__ __forceinline__ void ldsm4t(uint32_t* r, uint32_t addr) {
    asm volatile("ldmatrix.sync.aligned.m8n8.x4.trans.shared.b16 {%0,%1,%2,%3}, [%4];"
                 : "=r"(r[0]), "=r"(r[1]), "=r"(r[2]), "=r"(r[3]) : "r"(addr));
}
__device__ __forceinline__ void mma16816(float* c, const uint32_t* a, const uint32_t* b) {
    asm volatile("mma.sync.aligned.m16n8k16.row.col.f32.f16.f16.f32 "
                 "{%0,%1,%2,%3}, {%4,%5,%6,%7}, {%8,%9}, {%0,%1,%2,%3};"
                 : "+f"(c[0]), "+f"(c[1]), "+f"(c[2]), "+f"(c[3])
                 : "r"(a[0]), "r"(a[1]), "r"(a[2]), "r"(a[3]), "r"(b[0]), "r"(b[1]));
}
__device__ __forceinline__ unsigned short h16(float v) {
    return __half_as_ushort(__float2half_rn(v));
}
__device__ __forceinline__ uint32_t pack2(unsigned short a, unsigned short b) {
    return (uint32_t)a | ((uint32_t)b << 16);
}

// ---------------------------------------------------------------------------
// Prep kernels
// ---------------------------------------------------------------------------
__global__ void convert_f16_kernel(const float* __restrict__ in,
                                   __half* __restrict__ o16, int n4) {
    int i = blockIdx.x * blockDim.x + threadIdx.x;
    if (i >= n4) return;
    float4 v = ((const float4*)in)[i];
    ((ushort4*)o16)[i] = make_ushort4(h16(v.x), h16(v.y), h16(v.z), h16(v.w));
}

__global__ void transpose_f16_kernel(const float* __restrict__ W,
                                     __half* __restrict__ T16,
                                     int K, int N) {
    __shared__ float t[32][33];
    int n0 = blockIdx.x * 32, k0 = blockIdx.y * 32;
    int tx = threadIdx.x, ty = threadIdx.y;
#pragma unroll
    for (int j = 0; j < 4; j++) {
        int k = ty + j * 8;
        t[k][tx] = W[(size_t)(k0 + k) * N + n0 + tx];
    }
    __syncthreads();
#pragma unroll
    for (int j = 0; j < 4; j++) {
        int nl = ty + j * 8;
        T16[(size_t)(n0 + nl) * K + k0 + tx] = __ushort_as_half(h16(t[tx][nl]));
    }
}

// ---------------------------------------------------------------------------
// HMMA GEMM, pure fp16: C = A * B^T. 128x128 tile, BK=32, 8 warps,
// 3-stage cp.async pipeline, 2 CTA/SM.
// MODE 0: C fp32.  MODE 1: head-major fp16 q/k/v epilogue.
// ---------------------------------------------------------------------------
#define BM 128
#define BN 128
#define BK 32
#define RSTRIDE 80
#define TILE_B  (128 * RSTRIDE)       // 10240
#define OFF_A   0
#define OFF_B   (1 * TILE_B)
#define STAGE_B (2 * TILE_B)          // 20480
#define GEMM_SMEM (3 * STAGE_B)       // 61440

template <int MODE>
__global__ __launch_bounds__(256, 2) void gemm_mma_kernel(
    const __half* __restrict__ A, const __half* __restrict__ B,
    float* __restrict__ C,
    __half* __restrict__ q16, __half* __restrict__ k16, __half* __restrict__ v16,
    int M, int N, int K) {
    extern __shared__ __align__(128) char smem[];
    const uint32_t sb = smem_u32(smem);
    const int tid  = threadIdx.x;
    const int lane = tid & 31;
    const int wid  = tid >> 5;
    const int m0 = blockIdx.y * BM;
    const int n0 = blockIdx.x * BN;
    const int wm = (wid & 1) * 64;
    const int wn = (wid >> 1) * 32;
    const int NS = K / BK;

    const uint32_t a_off = (uint32_t)((lane & 15) * RSTRIDE + (lane >> 4) * 16);
    const uint32_t b_off = (uint32_t)((((lane >> 4) & 1) * 8 + (lane & 7)) * RSTRIDE +
                                      ((lane >> 3) & 1) * 16);

    float acc[4][4][4];
#pragma unroll
    for (int i = 0; i < 4; i++)
#pragma unroll
        for (int j = 0; j < 4; j++)
#pragma unroll
            for (int q = 0; q < 4; q++) acc[i][j][q] = 0.0f;

    auto load_stage = [&](int s) {
        const uint32_t base = sb + (uint32_t)(s % 3) * STAGE_B;
        const int k0 = s * BK;
        for (int i = tid; i < 512; i += 256) {
            int row = i >> 2;
            int ch  = (i & 3) * 16;
            uint32_t so = (uint32_t)(row * RSTRIDE + ch);
            size_t ga = (size_t)(m0 + row) * K + k0 + (ch >> 1);
            size_t gb = (size_t)(n0 + row) * K + k0 + (ch >> 1);
            cp16(base + OFF_A + so, A + ga);
            cp16(base + OFF_B + so, B + gb);
        }
        CP_COMMIT();
    };

    load_stage(0);
    load_stage(1);

    for (int s = 0; s < NS; s++) {
        if (s + 1 < NS) { CP_WAIT1(); }
        else            { CP_WAIT0(); }
        __syncthreads();
        if (s + 2 < NS) load_stage(s + 2);

        const uint32_t base = sb + (uint32_t)(s % 3) * STAGE_B;
#pragma unroll
        for (int kk = 0; kk < 2; kk++) {
            const uint32_t koff = kk * 32;
            uint32_t af[4][4], bf[2][4];
#pragma unroll
            for (int mt = 0; mt < 4; mt++) {
                uint32_t r = base + (uint32_t)((wm + mt * 16) * RSTRIDE) + koff;
                ldsm4(af[mt], r + OFF_A + a_off);
            }
#pragma unroll
            for (int ng = 0; ng < 2; ng++) {
                uint32_t r = base + (uint32_t)((wn + ng * 16) * RSTRIDE) + koff;
                ldsm4(bf[ng], r + OFF_B + b_off);
            }
#pragma unroll
            for (int mt = 0; mt < 4; mt++)
#pragma unroll
                for (int nt = 0; nt < 4; nt++)
                    mma16816(acc[mt][nt], af[mt], &bf[nt >> 1][(nt & 1) * 2]);
        }
    }

    if (MODE == 0) {
#pragma unroll
        for (int mt = 0; mt < 4; mt++)
#pragma unroll
            for (int nt = 0; nt < 4; nt++) {
                int row = m0 + wm + mt * 16 + (lane >> 2);
                int col = n0 + wn + nt * 8 + (lane & 3) * 2;
                *(float2*)&C[(size_t)row * N + col] =
                    make_float2(acc[mt][nt][0], acc[mt][nt][1]);
                *(float2*)&C[(size_t)(row + 8) * N + col] =
                    make_float2(acc[mt][nt][2], acc[mt][nt][3]);
            }
    } else {
        const int sec = (n0 + wn) >> 10;          // 0=q 1=k 2=v
        const int hh  = ((n0 + wn) >> 6) & 15;
        __half* DST = (sec == 0) ? q16 : (sec == 1) ? k16 : v16;
#pragma unroll
        for (int mt = 0; mt < 4; mt++)
#pragma unroll
            for (int nt = 0; nt < 4; nt++) {
                int row = m0 + wm + mt * 16 + (lane >> 2);
                int d   = ((wn + nt * 8) & 63) + (lane & 3) * 2;
                int b   = row >> 11;
                int ll  = row & 2047;
                size_t idx = ((size_t)(b * HEADS + hh) * LSEQ + ll) * KD + d;
                *(uint32_t*)(DST + idx) =
                    pack2(h16(acc[mt][nt][0]), h16(acc[mt][nt][1]));
                *(uint32_t*)(DST + idx + (size_t)8 * KD) =
                    pack2(h16(acc[mt][nt][2]), h16(acc[mt][nt][3]));
            }
    }
}

// ---------------------------------------------------------------------------
// Flash attention, pure fp16 MMA, causal. 2-stage pipeline.
// ---------------------------------------------------------------------------
#define ASTRIDE 144
#define AQ_OFF  0
#define ASTG0   (128 * ASTRIDE)        // 18432 (Q tile)
#define ASTG_SZ (2 * 64 * ASTRIDE)     // 18432 per stage (K, V)
#define AK 0
#define AV (64 * ASTRIDE)
#define ATT_SMEM (ASTG0 + 2 * ASTG_SZ) // 55296

__global__ __launch_bounds__(256, 2) void attn_mma_kernel(
    const __half* __restrict__ q16,
    const __half* __restrict__ k16, const __half* __restrict__ v16,
    __half* __restrict__ att16) {
    extern __shared__ __align__(128) char smem[];
    const uint32_t sb = smem_u32(smem);
    const int tid  = threadIdx.x;
    const int lane = tid & 31;
    const int wid  = tid >> 5;
    const int qt   = blockIdx.x;
    const int bh   = blockIdx.y;
    const int q0   = qt * 128;
    const int nkv  = 2 * qt + 2;

    const size_t hb = (size_t)bh * LSEQ * KD;
    const char* Qp = (const char*)(q16 + hb + (size_t)q0 * KD);
    const char* Kp = (const char*)(k16 + hb);
    const char* Vp = (const char*)(v16 + hb);

    auto load_q = [&]() {
        for (int i = tid; i < 1024; i += 256) {
            int row = i >> 3, ch = (i & 7) * 16;
            uint32_t so = (uint32_t)(row * ASTRIDE + ch);
            cp16(sb + AQ_OFF + so, Qp + (size_t)row * 128 + ch);
        }
    };
    auto load_stage = [&](int kt) {
        const uint32_t base = sb + ASTG0 + (uint32_t)(kt & 1) * ASTG_SZ;
        for (int i = tid; i < 512; i += 256) {
            int row = i >> 3, ch = (i & 7) * 16;
            uint32_t so = (uint32_t)(row * ASTRIDE + ch);
            size_t go = (size_t)(kt * 64 + row) * 128 + ch;
            cp16(base + AK + so, Kp + go);
            cp16(base + AV + so, Vp + go);
        }
        CP_COMMIT();
    };

    load_q();
    load_stage(0);

    const uint32_t a_off = (uint32_t)((lane & 15) * ASTRIDE + (lane >> 4) * 16);
    const uint32_t b_off = (uint32_t)((((lane >> 4) & 1) * 8 + (lane & 7)) * ASTRIDE +
                                      ((lane >> 3) & 1) * 16);
    const uint32_t v_off = (uint32_t)((lane & 15) * ASTRIDE + (lane >> 4) * 16);

    uint32_t qf[4][4];
    float oacc[8][4];
#pragma unroll
    for (int i = 0; i < 8; i++)
#pragma unroll
        for (int j = 0; j < 4; j++) oacc[i][j] = 0.0f;
    float mr0 = -1e30f, mr1 = -1e30f, lr0 = 0.0f, lr1 = 0.0f;

    const int r0 = q0 + wid * 16 + (lane >> 2);
    const int r1 = r0 + 8;

    for (int kt = 0; kt < nkv; kt++) {
        CP_WAIT0();
        __syncthreads();
        if (kt + 1 < nkv) load_stage(kt + 1);

        if (kt == 0) {
#pragma unroll
            for (int kc = 0; kc < 4; kc++) {
                uint32_t r = sb + (uint32_t)(wid * 16 * ASTRIDE) + kc * 32 + a_off;
                ldsm4(qf[kc], r + AQ_OFF);
            }
        }

        const uint32_t stg = sb + ASTG0 + (uint32_t)(kt & 1) * ASTG_SZ;

        // ---- S = Q K^T ----
        float sacc[8][4];
#pragma unroll
        for (int i = 0; i < 8; i++)
#pragma unroll
            for (int j = 0; j < 4; j++) sacc[i][j] = 0.0f;

#pragma unroll
        for (int kc = 0; kc < 4; kc++) {
            uint32_t kf[4][4];
#pragma unroll
            for (int ng = 0; ng < 4; ng++) {
                uint32_t r = stg + (uint32_t)(ng * 16 * ASTRIDE) + kc * 32 + b_off;
                ldsm4(kf[ng], r + AK);
            }
#pragma unroll
            for (int nt = 0; nt < 8; nt++)
                mma16816(sacc[nt], qf[kc], &kf[nt >> 1][(nt & 1) * 2]);
        }

        // ---- mask + scale ----
        const bool need_mask = (kt * 64 + 63) > (q0 + wid * 16);
        if (need_mask) {
#pragma unroll
            for (int nt = 0; nt < 8; nt++) {
                int colb = kt * 64 + nt * 8 + (lane & 3) * 2;
                sacc[nt][0] = (colb     <= r0) ? sacc[nt][0] * 0.125f : -1e30f;
                sacc[nt][1] = (colb + 1 <= r0) ? sacc[nt][1] * 0.125f : -1e30f;
                sacc[nt][2] = (colb     <= r1) ? sacc[nt][2] * 0.125f : -1e30f;
                sacc[nt][3] = (colb + 1 <= r1) ? sacc[nt][3] * 0.125f : -1e30f;
            }
        } else {
#pragma unroll
            for (int nt = 0; nt < 8; nt++)
#pragma unroll
                for (int e = 0; e < 4; e++) sacc[nt][e] *= 0.125f;
        }

        // ---- online softmax ----
        float m0 = -1e30f, m1 = -1e30f;
#pragma unroll
        for (int nt = 0; nt < 8; nt++) {
            m0 = fmaxf(m0, fmaxf(sacc[nt][0], sacc[nt][1]));
            m1 = fmaxf(m1, fmaxf(sacc[nt][2], sacc[nt][3]));
        }
        m0 = fmaxf(m0, __shfl_xor_sync(0xffffffffu, m0, 1));
        m0 = fmaxf(m0, __shfl_xor_sync(0xffffffffu, m0, 2));
        m1 = fmaxf(m1, __shfl_xor_sync(0xffffffffu, m1, 1));
        m1 = fmaxf(m1, __shfl_xor_sync(0xffffffffu, m1, 2));

        float mn0 = fmaxf(mr0, m0), mn1 = fmaxf(mr1, m1);
        float al0 = __expf(mr0 - mn0), al1 = __expf(mr1 - mn1);
        mr0 = mn0; mr1 = mn1;

        uint32_t pA[8], pB[8];
        float s0 = 0.0f, s1 = 0.0f;
#pragma unroll
        for (int nt = 0; nt < 8; nt++) {
            float p0 = __expf(sacc[nt][0] - mn0);
            float p1 = __expf(sacc[nt][1] - mn0);
            float p2 = __expf(sacc[nt][2] - mn1);
            float p3 = __expf(sacc[nt][3] - mn1);
            s0 += p0 + p1;
            s1 += p2 + p3;
            pA[nt] = pack2(h16(p0), h16(p1));
            pB[nt] = pack2(h16(p2), h16(p3));
        }
        s0 += __shfl_xor_sync(0xffffffffu, s0, 1);
        s0 += __shfl_xor_sync(0xffffffffu, s0, 2);
        s1 += __shfl_xor_sync(0xffffffffu, s1, 1);
        s1 += __shfl_xor_sync(0xffffffffu, s1, 2);
        lr0 = lr0 * al0 + s0;
        lr1 = lr1 * al1 + s1;

#pragma unroll
        for (int dt = 0; dt < 8; dt++) {
            oacc[dt][0] *= al0; oacc[dt][1] *= al0;
            oacc[dt][2] *= al1; oacc[dt][3] *= al1;
        }

        // ---- O += P V ----
#pragma unroll
        for (int kc = 0; kc < 4; kc++) {
            uint32_t pf[4] = {pA[2 * kc], pB[2 * kc], pA[2 * kc + 1], pB[2 * kc + 1]};
            uint32_t vf[4][4];
#pragma unroll
            for (int dg = 0; dg < 4; dg++) {
                uint32_t r = stg + (uint32_t)(kc * 16 * ASTRIDE) + dg * 32 + v_off;
                ldsm4t(vf[dg], r + AV);
            }
#pragma unroll
            for (int dg = 0; dg < 4; dg++) {
                mma16816(oacc[dg * 2],     pf, &vf[dg][0]);
                mma16816(oacc[dg * 2 + 1], pf, &vf[dg][2]);
            }
        }
    }

    // ---- epilogue ----
    const float inv0 = 1.0f / lr0, inv1 = 1.0f / lr1;
    const int b = bh >> 4, hh = bh & 15;
    size_t base0 = ((size_t)(b * LSEQ + r0)) * DMODEL + hh * KD + (lane & 3) * 2;
    size_t base1 = base0 + (size_t)8 * DMODEL;
#pragma unroll
    for (int dt = 0; dt < 8; dt++) {
        *(uint32_t*)(att16 + base0 + dt * 8) =
            pack2(h16(oacc[dt][0] * inv0), h16(oacc[dt][1] * inv0));
        *(uint32_t*)(att16 + base1 + dt * 8) =
            pack2(h16(oacc[dt][2] * inv1), h16(oacc[dt][3] * inv1));
    }
}

// ---------------------------------------------------------------------------
extern "C" void kernel_launch(void* const* d_in, const int* in_sizes, int n_in,
                              void* d_out, int out_size) {
    const float* x    = (const float*)d_in[0];
    const float* Wqkv = (const float*)d_in[1];
    const float* Wout = (const float*)d_in[2];
    float* out = (float*)d_out;

    __half *x16, *wq16, *wo16, *q16, *k16, *v16, *att16;
    cudaGetSymbolAddress((void**)&x16, g_x16);
    cudaGetSymbolAddress((void**)&wq16, g_wqkvT);
    cudaGetSymbolAddress((void**)&wo16, g_woutT);
    cudaGetSymbolAddress((void**)&q16, g_q16);
    cudaGetSymbolAddress((void**)&k16, g_k16);
    cudaGetSymbolAddress((void**)&v16, g_v16);
    cudaGetSymbolAddress((void**)&att16, g_att16);

    cudaFuncSetAttribute((const void*)gemm_mma_kernel<0>,
                         cudaFuncAttributeMaxDynamicSharedMemorySize, GEMM_SMEM);
    cudaFuncSetAttribute((const void*)gemm_mma_kernel<1>,
                         cudaFuncAttributeMaxDynamicSharedMemorySize, GEMM_SMEM);
    cudaFuncSetAttribute((const void*)attn_mma_kernel,
                         cudaFuncAttributeMaxDynamicSharedMemorySize, ATT_SMEM);

    // prep
    {
        int n4 = TOKENS * DMODEL / 4;
        convert_f16_kernel<<<(n4 + 255) / 256, 256>>>(x, x16, n4);
        transpose_f16_kernel<<<dim3(3 * DMODEL / 32, DMODEL / 32), dim3(32, 8)>>>(
            Wqkv, wq16, DMODEL, 3 * DMODEL);
        transpose_f16_kernel<<<dim3(DMODEL / 32, DMODEL / 32), dim3(32, 8)>>>(
            Wout, wo16, DMODEL, DMODEL);
    }

    // 1) qkv GEMM -> fp16 head-major q/k/v
    gemm_mma_kernel<1><<<dim3(3 * DMODEL / BN, TOKENS / BM), 256, GEMM_SMEM>>>(
        x16, wq16, nullptr, q16, k16, v16, TOKENS, 3 * DMODEL, DMODEL);

    // 2) tensor-core causal flash attention -> att fp16
    attn_mma_kernel<<<dim3(LSEQ / 128, BH_CNT), 256, ATT_SMEM>>>(
        q16, k16, v16, att16);

    // 3) out = att @ Wout
    gemm_mma_kernel<0><<<dim3(DMODEL / BN, TOKENS / BM), 256, GEMM_SMEM>>>(
        att16, wo16, out, nullptr, nullptr, nullptr, TOKENS, DMODEL, DMODEL);
}

// round 9
// speedup vs baseline: 6.6530x; 1.0651x over previous
#include <cuda_runtime.h>
#include <cuda_fp16.h>
#include <cstdint>

// ----------------------------------------------------------------------------
// SelfAttention: out = Attn(x @ Wqkv) @ Wout, causal, H=16, Kd=64
// B=4, L=2048, D=1024 -> tokens = 8192
// R9: pure fp16 HMMA; GEMM BK 32->64 (half the barriers, 64 MMAs/stage),
//     3-stage cp.async pipeline, 2 CTA/SM. Attention unchanged from R8.
// ----------------------------------------------------------------------------

#define TOKENS 8192
#define LSEQ   2048
#define DMODEL 1024
#define HEADS  16
#define KD     64
#define BH_CNT (4 * HEADS)   // 64

// ---------------- scratch ----------------------------------------------------
__device__ __half g_x16[(size_t)TOKENS * DMODEL];
__device__ __half g_wqkvT[(size_t)3 * DMODEL * DMODEL];
__device__ __half g_woutT[(size_t)DMODEL * DMODEL];
__device__ __half g_q16[(size_t)BH_CNT * LSEQ * KD];
__device__ __half g_k16[(size_t)BH_CNT * LSEQ * KD];
__device__ __half g_v16[(size_t)BH_CNT * LSEQ * KD];
__device__ __half g_att16[(size_t)TOKENS * DMODEL];

// ---------------- helpers ----------------------------------------------------
__device__ __forceinline__ uint32_t smem_u32(const void* p) {
    uint32_t a;
    asm("{ .reg .u64 t; cvta.to.shared.u64 t, %1; cvt.u32.u64 %0, t; }" : "=r"(a) : "l"(p));
    return a;
}
__device__ __forceinline__ void cp16(uint32_t s, const void* g) {
    asm volatile("cp.async.cg.shared.global [%0], [%1], 16;" :: "r"(s), "l"(g));
}
#define CP_COMMIT() asm volatile("cp.async.commit_group;" ::: "memory")
#define CP_WAIT0()  asm volatile("cp.async.wait_group 0;" ::: "memory")
#define CP_WAIT1()  asm volatile("cp.async.wait_group 1;" ::: "memory")

__device__ __forceinline__ void ldsm4(uint32_t* r, uint32_t addr) {
    asm volatile("ldmatrix.sync.aligned.m8n8.x4.shared.b16 {%0,%1,%2,%3}, [%4];"
                 : "=r"(r[0]), "=r"(r[1]), "=r"(r[2]), "=r"(r[3]) : "r"(addr));
}
__device__ __forceinline__ void ldsm4t(uint32_t* r, uint32_t addr) {
    asm volatile("ldmatrix.sync.aligned.m8n8.x4.trans.shared.b16 {%0,%1,%2,%3}, [%4];"
                 : "=r"(r[0]), "=r"(r[1]), "=r"(r[2]), "=r"(r[3]) : "r"(addr));
}
__device__ __forceinline__ void mma16816(float* c, const uint32_t* a, const uint32_t* b) {
    asm volatile("mma.sync.aligned.m16n8k16.row.col.f32.f16.f16.f32 "
                 "{%0,%1,%2,%3}, {%4,%5,%6,%7}, {%8,%9}, {%0,%1,%2,%3};"
                 : "+f"(c[0]), "+f"(c[1]), "+f"(c[2]), "+f"(c[3])
                 : "r"(a[0]), "r"(a[1]), "r"(a[2]), "r"(a[3]), "r"(b[0]), "r"(b[1]));
}
__device__ __forceinline__ unsigned short h16(float v) {
    return __half_as_ushort(__float2half_rn(v));
}
__device__ __forceinline__ uint32_t pack2(unsigned short a, unsigned short b) {
    return (uint32_t)a | ((uint32_t)b << 16);
}

// ---------------------------------------------------------------------------
// Prep kernels
// ---------------------------------------------------------------------------
__global__ void convert_f16_kernel(const float* __restrict__ in,
                                   __half* __restrict__ o16, int n4) {
    int i = blockIdx.x * blockDim.x + threadIdx.x;
    if (i >= n4) return;
    float4 v = ((const float4*)in)[i];
    ((ushort4*)o16)[i] = make_ushort4(h16(v.x), h16(v.y), h16(v.z), h16(v.w));
}

__global__ void transpose_f16_kernel(const float* __restrict__ W,
                                     __half* __restrict__ T16,
                                     int K, int N) {
    __shared__ float t[32][33];
    int n0 = blockIdx.x * 32, k0 = blockIdx.y * 32;
    int tx = threadIdx.x, ty = threadIdx.y;
#pragma unroll
    for (int j = 0; j < 4; j++) {
        int k = ty + j * 8;
        t[k][tx] = W[(size_t)(k0 + k) * N + n0 + tx];
    }
    __syncthreads();
#pragma unroll
    for (int j = 0; j < 4; j++) {
        int nl = ty + j * 8;
        T16[(size_t)(n0 + nl) * K + k0 + tx] = __ushort_as_half(h16(t[tx][nl]));
    }
}

// ---------------------------------------------------------------------------
// HMMA GEMM, pure fp16: C = A * B^T. 128x128 tile, BK=64, 8 warps,
// 3-stage cp.async pipeline, 2 CTA/SM. 64 MMAs per barrier.
// MODE 0: C fp32.  MODE 1: head-major fp16 q/k/v epilogue.
// ---------------------------------------------------------------------------
#define BM 128
#define BN 128
#define BK 64
#define RSTRIDE 144                    // 128B data + 16B pad (16B-aligned)
#define TILE_B  (128 * RSTRIDE)        // 18432
#define OFF_A   0
#define OFF_B   (1 * TILE_B)
#define STAGE_B (2 * TILE_B)           // 36864
#define GEMM_SMEM (3 * STAGE_B)        // 110592

template <int MODE>
__global__ __launch_bounds__(256, 2) void gemm_mma_kernel(
    const __half* __restrict__ A, const __half* __restrict__ B,
    float* __restrict__ C,
    __half* __restrict__ q16, __half* __restrict__ k16, __half* __restrict__ v16,
    int M, int N, int K) {
    extern __shared__ __align__(128) char smem[];
    const uint32_t sb = smem_u32(smem);
    const int tid  = threadIdx.x;
    const int lane = tid & 31;
    const int wid  = tid >> 5;
    const int m0 = blockIdx.y * BM;
    const int n0 = blockIdx.x * BN;
    const int wm = (wid & 1) * 64;
    const int wn = (wid >> 1) * 32;
    const int NS = K / BK;             // 16

    const uint32_t a_off = (uint32_t)((lane & 15) * RSTRIDE + (lane >> 4) * 16);
    const uint32_t b_off = (uint32_t)((((lane >> 4) & 1) * 8 + (lane & 7)) * RSTRIDE +
                                      ((lane >> 3) & 1) * 16);

    float acc[4][4][4];
#pragma unroll
    for (int i = 0; i < 4; i++)
#pragma unroll
        for (int j = 0; j < 4; j++)
#pragma unroll
            for (int q = 0; q < 4; q++) acc[i][j][q] = 0.0f;

    auto load_stage = [&](int s) {
        const uint32_t base = sb + (uint32_t)(s % 3) * STAGE_B;
        const int k0 = s * BK;
        // A: 128 rows x 8 chunks of 16B
        for (int i = tid; i < 1024; i += 256) {
            int row = i >> 3;
            int ch  = (i & 7) * 16;
            uint32_t so = (uint32_t)(row * RSTRIDE + ch);
            cp16(base + OFF_A + so, A + (size_t)(m0 + row) * K + k0 + (ch >> 1));
        }
        // B: 128 rows x 8 chunks of 16B
        for (int i = tid; i < 1024; i += 256) {
            int row = i >> 3;
            int ch  = (i & 7) * 16;
            uint32_t so = (uint32_t)(row * RSTRIDE + ch);
            cp16(base + OFF_B + so, B + (size_t)(n0 + row) * K + k0 + (ch >> 1));
        }
        CP_COMMIT();
    };

    load_stage(0);
    load_stage(1);

    for (int s = 0; s < NS; s++) {
        if (s + 1 < NS) { CP_WAIT1(); }
        else            { CP_WAIT0(); }
        __syncthreads();
        if (s + 2 < NS) load_stage(s + 2);

        const uint32_t base = sb + (uint32_t)(s % 3) * STAGE_B;
#pragma unroll
        for (int kk = 0; kk < 4; kk++) {
            const uint32_t koff = kk * 32;
            uint32_t af[4][4], bf[2][4];
#pragma unroll
            for (int mt = 0; mt < 4; mt++) {
                uint32_t r = base + (uint32_t)((wm + mt * 16) * RSTRIDE) + koff;
                ldsm4(af[mt], r + OFF_A + a_off);
            }
#pragma unroll
            for (int ng = 0; ng < 2; ng++) {
                uint32_t r = base + (uint32_t)((wn + ng * 16) * RSTRIDE) + koff;
                ldsm4(bf[ng], r + OFF_B + b_off);
            }
#pragma unroll
            for (int mt = 0; mt < 4; mt++)
#pragma unroll
                for (int nt = 0; nt < 4; nt++)
                    mma16816(acc[mt][nt], af[mt], &bf[nt >> 1][(nt & 1) * 2]);
        }
    }

    if (MODE == 0) {
#pragma unroll
        for (int mt = 0; mt < 4; mt++)
#pragma unroll
            for (int nt = 0; nt < 4; nt++) {
                int row = m0 + wm + mt * 16 + (lane >> 2);
                int col = n0 + wn + nt * 8 + (lane & 3) * 2;
                *(float2*)&C[(size_t)row * N + col] =
                    make_float2(acc[mt][nt][0], acc[mt][nt][1]);
                *(float2*)&C[(size_t)(row + 8) * N + col] =
                    make_float2(acc[mt][nt][2], acc[mt][nt][3]);
            }
    } else {
        const int sec = (n0 + wn) >> 10;          // 0=q 1=k 2=v
        const int hh  = ((n0 + wn) >> 6) & 15;
        __half* DST = (sec == 0) ? q16 : (sec == 1) ? k16 : v16;
#pragma unroll
        for (int mt = 0; mt < 4; mt++)
#pragma unroll
            for (int nt = 0; nt < 4; nt++) {
                int row = m0 + wm + mt * 16 + (lane >> 2);
                int d   = ((wn + nt * 8) & 63) + (lane & 3) * 2;
                int b   = row >> 11;
                int ll  = row & 2047;
                size_t idx = ((size_t)(b * HEADS + hh) * LSEQ + ll) * KD + d;
                *(uint32_t*)(DST + idx) =
                    pack2(h16(acc[mt][nt][0]), h16(acc[mt][nt][1]));
                *(uint32_t*)(DST + idx + (size_t)8 * KD) =
                    pack2(h16(acc[mt][nt][2]), h16(acc[mt][nt][3]));
            }
    }
}

// ---------------------------------------------------------------------------
// Flash attention, pure fp16 MMA, causal. 2-stage pipeline, 2 CTA/SM.
// ---------------------------------------------------------------------------
#define ASTRIDE 144
#define AQ_OFF  0
#define ASTG0   (128 * ASTRIDE)        // 18432 (Q tile)
#define ASTG_SZ (2 * 64 * ASTRIDE)     // 18432 per stage (K, V)
#define AK 0
#define AV (64 * ASTRIDE)
#define ATT_SMEM (ASTG0 + 2 * ASTG_SZ) // 55296

__global__ __launch_bounds__(256, 2) void attn_mma_kernel(
    const __half* __restrict__ q16,
    const __half* __restrict__ k16, const __half* __restrict__ v16,
    __half* __restrict__ att16) {
    extern __shared__ __align__(128) char smem[];
    const uint32_t sb = smem_u32(smem);
    const int tid  = threadIdx.x;
    const int lane = tid & 31;
    const int wid  = tid >> 5;
    const int qt   = blockIdx.x;
    const int bh   = blockIdx.y;
    const int q0   = qt * 128;
    const int nkv  = 2 * qt + 2;

    const size_t hb = (size_t)bh * LSEQ * KD;
    const char* Qp = (const char*)(q16 + hb + (size_t)q0 * KD);
    const char* Kp = (const char*)(k16 + hb);
    const char* Vp = (const char*)(v16 + hb);

    auto load_q = [&]() {
        for (int i = tid; i < 1024; i += 256) {
            int row = i >> 3, ch = (i & 7) * 16;
            uint32_t so = (uint32_t)(row * ASTRIDE + ch);
            cp16(sb + AQ_OFF + so, Qp + (size_t)row * 128 + ch);
        }
    };
    auto load_stage = [&](int kt) {
        const uint32_t base = sb + ASTG0 + (uint32_t)(kt & 1) * ASTG_SZ;
        for (int i = tid; i < 512; i += 256) {
            int row = i >> 3, ch = (i & 7) * 16;
            uint32_t so = (uint32_t)(row * ASTRIDE + ch);
            size_t go = (size_t)(kt * 64 + row) * 128 + ch;
            cp16(base + AK + so, Kp + go);
            cp16(base + AV + so, Vp + go);
        }
        CP_COMMIT();
    };

    load_q();
    load_stage(0);

    const uint32_t a_off = (uint32_t)((lane & 15) * ASTRIDE + (lane >> 4) * 16);
    const uint32_t b_off = (uint32_t)((((lane >> 4) & 1) * 8 + (lane & 7)) * ASTRIDE +
                                      ((lane >> 3) & 1) * 16);
    const uint32_t v_off = (uint32_t)((lane & 15) * ASTRIDE + (lane >> 4) * 16);

    uint32_t qf[4][4];
    float oacc[8][4];
#pragma unroll
    for (int i = 0; i < 8; i++)
#pragma unroll
        for (int j = 0; j < 4; j++) oacc[i][j] = 0.0f;
    float mr0 = -1e30f, mr1 = -1e30f, lr0 = 0.0f, lr1 = 0.0f;

    const int r0 = q0 + wid * 16 + (lane >> 2);
    const int r1 = r0 + 8;

    for (int kt = 0; kt < nkv; kt++) {
        CP_WAIT0();
        __syncthreads();
        if (kt + 1 < nkv) load_stage(kt + 1);

        if (kt == 0) {
#pragma unroll
            for (int kc = 0; kc < 4; kc++) {
                uint32_t r = sb + (uint32_t)(wid * 16 * ASTRIDE) + kc * 32 + a_off;
                ldsm4(qf[kc], r + AQ_OFF);
            }
        }

        const uint32_t stg = sb + ASTG0 + (uint32_t)(kt & 1) * ASTG_SZ;

        // ---- S = Q K^T ----
        float sacc[8][4];
#pragma unroll
        for (int i = 0; i < 8; i++)
#pragma unroll
            for (int j = 0; j < 4; j++) sacc[i][j] = 0.0f;

#pragma unroll
        for (int kc = 0; kc < 4; kc++) {
            uint32_t kf[4][4];
#pragma unroll
            for (int ng = 0; ng < 4; ng++) {
                uint32_t r = stg + (uint32_t)(ng * 16 * ASTRIDE) + kc * 32 + b_off;
                ldsm4(kf[ng], r + AK);
            }
#pragma unroll
            for (int nt = 0; nt < 8; nt++)
                mma16816(sacc[nt], qf[kc], &kf[nt >> 1][(nt & 1) * 2]);
        }

        // ---- mask + scale ----
        const bool need_mask = (kt * 64 + 63) > (q0 + wid * 16);
        if (need_mask) {
#pragma unroll
            for (int nt = 0; nt < 8; nt++) {
                int colb = kt * 64 + nt * 8 + (lane & 3) * 2;
                sacc[nt][0] = (colb     <= r0) ? sacc[nt][0] * 0.125f : -1e30f;
                sacc[nt][1] = (colb + 1 <= r0) ? sacc[nt][1] * 0.125f : -1e30f;
                sacc[nt][2] = (colb     <= r1) ? sacc[nt][2] * 0.125f : -1e30f;
                sacc[nt][3] = (colb + 1 <= r1) ? sacc[nt][3] * 0.125f : -1e30f;
            }
        } else {
#pragma unroll
            for (int nt = 0; nt < 8; nt++)
#pragma unroll
                for (int e = 0; e < 4; e++) sacc[nt][e] *= 0.125f;
        }

        // ---- online softmax ----
        float m0 = -1e30f, m1 = -1e30f;
#pragma unroll
        for (int nt = 0; nt < 8; nt++) {
            m0 = fmaxf(m0, fmaxf(sacc[nt][0], sacc[nt][1]));
            m1 = fmaxf(m1, fmaxf(sacc[nt][2], sacc[nt][3]));
        }
        m0 = fmaxf(m0, __shfl_xor_sync(0xffffffffu, m0, 1));
        m0 = fmaxf(m0, __shfl_xor_sync(0xffffffffu, m0, 2));
        m1 = fmaxf(m1, __shfl_xor_sync(0xffffffffu, m1, 1));
        m1 = fmaxf(m1, __shfl_xor_sync(0xffffffffu, m1, 2));

        float mn0 = fmaxf(mr0, m0), mn1 = fmaxf(mr1, m1);
        float al0 = __expf(mr0 - mn0), al1 = __expf(mr1 - mn1);
        mr0 = mn0; mr1 = mn1;

        uint32_t pA[8], pB[8];
        float s0 = 0.0f, s1 = 0.0f;
#pragma unroll
        for (int nt = 0; nt < 8; nt++) {
            float p0 = __expf(sacc[nt][0] - mn0);
            float p1 = __expf(sacc[nt][1] - mn0);
            float p2 = __expf(sacc[nt][2] - mn1);
            float p3 = __expf(sacc[nt][3] - mn1);
            s0 += p0 + p1;
            s1 += p2 + p3;
            pA[nt] = pack2(h16(p0), h16(p1));
            pB[nt] = pack2(h16(p2), h16(p3));
        }
        s0 += __shfl_xor_sync(0xffffffffu, s0, 1);
        s0 += __shfl_xor_sync(0xffffffffu, s0, 2);
        s1 += __shfl_xor_sync(0xffffffffu, s1, 1);
        s1 += __shfl_xor_sync(0xffffffffu, s1, 2);
        lr0 = lr0 * al0 + s0;
        lr1 = lr1 * al1 + s1;

#pragma unroll
        for (int dt = 0; dt < 8; dt++) {
            oacc[dt][0] *= al0; oacc[dt][1] *= al0;
            oacc[dt][2] *= al1; oacc[dt][3] *= al1;
        }

        // ---- O += P V ----
#pragma unroll
        for (int kc = 0; kc < 4; kc++) {
            uint32_t pf[4] = {pA[2 * kc], pB[2 * kc], pA[2 * kc + 1], pB[2 * kc + 1]};
            uint32_t vf[4][4];
#pragma unroll
            for (int dg = 0; dg < 4; dg++) {
                uint32_t r = stg + (uint32_t)(kc * 16 * ASTRIDE) + dg * 32 + v_off;
                ldsm4t(vf[dg], r + AV);
            }
#pragma unroll
            for (int dg = 0; dg < 4; dg++) {
                mma16816(oacc[dg * 2],     pf, &vf[dg][0]);
                mma16816(oacc[dg * 2 + 1], pf, &vf[dg][2]);
            }
        }
    }

    // ---- epilogue ----
    const float inv0 = 1.0f / lr0, inv1 = 1.0f / lr1;
    const int b = bh >> 4, hh = bh & 15;
    size_t base0 = ((size_t)(b * LSEQ + r0)) * DMODEL + hh * KD + (lane & 3) * 2;
    size_t base1 = base0 + (size_t)8 * DMODEL;
#pragma unroll
    for (int dt = 0; dt < 8; dt++) {
        *(uint32_t*)(att16 + base0 + dt * 8) =
            pack2(h16(oacc[dt][0] * inv0), h16(oacc[dt][1] * inv0));
        *(uint32_t*)(att16 + base1 + dt * 8) =
            pack2(h16(oacc[dt][2] * inv1), h16(oacc[dt][3] * inv1));
    }
}

// ---------------------------------------------------------------------------
extern "C" void kernel_launch(void* const* d_in, const int* in_sizes, int n_in,
                              void* d_out, int out_size) {
    const float* x    = (const float*)d_in[0];
    const float* Wqkv = (const float*)d_in[1];
    const float* Wout = (const float*)d_in[2];
    float* out = (float*)d_out;

    __half *x16, *wq16, *wo16, *q16, *k16, *v16, *att16;
    cudaGetSymbolAddress((void**)&x16, g_x16);
    cudaGetSymbolAddress((void**)&wq16, g_wqkvT);
    cudaGetSymbolAddress((void**)&wo16, g_woutT);
    cudaGetSymbolAddress((void**)&q16, g_q16);
    cudaGetSymbolAddress((void**)&k16, g_k16);
    cudaGetSymbolAddress((void**)&v16, g_v16);
    cudaGetSymbolAddress((void**)&att16, g_att16);

    cudaFuncSetAttribute((const void*)gemm_mma_kernel<0>,
                         cudaFuncAttributeMaxDynamicSharedMemorySize, GEMM_SMEM);
    cudaFuncSetAttribute((const void*)gemm_mma_kernel<1>,
                         cudaFuncAttributeMaxDynamicSharedMemorySize, GEMM_SMEM);
    cudaFuncSetAttribute((const void*)attn_mma_kernel,
                         cudaFuncAttributeMaxDynamicSharedMemorySize, ATT_SMEM);

    // prep
    {
        int n4 = TOKENS * DMODEL / 4;
        convert_f16_kernel<<<(n4 + 255) / 256, 256>>>(x, x16, n4);
        transpose_f16_kernel<<<dim3(3 * DMODEL / 32, DMODEL / 32), dim3(32, 8)>>>(
            Wqkv, wq16, DMODEL, 3 * DMODEL);
        transpose_f16_kernel<<<dim3(DMODEL / 32, DMODEL / 32), dim3(32, 8)>>>(
            Wout, wo16, DMODEL, DMODEL);
    }

    // 1) qkv GEMM -> fp16 head-major q/k/v
    gemm_mma_kernel<1><<<dim3(3 * DMODEL / BN, TOKENS / BM), 256, GEMM_SMEM>>>(
        x16, wq16, nullptr, q16, k16, v16, TOKENS, 3 * DMODEL, DMODEL);

    // 2) tensor-core causal flash attention -> att fp16
    attn_mma_kernel<<<dim3(LSEQ / 128, BH_CNT), 256, ATT_SMEM>>>(
        q16, k16, v16, att16);

    // 3) out = att @ Wout
    gemm_mma_kernel<0><<<dim3(DMODEL / BN, TOKENS / BM), 256, GEMM_SMEM>>>(
        att16, wo16, out, nullptr, nullptr, nullptr, TOKENS, DMODEL, DMODEL);
}

// round 10
// speedup vs baseline: 6.8496x; 1.0296x over previous
#include <cuda_runtime.h>
#include <cuda_fp16.h>
#include <cstdint>

// ----------------------------------------------------------------------------
// SelfAttention: out = Attn(x @ Wqkv) @ Wout, causal, H=16, Kd=64
// B=4, L=2048, D=1024 -> tokens = 8192
// R10: R9 + attention overhead cuts: scale folded into Q, 128-row kv stages
//      (2 sub-tiles per barrier), reversed qtile scheduling (heavy first).
// ----------------------------------------------------------------------------

#define TOKENS 8192
#define LSEQ   2048
#define DMODEL 1024
#define HEADS  16
#define KD     64
#define BH_CNT (4 * HEADS)   // 64

// ---------------- scratch ----------------------------------------------------
__device__ __half g_x16[(size_t)TOKENS * DMODEL];
__device__ __half g_wqkvT[(size_t)3 * DMODEL * DMODEL];
__device__ __half g_woutT[(size_t)DMODEL * DMODEL];
__device__ __half g_q16[(size_t)BH_CNT * LSEQ * KD];
__device__ __half g_k16[(size_t)BH_CNT * LSEQ * KD];
__device__ __half g_v16[(size_t)BH_CNT * LSEQ * KD];
__device__ __half g_att16[(size_t)TOKENS * DMODEL];

// ---------------- helpers ----------------------------------------------------
__device__ __forceinline__ uint32_t smem_u32(const void* p) {
    uint32_t a;
    asm("{ .reg .u64 t; cvta.to.shared.u64 t, %1; cvt.u32.u64 %0, t; }" : "=r"(a) : "l"(p));
    return a;
}
__device__ __forceinline__ void cp16(uint32_t s, const void* g) {
    asm volatile("cp.async.cg.shared.global [%0], [%1], 16;" :: "r"(s), "l"(g));
}
#define CP_COMMIT() asm volatile("cp.async.commit_group;" ::: "memory")
#define CP_WAIT0()  asm volatile("cp.async.wait_group 0;" ::: "memory")
#define CP_WAIT1()  asm volatile("cp.async.wait_group 1;" ::: "memory")

__device__ __forceinline__ void ldsm4(uint32_t* r, uint32_t addr) {
    asm volatile("ldmatrix.sync.aligned.m8n8.x4.shared.b16 {%0,%1,%2,%3}, [%4];"
                 : "=r"(r[0]), "=r"(r[1]), "=r"(r[2]), "=r"(r[3]) : "r"(addr));
}
__device__ __forceinline__ void ldsm4t(uint32_t* r, uint32_t addr) {
    asm volatile("ldmatrix.sync.aligned.m8n8.x4.trans.shared.b16 {%0,%1,%2,%3}, [%4];"
                 : "=r"(r[0]), "=r"(r[1]), "=r"(r[2]), "=r"(r[3]) : "r"(addr));
}
__device__ __forceinline__ void mma16816(float* c, const uint32_t* a, const uint32_t* b) {
    asm volatile("mma.sync.aligned.m16n8k16.row.col.f32.f16.f16.f32 "
                 "{%0,%1,%2,%3}, {%4,%5,%6,%7}, {%8,%9}, {%0,%1,%2,%3};"
                 : "+f"(c[0]), "+f"(c[1]), "+f"(c[2]), "+f"(c[3])
                 : "r"(a[0]), "r"(a[1]), "r"(a[2]), "r"(a[3]), "r"(b[0]), "r"(b[1]));
}
__device__ __forceinline__ unsigned short h16(float v) {
    return __half_as_ushort(__float2half_rn(v));
}
__device__ __forceinline__ uint32_t pack2(unsigned short a, unsigned short b) {
    return (uint32_t)a | ((uint32_t)b << 16);
}

// ---------------------------------------------------------------------------
// Prep kernels
// ---------------------------------------------------------------------------
__global__ void convert_f16_kernel(const float* __restrict__ in,
                                   __half* __restrict__ o16, int n4) {
    int i = blockIdx.x * blockDim.x + threadIdx.x;
    if (i >= n4) return;
    float4 v = ((const float4*)in)[i];
    ((ushort4*)o16)[i] = make_ushort4(h16(v.x), h16(v.y), h16(v.z), h16(v.w));
}

__global__ void transpose_f16_kernel(const float* __restrict__ W,
                                     __half* __restrict__ T16,
                                     int K, int N) {
    __shared__ float t[32][33];
    int n0 = blockIdx.x * 32, k0 = blockIdx.y * 32;
    int tx = threadIdx.x, ty = threadIdx.y;
#pragma unroll
    for (int j = 0; j < 4; j++) {
        int k = ty + j * 8;
        t[k][tx] = W[(size_t)(k0 + k) * N + n0 + tx];
    }
    __syncthreads();
#pragma unroll
    for (int j = 0; j < 4; j++) {
        int nl = ty + j * 8;
        T16[(size_t)(n0 + nl) * K + k0 + tx] = __ushort_as_half(h16(t[tx][nl]));
    }
}

// ---------------------------------------------------------------------------
// HMMA GEMM, pure fp16: C = A * B^T. 128x128 tile, BK=64, 8 warps,
// 3-stage cp.async pipeline, 2 CTA/SM. 64 MMAs per barrier.
// MODE 0: C fp32.  MODE 1: head-major fp16 q/k/v epilogue (q scaled by 1/8).
// ---------------------------------------------------------------------------
#define BM 128
#define BN 128
#define BK 64
#define RSTRIDE 144                    // 128B data + 16B pad
#define TILE_B  (128 * RSTRIDE)        // 18432
#define OFF_A   0
#define OFF_B   (1 * TILE_B)
#define STAGE_B (2 * TILE_B)           // 36864
#define GEMM_SMEM (3 * STAGE_B)        // 110592

template <int MODE>
__global__ __launch_bounds__(256, 2) void gemm_mma_kernel(
    const __half* __restrict__ A, const __half* __restrict__ B,
    float* __restrict__ C,
    __half* __restrict__ q16, __half* __restrict__ k16, __half* __restrict__ v16,
    int M, int N, int K) {
    extern __shared__ __align__(128) char smem[];
    const uint32_t sb = smem_u32(smem);
    const int tid  = threadIdx.x;
    const int lane = tid & 31;
    const int wid  = tid >> 5;
    const int m0 = blockIdx.y * BM;
    const int n0 = blockIdx.x * BN;
    const int wm = (wid & 1) * 64;
    const int wn = (wid >> 1) * 32;
    const int NS = K / BK;             // 16

    const uint32_t a_off = (uint32_t)((lane & 15) * RSTRIDE + (lane >> 4) * 16);
    const uint32_t b_off = (uint32_t)((((lane >> 4) & 1) * 8 + (lane & 7)) * RSTRIDE +
                                      ((lane >> 3) & 1) * 16);

    float acc[4][4][4];
#pragma unroll
    for (int i = 0; i < 4; i++)
#pragma unroll
        for (int j = 0; j < 4; j++)
#pragma unroll
            for (int q = 0; q < 4; q++) acc[i][j][q] = 0.0f;

    auto load_stage = [&](int s) {
        const uint32_t base = sb + (uint32_t)(s % 3) * STAGE_B;
        const int k0 = s * BK;
        for (int i = tid; i < 1024; i += 256) {
            int row = i >> 3;
            int ch  = (i & 7) * 16;
            uint32_t so = (uint32_t)(row * RSTRIDE + ch);
            cp16(base + OFF_A + so, A + (size_t)(m0 + row) * K + k0 + (ch >> 1));
        }
        for (int i = tid; i < 1024; i += 256) {
            int row = i >> 3;
            int ch  = (i & 7) * 16;
            uint32_t so = (uint32_t)(row * RSTRIDE + ch);
            cp16(base + OFF_B + so, B + (size_t)(n0 + row) * K + k0 + (ch >> 1));
        }
        CP_COMMIT();
    };

    load_stage(0);
    load_stage(1);

    for (int s = 0; s < NS; s++) {
        if (s + 1 < NS) { CP_WAIT1(); }
        else            { CP_WAIT0(); }
        __syncthreads();
        if (s + 2 < NS) load_stage(s + 2);

        const uint32_t base = sb + (uint32_t)(s % 3) * STAGE_B;
#pragma unroll
        for (int kk = 0; kk < 4; kk++) {
            const uint32_t koff = kk * 32;
            uint32_t af[4][4], bf[2][4];
#pragma unroll
            for (int mt = 0; mt < 4; mt++) {
                uint32_t r = base + (uint32_t)((wm + mt * 16) * RSTRIDE) + koff;
                ldsm4(af[mt], r + OFF_A + a_off);
            }
#pragma unroll
            for (int ng = 0; ng < 2; ng++) {
                uint32_t r = base + (uint32_t)((wn + ng * 16) * RSTRIDE) + koff;
                ldsm4(bf[ng], r + OFF_B + b_off);
            }
#pragma unroll
            for (int mt = 0; mt < 4; mt++)
#pragma unroll
                for (int nt = 0; nt < 4; nt++)
                    mma16816(acc[mt][nt], af[mt], &bf[nt >> 1][(nt & 1) * 2]);
        }
    }

    if (MODE == 0) {
#pragma unroll
        for (int mt = 0; mt < 4; mt++)
#pragma unroll
            for (int nt = 0; nt < 4; nt++) {
                int row = m0 + wm + mt * 16 + (lane >> 2);
                int col = n0 + wn + nt * 8 + (lane & 3) * 2;
                *(float2*)&C[(size_t)row * N + col] =
                    make_float2(acc[mt][nt][0], acc[mt][nt][1]);
                *(float2*)&C[(size_t)(row + 8) * N + col] =
                    make_float2(acc[mt][nt][2], acc[mt][nt][3]);
            }
    } else {
        const int sec = (n0 + wn) >> 10;          // 0=q 1=k 2=v
        const int hh  = ((n0 + wn) >> 6) & 15;
        __half* DST = (sec == 0) ? q16 : (sec == 1) ? k16 : v16;
        const float scl = (sec == 0) ? 0.125f : 1.0f;   // fold 1/sqrt(64) into Q
#pragma unroll
        for (int mt = 0; mt < 4; mt++)
#pragma unroll
            for (int nt = 0; nt < 4; nt++) {
                int row = m0 + wm + mt * 16 + (lane >> 2);
                int d   = ((wn + nt * 8) & 63) + (lane & 3) * 2;
                int b   = row >> 11;
                int ll  = row & 2047;
                size_t idx = ((size_t)(b * HEADS + hh) * LSEQ + ll) * KD + d;
                *(uint32_t*)(DST + idx) =
                    pack2(h16(acc[mt][nt][0] * scl), h16(acc[mt][nt][1] * scl));
                *(uint32_t*)(DST + idx + (size_t)8 * KD) =
                    pack2(h16(acc[mt][nt][2] * scl), h16(acc[mt][nt][3] * scl));
            }
    }
}

// ---------------------------------------------------------------------------
// Flash attention, pure fp16 MMA, causal. 128-row kv stages (2 sub-tiles per
// barrier), 2 CTA/SM, heavy q-tiles scheduled first. Scale pre-folded into Q.
// ---------------------------------------------------------------------------
#define ASTRIDE 144
#define AQ_OFF  0
#define ASTG0   (128 * ASTRIDE)        // 18432 (Q tile)
#define ASTG_SZ (2 * 128 * ASTRIDE)    // 36864 per stage (K 128 rows, V 128 rows)
#define AK 0
#define AV (128 * ASTRIDE)
#define ATT_SMEM (ASTG0 + 2 * ASTG_SZ) // 92160

__global__ __launch_bounds__(256, 2) void attn_mma_kernel(
    const __half* __restrict__ q16,
    const __half* __restrict__ k16, const __half* __restrict__ v16,
    __half* __restrict__ att16) {
    extern __shared__ __align__(128) char smem[];
    const uint32_t sb = smem_u32(smem);
    const int tid  = threadIdx.x;
    const int lane = tid & 31;
    const int wid  = tid >> 5;
    const int qt   = gridDim.x - 1 - blockIdx.x;   // heavy tiles first
    const int bh   = blockIdx.y;
    const int q0   = qt * 128;
    const int nst  = qt + 1;                        // 128-row kv stages

    const size_t hb = (size_t)bh * LSEQ * KD;
    const char* Qp = (const char*)(q16 + hb + (size_t)q0 * KD);
    const char* Kp = (const char*)(k16 + hb);
    const char* Vp = (const char*)(v16 + hb);

    auto load_q = [&]() {
        for (int i = tid; i < 1024; i += 256) {
            int row = i >> 3, ch = (i & 7) * 16;
            uint32_t so = (uint32_t)(row * ASTRIDE + ch);
            cp16(sb + AQ_OFF + so, Qp + (size_t)row * 128 + ch);
        }
    };
    auto load_stage = [&](int st) {
        const uint32_t base = sb + ASTG0 + (uint32_t)(st & 1) * ASTG_SZ;
        for (int i = tid; i < 1024; i += 256) {
            int row = i >> 3, ch = (i & 7) * 16;
            uint32_t so = (uint32_t)(row * ASTRIDE + ch);
            size_t go = (size_t)(st * 128 + row) * 128 + ch;
            cp16(base + AK + so, Kp + go);
            cp16(base + AV + so, Vp + go);
        }
        CP_COMMIT();
    };

    load_q();
    load_stage(0);

    const uint32_t a_off = (uint32_t)((lane & 15) * ASTRIDE + (lane >> 4) * 16);
    const uint32_t b_off = (uint32_t)((((lane >> 4) & 1) * 8 + (lane & 7)) * ASTRIDE +
                                      ((lane >> 3) & 1) * 16);
    const uint32_t v_off = (uint32_t)((lane & 15) * ASTRIDE + (lane >> 4) * 16);

    uint32_t qf[4][4];
    float oacc[8][4];
#pragma unroll
    for (int i = 0; i < 8; i++)
#pragma unroll
        for (int j = 0; j < 4; j++) oacc[i][j] = 0.0f;
    float mr0 = -1e30f, mr1 = -1e30f, lr0 = 0.0f, lr1 = 0.0f;

    const int r0 = q0 + wid * 16 + (lane >> 2);
    const int r1 = r0 + 8;

    for (int st = 0; st < nst; st++) {
        CP_WAIT0();
        __syncthreads();
        if (st + 1 < nst) load_stage(st + 1);

        if (st == 0) {
#pragma unroll
            for (int kc = 0; kc < 4; kc++) {
                uint32_t r = sb + (uint32_t)(wid * 16 * ASTRIDE) + kc * 32 + a_off;
                ldsm4(qf[kc], r + AQ_OFF);
            }
        }

        const uint32_t stg = sb + ASTG0 + (uint32_t)(st & 1) * ASTG_SZ;

#pragma unroll
        for (int sub = 0; sub < 2; sub++) {
            const int kt = st * 2 + sub;
            const uint32_t ksub = stg + AK + (uint32_t)(sub * 64 * ASTRIDE);
            const uint32_t vsub = stg + AV + (uint32_t)(sub * 64 * ASTRIDE);

            // ---- S = Q K^T (Q pre-scaled by 1/8) ----
            float sacc[8][4];
#pragma unroll
            for (int i = 0; i < 8; i++)
#pragma unroll
                for (int j = 0; j < 4; j++) sacc[i][j] = 0.0f;

#pragma unroll
            for (int kc = 0; kc < 4; kc++) {
                uint32_t kf[4][4];
#pragma unroll
                for (int ng = 0; ng < 4; ng++) {
                    uint32_t r = ksub + (uint32_t)(ng * 16 * ASTRIDE) + kc * 32 + b_off;
                    ldsm4(kf[ng], r);
                }
#pragma unroll
                for (int nt = 0; nt < 8; nt++)
                    mma16816(sacc[nt], qf[kc], &kf[nt >> 1][(nt & 1) * 2]);
            }

            // ---- causal mask (diagonal tiles only) ----
            if (kt * 64 + 63 > q0 + wid * 16) {
#pragma unroll
                for (int nt = 0; nt < 8; nt++) {
                    int colb = kt * 64 + nt * 8 + (lane & 3) * 2;
                    if (colb     > r0) sacc[nt][0] = -1e30f;
                    if (colb + 1 > r0) sacc[nt][1] = -1e30f;
                    if (colb     > r1) sacc[nt][2] = -1e30f;
                    if (colb + 1 > r1) sacc[nt][3] = -1e30f;
                }
            }

            // ---- online softmax ----
            float m0 = -1e30f, m1 = -1e30f;
#pragma unroll
            for (int nt = 0; nt < 8; nt++) {
                m0 = fmaxf(m0, fmaxf(sacc[nt][0], sacc[nt][1]));
                m1 = fmaxf(m1, fmaxf(sacc[nt][2], sacc[nt][3]));
            }
            m0 = fmaxf(m0, __shfl_xor_sync(0xffffffffu, m0, 1));
            m0 = fmaxf(m0, __shfl_xor_sync(0xffffffffu, m0, 2));
            m1 = fmaxf(m1, __shfl_xor_sync(0xffffffffu, m1, 1));
            m1 = fmaxf(m1, __shfl_xor_sync(0xffffffffu, m1, 2));

            float mn0 = fmaxf(mr0, m0), mn1 = fmaxf(mr1, m1);
            float al0 = __expf(mr0 - mn0), al1 = __expf(mr1 - mn1);
            mr0 = mn0; mr1 = mn1;

            uint32_t pA[8], pB[8];
            float s0 = 0.0f, s1 = 0.0f;
#pragma unroll
            for (int nt = 0; nt < 8; nt++) {
                float p0 = __expf(sacc[nt][0] - mn0);
                float p1 = __expf(sacc[nt][1] - mn0);
                float p2 = __expf(sacc[nt][2] - mn1);
                float p3 = __expf(sacc[nt][3] - mn1);
                s0 += p0 + p1;
                s1 += p2 + p3;
                pA[nt] = pack2(h16(p0), h16(p1));
                pB[nt] = pack2(h16(p2), h16(p3));
            }
            s0 += __shfl_xor_sync(0xffffffffu, s0, 1);
            s0 += __shfl_xor_sync(0xffffffffu, s0, 2);
            s1 += __shfl_xor_sync(0xffffffffu, s1, 1);
            s1 += __shfl_xor_sync(0xffffffffu, s1, 2);
            lr0 = lr0 * al0 + s0;
            lr1 = lr1 * al1 + s1;

#pragma unroll
            for (int dt = 0; dt < 8; dt++) {
                oacc[dt][0] *= al0; oacc[dt][1] *= al0;
                oacc[dt][2] *= al1; oacc[dt][3] *= al1;
            }

            // ---- O += P V ----
#pragma unroll
            for (int kc = 0; kc < 4; kc++) {
                uint32_t pf[4] = {pA[2 * kc], pB[2 * kc], pA[2 * kc + 1], pB[2 * kc + 1]};
                uint32_t vf[4][4];
#pragma unroll
                for (int dg = 0; dg < 4; dg++) {
                    uint32_t r = vsub + (uint32_t)(kc * 16 * ASTRIDE) + dg * 32 + v_off;
                    ldsm4t(vf[dg], r);
                }
#pragma unroll
                for (int dg = 0; dg < 4; dg++) {
                    mma16816(oacc[dg * 2],     pf, &vf[dg][0]);
                    mma16816(oacc[dg * 2 + 1], pf, &vf[dg][2]);
                }
            }
        }
    }

    // ---- epilogue ----
    const float inv0 = 1.0f / lr0, inv1 = 1.0f / lr1;
    const int b = bh >> 4, hh = bh & 15;
    size_t base0 = ((size_t)(b * LSEQ + r0)) * DMODEL + hh * KD + (lane & 3) * 2;
    size_t base1 = base0 + (size_t)8 * DMODEL;
#pragma unroll
    for (int dt = 0; dt < 8; dt++) {
        *(uint32_t*)(att16 + base0 + dt * 8) =
            pack2(h16(oacc[dt][0] * inv0), h16(oacc[dt][1] * inv0));
        *(uint32_t*)(att16 + base1 + dt * 8) =
            pack2(h16(oacc[dt][2] * inv1), h16(oacc[dt][3] * inv1));
    }
}

// ---------------------------------------------------------------------------
extern "C" void kernel_launch(void* const* d_in, const int* in_sizes, int n_in,
                              void* d_out, int out_size) {
    const float* x    = (const float*)d_in[0];
    const float* Wqkv = (const float*)d_in[1];
    const float* Wout = (const float*)d_in[2];
    float* out = (float*)d_out;

    __half *x16, *wq16, *wo16, *q16, *k16, *v16, *att16;
    cudaGetSymbolAddress((void**)&x16, g_x16);
    cudaGetSymbolAddress((void**)&wq16, g_wqkvT);
    cudaGetSymbolAddress((void**)&wo16, g_woutT);
    cudaGetSymbolAddress((void**)&q16, g_q16);
    cudaGetSymbolAddress((void**)&k16, g_k16);
    cudaGetSymbolAddress((void**)&v16, g_v16);
    cudaGetSymbolAddress((void**)&att16, g_att16);

    cudaFuncSetAttribute((const void*)gemm_mma_kernel<0>,
                         cudaFuncAttributeMaxDynamicSharedMemorySize, GEMM_SMEM);
    cudaFuncSetAttribute((const void*)gemm_mma_kernel<1>,
                         cudaFuncAttributeMaxDynamicSharedMemorySize, GEMM_SMEM);
    cudaFuncSetAttribute((const void*)attn_mma_kernel,
                         cudaFuncAttributeMaxDynamicSharedMemorySize, ATT_SMEM);

    // prep
    {
        int n4 = TOKENS * DMODEL / 4;
        convert_f16_kernel<<<(n4 + 255) / 256, 256>>>(x, x16, n4);
        transpose_f16_kernel<<<dim3(3 * DMODEL / 32, DMODEL / 32), dim3(32, 8)>>>(
            Wqkv, wq16, DMODEL, 3 * DMODEL);
        transpose_f16_kernel<<<dim3(DMODEL / 32, DMODEL / 32), dim3(32, 8)>>>(
            Wout, wo16, DMODEL, DMODEL);
    }

    // 1) qkv GEMM -> fp16 head-major q/k/v (q pre-scaled by 1/8)
    gemm_mma_kernel<1><<<dim3(3 * DMODEL / BN, TOKENS / BM), 256, GEMM_SMEM>>>(
        x16, wq16, nullptr, q16, k16, v16, TOKENS, 3 * DMODEL, DMODEL);

    // 2) tensor-core causal flash attention -> att fp16
    attn_mma_kernel<<<dim3(LSEQ / 128, BH_CNT), 256, ATT_SMEM>>>(
        q16, k16, v16, att16);

    // 3) out = att @ Wout
    gemm_mma_kernel<0><<<dim3(DMODEL / BN, TOKENS / BM), 256, GEMM_SMEM>>>(
        att16, wo16, out, nullptr, nullptr, nullptr, TOKENS, DMODEL, DMODEL);
}

// round 11
// speedup vs baseline: 6.9318x; 1.0120x over previous
#include <cuda_runtime.h>
#include <cuda_fp16.h>
#include <cstdint>

// ----------------------------------------------------------------------------
// SelfAttention: out = Attn(x @ Wqkv) @ Wout, causal, H=16, Kd=64
// B=4, L=2048, D=1024 -> tokens = 8192
// R11: persistent-tile GEMMs (no wave-quantization tail) + exp2 softmax with
//      log2(e) folded into Q. Pure fp16 HMMA, fp32 accum.
// ----------------------------------------------------------------------------

#define TOKENS 8192
#define LSEQ   2048
#define DMODEL 1024
#define HEADS  16
#define KD     64
#define BH_CNT (4 * HEADS)   // 64
#define PERSIST_CTAS 304     // 2 per SM (152 SMs on GB300)

// ---------------- scratch ----------------------------------------------------
__device__ __half g_x16[(size_t)TOKENS * DMODEL];
__device__ __half g_wqkvT[(size_t)3 * DMODEL * DMODEL];
__device__ __half g_woutT[(size_t)DMODEL * DMODEL];
__device__ __half g_q16[(size_t)BH_CNT * LSEQ * KD];
__device__ __half g_k16[(size_t)BH_CNT * LSEQ * KD];
__device__ __half g_v16[(size_t)BH_CNT * LSEQ * KD];
__device__ __half g_att16[(size_t)TOKENS * DMODEL];

// ---------------- helpers ----------------------------------------------------
__device__ __forceinline__ uint32_t smem_u32(const void* p) {
    uint32_t a;
    asm("{ .reg .u64 t; cvta.to.shared.u64 t, %1; cvt.u32.u64 %0, t; }" : "=r"(a) : "l"(p));
    return a;
}
__device__ __forceinline__ void cp16(uint32_t s, const void* g) {
    asm volatile("cp.async.cg.shared.global [%0], [%1], 16;" :: "r"(s), "l"(g));
}
#define CP_COMMIT() asm volatile("cp.async.commit_group;" ::: "memory")
#define CP_WAIT0()  asm volatile("cp.async.wait_group 0;" ::: "memory")
#define CP_WAIT1()  asm volatile("cp.async.wait_group 1;" ::: "memory")

__device__ __forceinline__ void ldsm4(uint32_t* r, uint32_t addr) {
    asm volatile("ldmatrix.sync.aligned.m8n8.x4.shared.b16 {%0,%1,%2,%3}, [%4];"
                 : "=r"(r[0]), "=r"(r[1]), "=r"(r[2]), "=r"(r[3]) : "r"(addr));
}
__device__ __forceinline__ void ldsm4t(uint32_t* r, uint32_t addr) {
    asm volatile("ldmatrix.sync.aligned.m8n8.x4.trans.shared.b16 {%0,%1,%2,%3}, [%4];"
                 : "=r"(r[0]), "=r"(r[1]), "=r"(r[2]), "=r"(r[3]) : "r"(addr));
}
__device__ __forceinline__ void mma16816(float* c, const uint32_t* a, const uint32_t* b) {
    asm volatile("mma.sync.aligned.m16n8k16.row.col.f32.f16.f16.f32 "
                 "{%0,%1,%2,%3}, {%4,%5,%6,%7}, {%8,%9}, {%0,%1,%2,%3};"
                 : "+f"(c[0]), "+f"(c[1]), "+f"(c[2]), "+f"(c[3])
                 : "r"(a[0]), "r"(a[1]), "r"(a[2]), "r"(a[3]), "r"(b[0]), "r"(b[1]));
}
__device__ __forceinline__ float ex2(float x) {
    float y;
    asm("ex2.approx.f32 %0, %1;" : "=f"(y) : "f"(x));
    return y;
}
__device__ __forceinline__ unsigned short h16(float v) {
    return __half_as_ushort(__float2half_rn(v));
}
__device__ __forceinline__ uint32_t pack2(unsigned short a, unsigned short b) {
    return (uint32_t)a | ((uint32_t)b << 16);
}

// ---------------------------------------------------------------------------
// Prep kernels
// ---------------------------------------------------------------------------
__global__ void convert_f16_kernel(const float* __restrict__ in,
                                   __half* __restrict__ o16, int n4) {
    int i = blockIdx.x * blockDim.x + threadIdx.x;
    if (i >= n4) return;
    float4 v = ((const float4*)in)[i];
    ((ushort4*)o16)[i] = make_ushort4(h16(v.x), h16(v.y), h16(v.z), h16(v.w));
}

__global__ void transpose_f16_kernel(const float* __restrict__ W,
                                     __half* __restrict__ T16,
                                     int K, int N) {
    __shared__ float t[32][33];
    int n0 = blockIdx.x * 32, k0 = blockIdx.y * 32;
    int tx = threadIdx.x, ty = threadIdx.y;
#pragma unroll
    for (int j = 0; j < 4; j++) {
        int k = ty + j * 8;
        t[k][tx] = W[(size_t)(k0 + k) * N + n0 + tx];
    }
    __syncthreads();
#pragma unroll
    for (int j = 0; j < 4; j++) {
        int nl = ty + j * 8;
        T16[(size_t)(n0 + nl) * K + k0 + tx] = __ushort_as_half(h16(t[tx][nl]));
    }
}

// ---------------------------------------------------------------------------
// Persistent HMMA GEMM, pure fp16: C = A * B^T. 128x128 tile, BK=64, 8 warps,
// 3-stage cp.async pipeline, 2 CTA/SM, CTA loops over tiles (grid=304).
// MODE 0: C fp32.  MODE 1: head-major fp16 q/k/v epilogue (q scaled).
// ---------------------------------------------------------------------------
#define BM 128
#define BN 128
#define BK 64
#define RSTRIDE 144                    // 128B data + 16B pad
#define TILE_B  (128 * RSTRIDE)        // 18432
#define OFF_A   0
#define OFF_B   (1 * TILE_B)
#define STAGE_B (2 * TILE_B)           // 36864
#define GEMM_SMEM (3 * STAGE_B)        // 110592
// Q scale: 1/sqrt(64) * log2(e)  (softmax runs in exp2 domain)
#define QSCALE (0.125f * 1.4426950408889634f)

template <int MODE>
__global__ __launch_bounds__(256, 2) void gemm_mma_kernel(
    const __half* __restrict__ A, const __half* __restrict__ B,
    float* __restrict__ C,
    __half* __restrict__ q16, __half* __restrict__ k16, __half* __restrict__ v16,
    int M, int N, int K) {
    extern __shared__ __align__(128) char smem[];
    const uint32_t sb = smem_u32(smem);
    const int tid  = threadIdx.x;
    const int lane = tid & 31;
    const int wid  = tid >> 5;
    const int wm = (wid & 1) * 64;
    const int wn = (wid >> 1) * 32;
    const int NS = K / BK;             // 16
    const int nmt = M / BM;
    const int ntiles = nmt * (N / BN);

    const uint32_t a_off = (uint32_t)((lane & 15) * RSTRIDE + (lane >> 4) * 16);
    const uint32_t b_off = (uint32_t)((((lane >> 4) & 1) * 8 + (lane & 7)) * RSTRIDE +
                                      ((lane >> 3) & 1) * 16);

    for (int t = blockIdx.x; t < ntiles; t += gridDim.x) {
        const int m0 = (t % nmt) * BM;
        const int n0 = (t / nmt) * BN;

        float acc[4][4][4];
#pragma unroll
        for (int i = 0; i < 4; i++)
#pragma unroll
            for (int j = 0; j < 4; j++)
#pragma unroll
                for (int q = 0; q < 4; q++) acc[i][j][q] = 0.0f;

        auto load_stage = [&](int s) {
            const uint32_t base = sb + (uint32_t)(s % 3) * STAGE_B;
            const int k0 = s * BK;
            for (int i = tid; i < 1024; i += 256) {
                int row = i >> 3;
                int ch  = (i & 7) * 16;
                uint32_t so = (uint32_t)(row * RSTRIDE + ch);
                cp16(base + OFF_A + so, A + (size_t)(m0 + row) * K + k0 + (ch >> 1));
            }
            for (int i = tid; i < 1024; i += 256) {
                int row = i >> 3;
                int ch  = (i & 7) * 16;
                uint32_t so = (uint32_t)(row * RSTRIDE + ch);
                cp16(base + OFF_B + so, B + (size_t)(n0 + row) * K + k0 + (ch >> 1));
            }
            CP_COMMIT();
        };

        load_stage(0);
        load_stage(1);

        for (int s = 0; s < NS; s++) {
            if (s + 1 < NS) { CP_WAIT1(); }
            else            { CP_WAIT0(); }
            __syncthreads();
            if (s + 2 < NS) load_stage(s + 2);

            const uint32_t base = sb + (uint32_t)(s % 3) * STAGE_B;
#pragma unroll
            for (int kk = 0; kk < 4; kk++) {
                const uint32_t koff = kk * 32;
                uint32_t af[4][4], bf[2][4];
#pragma unroll
                for (int mt = 0; mt < 4; mt++) {
                    uint32_t r = base + (uint32_t)((wm + mt * 16) * RSTRIDE) + koff;
                    ldsm4(af[mt], r + OFF_A + a_off);
                }
#pragma unroll
                for (int ng = 0; ng < 2; ng++) {
                    uint32_t r = base + (uint32_t)((wn + ng * 16) * RSTRIDE) + koff;
                    ldsm4(bf[ng], r + OFF_B + b_off);
                }
#pragma unroll
                for (int mt = 0; mt < 4; mt++)
#pragma unroll
                    for (int nt = 0; nt < 4; nt++)
                        mma16816(acc[mt][nt], af[mt], &bf[nt >> 1][(nt & 1) * 2]);
            }
        }

        if (MODE == 0) {
#pragma unroll
            for (int mt = 0; mt < 4; mt++)
#pragma unroll
                for (int nt = 0; nt < 4; nt++) {
                    int row = m0 + wm + mt * 16 + (lane >> 2);
                    int col = n0 + wn + nt * 8 + (lane & 3) * 2;
                    *(float2*)&C[(size_t)row * N + col] =
                        make_float2(acc[mt][nt][0], acc[mt][nt][1]);
                    *(float2*)&C[(size_t)(row + 8) * N + col] =
                        make_float2(acc[mt][nt][2], acc[mt][nt][3]);
                }
        } else {
            const int sec = (n0 + wn) >> 10;          // 0=q 1=k 2=v
            const int hh  = ((n0 + wn) >> 6) & 15;
            __half* DST = (sec == 0) ? q16 : (sec == 1) ? k16 : v16;
            const float scl = (sec == 0) ? QSCALE : 1.0f;
#pragma unroll
            for (int mt = 0; mt < 4; mt++)
#pragma unroll
                for (int nt = 0; nt < 4; nt++) {
                    int row = m0 + wm + mt * 16 + (lane >> 2);
                    int d   = ((wn + nt * 8) & 63) + (lane & 3) * 2;
                    int b   = row >> 11;
                    int ll  = row & 2047;
                    size_t idx = ((size_t)(b * HEADS + hh) * LSEQ + ll) * KD + d;
                    *(uint32_t*)(DST + idx) =
                        pack2(h16(acc[mt][nt][0] * scl), h16(acc[mt][nt][1] * scl));
                    *(uint32_t*)(DST + idx + (size_t)8 * KD) =
                        pack2(h16(acc[mt][nt][2] * scl), h16(acc[mt][nt][3] * scl));
                }
        }
        __syncthreads();   // epilogue/frag reads done before next tile's loads
    }
}

// ---------------------------------------------------------------------------
// Flash attention, pure fp16 MMA, causal, exp2 softmax (Q pre-scaled by
// log2(e)/8). 128-row kv stages, 2 CTA/SM, heavy q-tiles first.
// ---------------------------------------------------------------------------
#define ASTRIDE 144
#define AQ_OFF  0
#define ASTG0   (128 * ASTRIDE)        // 18432 (Q tile)
#define ASTG_SZ (2 * 128 * ASTRIDE)    // 36864 per stage (K, V: 128 rows each)
#define AK 0
#define AV (128 * ASTRIDE)
#define ATT_SMEM (ASTG0 + 2 * ASTG_SZ) // 92160

__global__ __launch_bounds__(256, 2) void attn_mma_kernel(
    const __half* __restrict__ q16,
    const __half* __restrict__ k16, const __half* __restrict__ v16,
    __half* __restrict__ att16) {
    extern __shared__ __align__(128) char smem[];
    const uint32_t sb = smem_u32(smem);
    const int tid  = threadIdx.x;
    const int lane = tid & 31;
    const int wid  = tid >> 5;
    const int qt   = gridDim.x - 1 - blockIdx.x;   // heavy tiles first
    const int bh   = blockIdx.y;
    const int q0   = qt * 128;
    const int nst  = qt + 1;

    const size_t hb = (size_t)bh * LSEQ * KD;
    const char* Qp = (const char*)(q16 + hb + (size_t)q0 * KD);
    const char* Kp = (const char*)(k16 + hb);
    const char* Vp = (const char*)(v16 + hb);

    auto load_q = [&]() {
        for (int i = tid; i < 1024; i += 256) {
            int row = i >> 3, ch = (i & 7) * 16;
            uint32_t so = (uint32_t)(row * ASTRIDE + ch);
            cp16(sb + AQ_OFF + so, Qp + (size_t)row * 128 + ch);
        }
    };
    auto load_stage = [&](int st) {
        const uint32_t base = sb + ASTG0 + (uint32_t)(st & 1) * ASTG_SZ;
        for (int i = tid; i < 1024; i += 256) {
            int row = i >> 3, ch = (i & 7) * 16;
            uint32_t so = (uint32_t)(row * ASTRIDE + ch);
            size_t go = (size_t)(st * 128 + row) * 128 + ch;
            cp16(base + AK + so, Kp + go);
            cp16(base + AV + so, Vp + go);
        }
        CP_COMMIT();
    };

    load_q();
    load_stage(0);

    const uint32_t a_off = (uint32_t)((lane & 15) * ASTRIDE + (lane >> 4) * 16);
    const uint32_t b_off = (uint32_t)((((lane >> 4) & 1) * 8 + (lane & 7)) * ASTRIDE +
                                      ((lane >> 3) & 1) * 16);
    const uint32_t v_off = (uint32_t)((lane & 15) * ASTRIDE + (lane >> 4) * 16);

    uint32_t qf[4][4];
    float oacc[8][4];
#pragma unroll
    for (int i = 0; i < 8; i++)
#pragma unroll
        for (int j = 0; j < 4; j++) oacc[i][j] = 0.0f;
    float mr0 = -1e30f, mr1 = -1e30f, lr0 = 0.0f, lr1 = 0.0f;

    const int r0 = q0 + wid * 16 + (lane >> 2);
    const int r1 = r0 + 8;

    for (int st = 0; st < nst; st++) {
        CP_WAIT0();
        __syncthreads();
        if (st + 1 < nst) load_stage(st + 1);

        if (st == 0) {
#pragma unroll
            for (int kc = 0; kc < 4; kc++) {
                uint32_t r = sb + (uint32_t)(wid * 16 * ASTRIDE) + kc * 32 + a_off;
                ldsm4(qf[kc], r + AQ_OFF);
            }
        }

        const uint32_t stg = sb + ASTG0 + (uint32_t)(st & 1) * ASTG_SZ;

#pragma unroll
        for (int sub = 0; sub < 2; sub++) {
            const int kt = st * 2 + sub;
            const uint32_t ksub = stg + AK + (uint32_t)(sub * 64 * ASTRIDE);
            const uint32_t vsub = stg + AV + (uint32_t)(sub * 64 * ASTRIDE);

            // ---- S = Q K^T (Q pre-scaled, scores in log2 domain) ----
            float sacc[8][4];
#pragma unroll
            for (int i = 0; i < 8; i++)
#pragma unroll
                for (int j = 0; j < 4; j++) sacc[i][j] = 0.0f;

#pragma unroll
            for (int kc = 0; kc < 4; kc++) {
                uint32_t kf[4][4];
#pragma unroll
                for (int ng = 0; ng < 4; ng++) {
                    uint32_t r = ksub + (uint32_t)(ng * 16 * ASTRIDE) + kc * 32 + b_off;
                    ldsm4(kf[ng], r);
                }
#pragma unroll
                for (int nt = 0; nt < 8; nt++)
                    mma16816(sacc[nt], qf[kc], &kf[nt >> 1][(nt & 1) * 2]);
            }

            // ---- causal mask (diagonal tiles only) ----
            if (kt * 64 + 63 > q0 + wid * 16) {
#pragma unroll
                for (int nt = 0; nt < 8; nt++) {
                    int colb = kt * 64 + nt * 8 + (lane & 3) * 2;
                    if (colb     > r0) sacc[nt][0] = -1e30f;
                    if (colb + 1 > r0) sacc[nt][1] = -1e30f;
                    if (colb     > r1) sacc[nt][2] = -1e30f;
                    if (colb + 1 > r1) sacc[nt][3] = -1e30f;
                }
            }

            // ---- online softmax (exp2 domain) ----
            float m0 = -1e30f, m1 = -1e30f;
#pragma unroll
            for (int nt = 0; nt < 8; nt++) {
                m0 = fmaxf(m0, fmaxf(sacc[nt][0], sacc[nt][1]));
                m1 = fmaxf(m1, fmaxf(sacc[nt][2], sacc[nt][3]));
            }
            m0 = fmaxf(m0, __shfl_xor_sync(0xffffffffu, m0, 1));
            m0 = fmaxf(m0, __shfl_xor_sync(0xffffffffu, m0, 2));
            m1 = fmaxf(m1, __shfl_xor_sync(0xffffffffu, m1, 1));
            m1 = fmaxf(m1, __shfl_xor_sync(0xffffffffu, m1, 2));

            float mn0 = fmaxf(mr0, m0), mn1 = fmaxf(mr1, m1);
            float al0 = ex2(mr0 - mn0), al1 = ex2(mr1 - mn1);
            mr0 = mn0; mr1 = mn1;

            uint32_t pA[8], pB[8];
            float s0 = 0.0f, s1 = 0.0f;
#pragma unroll
            for (int nt = 0; nt < 8; nt++) {
                float p0 = ex2(sacc[nt][0] - mn0);
                float p1 = ex2(sacc[nt][1] - mn0);
                float p2 = ex2(sacc[nt][2] - mn1);
                float p3 = ex2(sacc[nt][3] - mn1);
                s0 += p0 + p1;
                s1 += p2 + p3;
                pA[nt] = pack2(h16(p0), h16(p1));
                pB[nt] = pack2(h16(p2), h16(p3));
            }
            s0 += __shfl_xor_sync(0xffffffffu, s0, 1);
            s0 += __shfl_xor_sync(0xffffffffu, s0, 2);
            s1 += __shfl_xor_sync(0xffffffffu, s1, 1);
            s1 += __shfl_xor_sync(0xffffffffu, s1, 2);
            lr0 = lr0 * al0 + s0;
            lr1 = lr1 * al1 + s1;

#pragma unroll
            for (int dt = 0; dt < 8; dt++) {
                oacc[dt][0] *= al0; oacc[dt][1] *= al0;
                oacc[dt][2] *= al1; oacc[dt][3] *= al1;
            }

            // ---- O += P V ----
#pragma unroll
            for (int kc = 0; kc < 4; kc++) {
                uint32_t pf[4] = {pA[2 * kc], pB[2 * kc], pA[2 * kc + 1], pB[2 * kc + 1]};
                uint32_t vf[4][4];
#pragma unroll
                for (int dg = 0; dg < 4; dg++) {
                    uint32_t r = vsub + (uint32_t)(kc * 16 * ASTRIDE) + dg * 32 + v_off;
                    ldsm4t(vf[dg], r);
                }
#pragma unroll
                for (int dg = 0; dg < 4; dg++) {
                    mma16816(oacc[dg * 2],     pf, &vf[dg][0]);
                    mma16816(oacc[dg * 2 + 1], pf, &vf[dg][2]);
                }
            }
        }
    }

    // ---- epilogue ----
    const float inv0 = 1.0f / lr0, inv1 = 1.0f / lr1;
    const int b = bh >> 4, hh = bh & 15;
    size_t base0 = ((size_t)(b * LSEQ + r0)) * DMODEL + hh * KD + (lane & 3) * 2;
    size_t base1 = base0 + (size_t)8 * DMODEL;
#pragma unroll
    for (int dt = 0; dt < 8; dt++) {
        *(uint32_t*)(att16 + base0 + dt * 8) =
            pack2(h16(oacc[dt][0] * inv0), h16(oacc[dt][1] * inv0));
        *(uint32_t*)(att16 + base1 + dt * 8) =
            pack2(h16(oacc[dt][2] * inv1), h16(oacc[dt][3] * inv1));
    }
}

// ---------------------------------------------------------------------------
extern "C" void kernel_launch(void* const* d_in, const int* in_sizes, int n_in,
                              void* d_out, int out_size) {
    const float* x    = (const float*)d_in[0];
    const float* Wqkv = (const float*)d_in[1];
    const float* Wout = (const float*)d_in[2];
    float* out = (float*)d_out;

    __half *x16, *wq16, *wo16, *q16, *k16, *v16, *att16;
    cudaGetSymbolAddress((void**)&x16, g_x16);
    cudaGetSymbolAddress((void**)&wq16, g_wqkvT);
    cudaGetSymbolAddress((void**)&wo16, g_woutT);
    cudaGetSymbolAddress((void**)&q16, g_q16);
    cudaGetSymbolAddress((void**)&k16, g_k16);
    cudaGetSymbolAddress((void**)&v16, g_v16);
    cudaGetSymbolAddress((void**)&att16, g_att16);

    cudaFuncSetAttribute((const void*)gemm_mma_kernel<0>,
                         cudaFuncAttributeMaxDynamicSharedMemorySize, GEMM_SMEM);
    cudaFuncSetAttribute((const void*)gemm_mma_kernel<1>,
                         cudaFuncAttributeMaxDynamicSharedMemorySize, GEMM_SMEM);
    cudaFuncSetAttribute((const void*)attn_mma_kernel,
                         cudaFuncAttributeMaxDynamicSharedMemorySize, ATT_SMEM);

    // prep
    {
        int n4 = TOKENS * DMODEL / 4;
        convert_f16_kernel<<<(n4 + 255) / 256, 256>>>(x, x16, n4);
        transpose_f16_kernel<<<dim3(3 * DMODEL / 32, DMODEL / 32), dim3(32, 8)>>>(
            Wqkv, wq16, DMODEL, 3 * DMODEL);
        transpose_f16_kernel<<<dim3(DMODEL / 32, DMODEL / 32), dim3(32, 8)>>>(
            Wout, wo16, DMODEL, DMODEL);
    }

    // 1) qkv GEMM (persistent) -> fp16 head-major q/k/v
    gemm_mma_kernel<1><<<PERSIST_CTAS, 256, GEMM_SMEM>>>(
        x16, wq16, nullptr, q16, k16, v16, TOKENS, 3 * DMODEL, DMODEL);

    // 2) tensor-core causal flash attention -> att fp16
    attn_mma_kernel<<<dim3(LSEQ / 128, BH_CNT), 256, ATT_SMEM>>>(
        q16, k16, v16, att16);

    // 3) out = att @ Wout (persistent)
    gemm_mma_kernel<0><<<PERSIST_CTAS, 256, GEMM_SMEM>>>(
        att16, wo16, out, nullptr, nullptr, nullptr, TOKENS, DMODEL, DMODEL);
}